// round 10
// baseline (speedup 1.0000x reference)
#include <cuda_runtime.h>
#include <cuda_fp16.h>
#include <mma.h>
#include <math.h>
#include <stdint.h>

using namespace nvcuda;

// ---------------------------------------------------------------------------
// Problem constants
// ---------------------------------------------------------------------------
#define B       2
#define C_DIM   64
#define H_IMG   128
#define W_IMG   128
#define HW      (H_IMG * W_IMG)          // 16384
#define HEADS   8
#define DIM_HEAD 64
#define INNER   (HEADS * DIM_HEAD)       // 512
#define Q_L     16
#define KV_L    48
#define LN_EPS  1e-5f

// ---------------------------------------------------------------------------
// Scratch buffers (__device__ globals; allocation is forbidden)
// ---------------------------------------------------------------------------
__device__ __half g_qn  [B * HW * C_DIM];            // LN(q), NHWC fp16
__device__ __half g_kvn [B * 3 * HW * C_DIM];        // warped+LN kv, NHWC fp16
__device__ __half g_q   [B * HW * INNER];            // conv q out, NHWC fp16 (pre-scaled)
__device__ __half g_kv  [B * 3 * HW * 2 * INNER];    // conv kv out, NHWC fp16
__device__ __half g_att [B * HW * INNER];            // attention out, NHWC fp16
__device__ __half g_wt_q  [9 * INNER * C_DIM];       // Wq*0.125 as [tap][oc][ic] fp16
__device__ __half g_wt_kv [9 * 2 * INNER * C_DIM];   // Wkv as [tap][oc][ic] fp16
__device__ __half g_wt_out[9 * C_DIM * INNER];       // Wout as [tap][oc][ic] fp16

// ---------------------------------------------------------------------------
// Kernel 0: weight transform  W[oc][ic][3][3] -> Wt[tap][oc][ic] (fp16, scaled)
// ---------------------------------------------------------------------------
__global__ void wtrans_kernel(const float* __restrict__ W,
                              __half* __restrict__ Wt, int OC, int IC,
                              float scale)
{
    int idx = blockIdx.x * blockDim.x + threadIdx.x;
    if (idx >= OC * IC) return;
    int oc = idx / IC, ic = idx % IC;
    const float* src = W + ((size_t)oc * IC + ic) * 9;
#pragma unroll
    for (int t = 0; t < 9; t++)
        Wt[((size_t)t * OC + oc) * IC + ic] = __float2half_rn(src[t] * scale);
}

// ---------------------------------------------------------------------------
// Kernel 1: LayerNorm q -> NHWC fp16
// ---------------------------------------------------------------------------
__global__ void ln_q_kernel(const float* __restrict__ q_inp,
                            const float* __restrict__ g,
                            const float* __restrict__ beta,
                            __half* __restrict__ out)
{
    int pix = blockIdx.x * blockDim.x + threadIdx.x;
    if (pix >= HW) return;
    int bb = blockIdx.z;

    const float* base = q_inp + ((size_t)bb * C_DIM) * HW + pix;
    float vals[C_DIM];
    float sum = 0.f;
#pragma unroll
    for (int c = 0; c < C_DIM; c++) { float v = base[(size_t)c * HW]; vals[c] = v; sum += v; }
    float mu = sum * (1.f / C_DIM);
    float var = 0.f;
#pragma unroll
    for (int c = 0; c < C_DIM; c++) { float d = vals[c] - mu; var += d * d; }
    var *= (1.f / C_DIM);
    float inv = rsqrtf(var + LN_EPS);

    __half2* ob = (__half2*)(out + ((size_t)bb * HW + pix) * C_DIM);
#pragma unroll
    for (int c = 0; c < C_DIM; c += 2)
        ob[c >> 1] = __floats2half2_rn((vals[c]   - mu) * inv * g[c]   + beta[c],
                                       (vals[c+1] - mu) * inv * g[c+1] + beta[c+1]);
}

// ---------------------------------------------------------------------------
// Kernel 2: flow warp + stack + LayerNorm kv -> NHWC fp16
// ---------------------------------------------------------------------------
__global__ void warp_ln_kv_kernel(const float* __restrict__ k_inp,
                                  const float* __restrict__ flow_f,
                                  const float* __restrict__ flow_b,
                                  const float* __restrict__ g,
                                  const float* __restrict__ beta,
                                  __half* __restrict__ out)
{
    int pix = blockIdx.x * blockDim.x + threadIdx.x;
    if (pix >= HW) return;
    int f  = blockIdx.y;   // 0..2
    int bb = blockIdx.z;   // 0..1
    int y = pix >> 7, x = pix & 127;

    int src = pix;
    bool valid = true;
    if (f != 1) {
        const float* fl = (f == 0) ? flow_f : flow_b;
        float fx = fl[((size_t)bb * 2 + 0) * HW + pix];
        float fy = fl[((size_t)bb * 2 + 1) * HW + pix];
        int ix = (int)rintf((float)x + fx);
        int iy = (int)rintf((float)y + fy);
        valid = (ix >= 0) && (ix < W_IMG) && (iy >= 0) && (iy < H_IMG);
        int cx = min(max(ix, 0), W_IMG - 1);
        int cy = min(max(iy, 0), H_IMG - 1);
        src = cy * W_IMG + cx;
    }

    const float* base = k_inp + (((size_t)bb * 3 + f) * C_DIM) * HW + src;
    float vals[C_DIM];
    float sum = 0.f;
#pragma unroll
    for (int c = 0; c < C_DIM; c++) {
        float v = valid ? base[(size_t)c * HW] : 0.f;
        vals[c] = v; sum += v;
    }
    float mu = sum * (1.f / C_DIM);
    float var = 0.f;
#pragma unroll
    for (int c = 0; c < C_DIM; c++) { float d = vals[c] - mu; var += d * d; }
    var *= (1.f / C_DIM);
    float inv = rsqrtf(var + LN_EPS);

    __half2* ob = (__half2*)(out + (((size_t)(bb * 3 + f)) * HW + pix) * C_DIM);
#pragma unroll
    for (int c = 0; c < C_DIM; c += 2)
        ob[c >> 1] = __floats2half2_rn((vals[c]   - mu) * inv * g[c]   + beta[c],
                                       (vals[c+1] - mu) * inv * g[c+1] + beta[c+1]);
}

// ---------------------------------------------------------------------------
// Kernel 3: 3x3 conv as implicit GEMM on wmma fp16 (m16n16k16, fp32 accum).
// One CTA = ROWS rows x (OC_ITERS x 64) output channels. A staged once per
// chunk; when chunks==1 and OC_ITERS>1, A is reused across oc-tiles and only
// the 64-oc B tile is restaged. Epilogue uses a dedicated staging region so
// sA survives across iterations.
// Warp layout: ROWS x PXG x NOCG = 8, warp tile = (MF*16) px x (NF*16) oc.
// ---------------------------------------------------------------------------
#define AROWH 72                            // halfs per px (64 + 8 pad)

template <int ROWS, int MF, int OC_ITERS, bool OUT_FP16_NHWC>
__global__ __launch_bounds__(256, 1)
void conv3x3_h_kernel(const __half* __restrict__ in,   // NHWC fp16
                      const __half* __restrict__ Wt,   // [9][OC][IC] fp16
                      void* __restrict__ out_raw,
                      int IC, int OC)
{
    constexpr int PXG  = 128 / (16 * MF);    // px groups
    constexpr int NOCG = 8 / (ROWS * PXG);   // oc groups
    constexpr int OCW  = 64 / NOCG;          // oc per warp
    constexpr int NF   = OCW / 16;           // B fragments per warp
    static_assert(ROWS * PXG * NOCG == 8, "warp layout");
    constexpr int A_ELEMS = (ROWS + 2) * 130 * AROWH;
    constexpr int B_ELEMS = 9 * 64 * AROWH;

    extern __shared__ __half smh[];
    __half* sA   = smh;
    __half* sB   = smh + A_ELEMS;
    float*  sEpi = (float*)(smh + A_ELEMS + B_ELEMS);   // 8 x 320 floats

    int tid  = threadIdx.x;
    int wid  = tid >> 5;
    int lane = tid & 31;

    int y0   = blockIdx.x * ROWS;
    int ocb  = blockIdx.y * (64 * OC_ITERS);
    int img  = blockIdx.z;

    int warp_row = wid % ROWS;
    int warp_pxg = (wid / ROWS) % PXG;
    int warp_ocg = wid / (ROWS * PXG);

    const int chunks = IC / 64;

    for (int iter = 0; iter < OC_ITERS; iter++) {
        int oc0 = ocb + iter * 64;

        wmma::fragment<wmma::accumulator, 16, 16, 16, float> acc[MF][NF];
#pragma unroll
        for (int mf = 0; mf < MF; mf++)
#pragma unroll
            for (int nf = 0; nf < NF; nf++) wmma::fill_fragment(acc[mf][nf], 0.0f);

        for (int c = 0; c < chunks; c++) {
            int ic0 = c * 64;

            __syncthreads();
            // ---- stage A (skip if already resident from iter 0) ----
            if (iter == 0 || chunks > 1) {
                for (int i = tid; i < (ROWS + 2) * 130 * 8; i += 256) {
                    int r   = i / (130 * 8);
                    int rem = i % (130 * 8);
                    int p   = rem >> 3;
                    int v   = rem & 7;
                    int gy = y0 + r - 1, gx = p - 1;
                    uint4 d = make_uint4(0u, 0u, 0u, 0u);
                    if (gy >= 0 && gy < H_IMG && gx >= 0 && gx < W_IMG)
                        d = *(const uint4*)&in[(((size_t)img * H_IMG + gy) * W_IMG + gx) * IC + ic0 + v * 8];
                    *(uint4*)&sA[(r * 130 + p) * AROWH + v * 8] = d;
                }
            }
            // ---- stage B: 9 taps x 64 oc x 64 ic ----
            for (int i = tid; i < 9 * 64 * 8; i += 256) {
                int tap = i / (64 * 8);
                int rem = i % (64 * 8);
                int o   = rem >> 3;
                int v   = rem & 7;
                *(uint4*)&sB[(tap * 64 + o) * AROWH + v * 8] =
                    *(const uint4*)&Wt[(((size_t)tap * OC) + oc0 + o) * IC + ic0 + v * 8];
            }
            __syncthreads();

            // ---- compute: 9 taps x 4 k-steps ----
#pragma unroll
            for (int dy = 0; dy < 3; dy++) {
#pragma unroll
                for (int dx = 0; dx < 3; dx++) {
                    const int tap = dy * 3 + dx;
#pragma unroll
                    for (int s = 0; s < 4; s++) {
                        wmma::fragment<wmma::matrix_b, 16, 16, 16, __half,
                                       wmma::col_major> bf[NF];
#pragma unroll
                        for (int nf = 0; nf < NF; nf++)
                            wmma::load_matrix_sync(
                                bf[nf],
                                &sB[(tap * 64 + warp_ocg * OCW + nf * 16) * AROWH + s * 16],
                                AROWH);
#pragma unroll
                        for (int mf = 0; mf < MF; mf++) {
                            int px = warp_pxg * (MF * 16) + mf * 16;
                            wmma::fragment<wmma::matrix_a, 16, 16, 16, __half,
                                           wmma::row_major> af;
                            wmma::load_matrix_sync(
                                af,
                                &sA[((warp_row + dy) * 130 + px + dx) * AROWH + s * 16],
                                AROWH);
#pragma unroll
                            for (int nf = 0; nf < NF; nf++)
                                wmma::mma_sync(acc[mf][nf], af, bf[nf], acc[mf][nf]);
                        }
                    }
                }
            }
        }

        // ---- epilogue (per-warp staging; sA untouched) ----
        int y = y0 + warp_row;
        if (OUT_FP16_NHWC) {
            __half* outp = (__half*)out_raw;
            float* buf = sEpi + wid * 320;            // 16 x 20 fp32 per warp
            int r  = lane >> 1;
            int hp = lane & 1;
#pragma unroll
            for (int mf = 0; mf < MF; mf++) {
                int px = warp_pxg * (MF * 16) + mf * 16;
#pragma unroll
                for (int nf = 0; nf < NF; nf++) {
                    int oc = oc0 + warp_ocg * OCW + nf * 16;
                    wmma::store_matrix_sync(buf, acc[mf][nf], 20, wmma::mem_row_major);
                    __syncwarp();
                    float4 a = *(float4*)&buf[r * 20 + hp * 8];
                    float4 b = *(float4*)&buf[r * 20 + hp * 8 + 4];
                    __half2 h[4];
                    h[0] = __floats2half2_rn(a.x, a.y);
                    h[1] = __floats2half2_rn(a.z, a.w);
                    h[2] = __floats2half2_rn(b.x, b.y);
                    h[3] = __floats2half2_rn(b.z, b.w);
                    *(uint4*)&outp[(((size_t)img * H_IMG + y) * W_IMG + px + r) * OC + oc + hp * 8] =
                        *(uint4*)h;
                    __syncwarp();
                }
            }
        } else {
            float* outp = (float*)out_raw;            // NCHW fp32 (d_out)
#pragma unroll
            for (int mf = 0; mf < MF; mf++) {
                int px = warp_pxg * (MF * 16) + mf * 16;
#pragma unroll
                for (int nf = 0; nf < NF; nf++) {
                    int oc = oc0 + warp_ocg * OCW + nf * 16;
                    float* dst = &outp[(((size_t)img * OC + oc) * H_IMG + y) * W_IMG + px];
                    wmma::store_matrix_sync(dst, acc[mf][nf], HW, wmma::mem_col_major);
                }
            }
        }
    }
}

// ---------------------------------------------------------------------------
// Kernel 4: windowed attention on tensor cores (warp per head).
// ---------------------------------------------------------------------------
#define QSTR 520                              // half stride per pixel row
#define FSTR 68                               // float stride, per-warp staging
#define PSTR 56                               // half stride, probs

__global__ __launch_bounds__(256, 1)
void attn_kernel(const __half* __restrict__ q,
                 const __half* __restrict__ kv,
                 const float* __restrict__ stat,
                 __half* __restrict__ outp)
{
    extern __shared__ __half smh[];
    __half* sQ = smh;                         // [16][QSTR]
    __half* sK = sQ + Q_L * QSTR;             // [48][QSTR]
    __half* sV = sK + KV_L * QSTR;            // [48][QSTR]
    float*  fB = (float*)(sV + KV_L * QSTR);  // 8 x [16][FSTR]
    __half* sP = (__half*)(fB + 8 * Q_L * FSTR); // 8 x [16][PSTR]

    int tid  = threadIdx.x;
    int wid  = tid >> 5;                      // head
    int lane = tid & 31;
    int win = blockIdx.x;
    int bb  = blockIdx.z;
    int wy = win >> 5, wx = win & 31;
    int d0 = wid * DIM_HEAD;

    for (int i = tid; i < Q_L * 64; i += 256) {
        int pi = i >> 6, v = i & 63;
        int py = pi >> 2, px = pi & 3;
        int pix = (wy * 4 + py) * W_IMG + wx * 4 + px;
        *(uint4*)&sQ[pi * QSTR + v * 8] =
            *(const uint4*)&q[((size_t)bb * HW + pix) * INNER + v * 8];
    }
    for (int i = tid; i < KV_L * 64; i += 256) {
        int j = i >> 6, v = i & 63;
        int f = j >> 4, pi = j & 15;
        int py = pi >> 2, px = pi & 3;
        int pix = (wy * 4 + py) * W_IMG + wx * 4 + px;
        size_t base = ((size_t)(bb * 3 + f) * HW + pix) * (2 * INNER);
        *(uint4*)&sK[j * QSTR + v * 8] = *(const uint4*)&kv[base + v * 8];
        *(uint4*)&sV[j * QSTR + v * 8] = *(const uint4*)&kv[base + INNER + v * 8];
    }
    __syncthreads();

    float*  fbw = fB + wid * Q_L * FSTR;
    __half* spw = sP + wid * Q_L * PSTR;

    // ---- sim = q k^T ----
    wmma::fragment<wmma::accumulator, 16, 16, 16, float> sim[3];
#pragma unroll
    for (int n = 0; n < 3; n++) wmma::fill_fragment(sim[n], 0.0f);
#pragma unroll
    for (int s = 0; s < 4; s++) {
        wmma::fragment<wmma::matrix_a, 16, 16, 16, __half, wmma::row_major> af;
        wmma::load_matrix_sync(af, &sQ[d0 + s * 16], QSTR);
#pragma unroll
        for (int n = 0; n < 3; n++) {
            wmma::fragment<wmma::matrix_b, 16, 16, 16, __half, wmma::col_major> bf;
            wmma::load_matrix_sync(bf, &sK[n * 16 * QSTR + d0 + s * 16], QSTR);
            wmma::mma_sync(sim[n], af, bf, sim[n]);
        }
    }
#pragma unroll
    for (int n = 0; n < 3; n++)
        wmma::store_matrix_sync(&fbw[n * 16], sim[n], FSTR, wmma::mem_row_major);
    __syncwarp();

    for (int e = lane; e < Q_L * KV_L; e += 32) {
        int i = e / KV_L, j = e % KV_L;
        fbw[i * FSTR + j] += stat[((size_t)wid * Q_L + i) * KV_L + j];
    }
    __syncwarp();

    if (lane < Q_L) {
        float* row = &fbw[lane * FSTR];
        float m = -1e30f;
#pragma unroll
        for (int j = 0; j < KV_L; j++) m = fmaxf(m, row[j]);
        float ssum = 0.f;
#pragma unroll
        for (int j = 0; j < KV_L; j++) {
            float e = expf(row[j] - m);
            row[j] = e; ssum += e;
        }
        float inv = 1.f / ssum;
#pragma unroll
        for (int j = 0; j < KV_L; j++) row[j] *= inv;
    }
    __syncwarp();

    for (int e = lane; e < Q_L * KV_L; e += 32) {
        int i = e / KV_L, j = e % KV_L;
        spw[i * PSTR + j] = __float2half_rn(fbw[i * FSTR + j]);
    }
    __syncwarp();

    // ---- out = p v ----
    wmma::fragment<wmma::accumulator, 16, 16, 16, float> oacc[4];
#pragma unroll
    for (int n = 0; n < 4; n++) wmma::fill_fragment(oacc[n], 0.0f);
#pragma unroll
    for (int s = 0; s < 3; s++) {
        wmma::fragment<wmma::matrix_a, 16, 16, 16, __half, wmma::row_major> af;
        wmma::load_matrix_sync(af, &spw[s * 16], PSTR);
#pragma unroll
        for (int n = 0; n < 4; n++) {
            wmma::fragment<wmma::matrix_b, 16, 16, 16, __half, wmma::row_major> bf;
            wmma::load_matrix_sync(bf, &sV[s * 16 * QSTR + d0 + n * 16], QSTR);
            wmma::mma_sync(oacc[n], af, bf, oacc[n]);
        }
    }
#pragma unroll
    for (int n = 0; n < 4; n++)
        wmma::store_matrix_sync(&fbw[n * 16], oacc[n], FSTR, wmma::mem_row_major);
    __syncwarp();

    {
        int r  = lane >> 1;
        int hp = lane & 1;
        int py = r >> 2, px = r & 3;
        int pix = (wy * 4 + py) * W_IMG + wx * 4 + px;
        __half* dst = &outp[((size_t)bb * HW + pix) * INNER + d0 + hp * 32];
        const float* srcr = &fbw[r * FSTR + hp * 32];
        __half2 h[16];
#pragma unroll
        for (int t = 0; t < 16; t++)
            h[t] = __floats2half2_rn(srcr[t * 2], srcr[t * 2 + 1]);
#pragma unroll
        for (int t = 0; t < 4; t++)
            *(uint4*)&dst[t * 8] = ((uint4*)h)[t];
    }
}

// ---------------------------------------------------------------------------
// Host launch
// ---------------------------------------------------------------------------
extern "C" void kernel_launch(void* const* d_in, const int* in_sizes, int n_in,
                              void* d_out, int out_size)
{
    (void)in_sizes; (void)n_in; (void)out_size;

    const float* q_inp   = (const float*)d_in[0];
    const float* k_inp   = (const float*)d_in[1];
    const float* flow_f  = (const float*)d_in[2];
    const float* flow_b  = (const float*)d_in[3];
    const float* gq      = (const float*)d_in[4];
    const float* bq      = (const float*)d_in[5];
    const float* gkv     = (const float*)d_in[6];
    const float* bkv     = (const float*)d_in[7];
    const float* Wq      = (const float*)d_in[8];
    const float* Wkv     = (const float*)d_in[9];
    const float* Wout    = (const float*)d_in[10];
    const float* statica = (const float*)d_in[11];

    __half *qn, *kvn, *qb, *kvb, *attb, *wtq, *wtkv, *wtout;
    cudaGetSymbolAddress((void**)&qn,    g_qn);
    cudaGetSymbolAddress((void**)&kvn,   g_kvn);
    cudaGetSymbolAddress((void**)&qb,    g_q);
    cudaGetSymbolAddress((void**)&kvb,   g_kv);
    cudaGetSymbolAddress((void**)&attb,  g_att);
    cudaGetSymbolAddress((void**)&wtq,   g_wt_q);
    cudaGetSymbolAddress((void**)&wtkv,  g_wt_kv);
    cudaGetSymbolAddress((void**)&wtout, g_wt_out);

    // smem: A + B + epilogue staging (8 warps x 320 floats)
    const int SMEM4 = ((4 + 2) * 130 * AROWH + 9 * 64 * AROWH) * 2 + 8 * 320 * 4; // 205,504
    const int SMEM1 = ((1 + 2) * 130 * AROWH + 9 * 64 * AROWH) * 2;               // 139,104
    const int SMEMA = (Q_L + 2 * KV_L) * QSTR * 2
                    + 8 * Q_L * FSTR * 4
                    + 8 * Q_L * PSTR * 2;
    cudaFuncSetAttribute((const void*)conv3x3_h_kernel<4, 4, 2, true>,
                         cudaFuncAttributeMaxDynamicSharedMemorySize, SMEM4);
    cudaFuncSetAttribute((const void*)conv3x3_h_kernel<4, 4, 4, true>,
                         cudaFuncAttributeMaxDynamicSharedMemorySize, SMEM4);
    cudaFuncSetAttribute((const void*)conv3x3_h_kernel<1, 2, 1, false>,
                         cudaFuncAttributeMaxDynamicSharedMemorySize, SMEM1);
    cudaFuncSetAttribute((const void*)attn_kernel,
                         cudaFuncAttributeMaxDynamicSharedMemorySize, SMEMA);

    // 0) weight transforms (fp16; q-scale 0.125 folded into Wq)
    wtrans_kernel<<<(INNER * C_DIM + 255) / 256, 256>>>(Wq, wtq, INNER, C_DIM, 0.125f);
    wtrans_kernel<<<(2 * INNER * C_DIM + 255) / 256, 256>>>(Wkv, wtkv, 2 * INNER, C_DIM, 1.0f);
    wtrans_kernel<<<(C_DIM * INNER + 255) / 256, 256>>>(Wout, wtout, C_DIM, INNER, 1.0f);

    // 1) layernorm q  (NHWC fp16)
    ln_q_kernel<<<dim3(HW / 128, 1, B), 128>>>(q_inp, gq, bq, qn);

    // 2) warp + stack + layernorm kv  (NHWC fp16)
    warp_ln_kv_kernel<<<dim3(HW / 128, 3, B), 128>>>(k_inp, flow_f, flow_b, gkv, bkv, kvn);

    // 3) conv q: 64 -> 512 (2 oc-tiles per CTA, A staged once) : 256 CTAs
    conv3x3_h_kernel<4, 4, 2, true><<<dim3(H_IMG / 4, INNER / 128, B), 256, SMEM4>>>(
        qn, wtq, qb, C_DIM, INNER);

    // 4) conv kv: 64 -> 1024 (4 oc-tiles per CTA) : 768 CTAs
    conv3x3_h_kernel<4, 4, 4, true><<<dim3(H_IMG / 4, (2 * INNER) / 256, B * 3), 256, SMEM4>>>(
        kvn, wtkv, kvb, C_DIM, 2 * INNER);

    // 5) attention: tensor-core, one block per window
    attn_kernel<<<dim3(1024, 1, B), 256, SMEMA>>>(qb, kvb, statica, attb);

    // 6) conv out: 512 -> 64, fp32 NCHW -> d_out : 256 CTAs (1-row strips)
    conv3x3_h_kernel<1, 2, 1, false><<<dim3(H_IMG, 1, B), 256, SMEM1>>>(
        attb, wtout, (float*)d_out, INNER, C_DIM);
}

// round 11
// speedup vs baseline: 1.0145x; 1.0145x over previous
#include <cuda_runtime.h>
#include <cuda_fp16.h>
#include <mma.h>
#include <math.h>
#include <stdint.h>

using namespace nvcuda;

// ---------------------------------------------------------------------------
// Problem constants
// ---------------------------------------------------------------------------
#define B       2
#define C_DIM   64
#define H_IMG   128
#define W_IMG   128
#define HW      (H_IMG * W_IMG)          // 16384
#define HEADS   8
#define DIM_HEAD 64
#define INNER   (HEADS * DIM_HEAD)       // 512
#define Q_L     16
#define KV_L    48
#define LN_EPS  1e-5f

// ---------------------------------------------------------------------------
// Scratch buffers (__device__ globals; allocation is forbidden)
// ---------------------------------------------------------------------------
__device__ __half g_qn  [B * HW * C_DIM];            // LN(q), NHWC fp16
__device__ __half g_kvn [B * 3 * HW * C_DIM];        // warped+LN kv, NHWC fp16
__device__ __half g_q   [B * HW * INNER];            // conv q out, NHWC fp16 (pre-scaled)
__device__ __half g_kv  [B * 3 * HW * 2 * INNER];    // conv kv out, NHWC fp16
__device__ __half g_att [B * HW * INNER];            // attention out, NHWC fp16
__device__ __half g_wt_q  [9 * INNER * C_DIM];       // Wq*0.125 as [tap][oc][ic] fp16
__device__ __half g_wt_kv [9 * 2 * INNER * C_DIM];   // Wkv as [tap][oc][ic] fp16
__device__ __half g_wt_out[9 * C_DIM * INNER];       // Wout as [tap][oc][ic] fp16

// ---------------------------------------------------------------------------
// Kernel 0: weight transform  W[oc][ic][3][3] -> Wt[tap][oc][ic] (fp16, scaled)
// ---------------------------------------------------------------------------
__global__ void wtrans_kernel(const float* __restrict__ W,
                              __half* __restrict__ Wt, int OC, int IC,
                              float scale)
{
    int idx = blockIdx.x * blockDim.x + threadIdx.x;
    if (idx >= OC * IC) return;
    int oc = idx / IC, ic = idx % IC;
    const float* src = W + ((size_t)oc * IC + ic) * 9;
#pragma unroll
    for (int t = 0; t < 9; t++)
        Wt[((size_t)t * OC + oc) * IC + ic] = __float2half_rn(src[t] * scale);
}

// ---------------------------------------------------------------------------
// Kernel 1: LayerNorm q -> NHWC fp16. Two threads per pixel (32 ch each),
// pair-combined via shfl.
// ---------------------------------------------------------------------------
__global__ void ln_q_kernel(const float* __restrict__ q_inp,
                            const float* __restrict__ g,
                            const float* __restrict__ beta,
                            __half* __restrict__ out)
{
    int t   = blockIdx.x * blockDim.x + threadIdx.x;
    int pix = t >> 1;
    int hf  = t & 1;                 // channel half: 0 -> ch 0..31, 1 -> 32..63
    if (pix >= HW) return;
    int bb = blockIdx.z;

    const float* base = q_inp + ((size_t)bb * C_DIM + hf * 32) * HW + pix;
    float v[32];
    float s = 0.f;
#pragma unroll
    for (int i = 0; i < 32; i++) { v[i] = base[(size_t)i * HW]; s += v[i]; }
    s += __shfl_xor_sync(0xffffffffu, s, 1);
    float mu = s * (1.f / C_DIM);
    float var = 0.f;
#pragma unroll
    for (int i = 0; i < 32; i++) { float d = v[i] - mu; var += d * d; }
    var += __shfl_xor_sync(0xffffffffu, var, 1);
    var *= (1.f / C_DIM);
    float inv = rsqrtf(var + LN_EPS);

    __half2 h[16];
#pragma unroll
    for (int i = 0; i < 32; i += 2) {
        int c = hf * 32 + i;
        h[i >> 1] = __floats2half2_rn((v[i]   - mu) * inv * g[c]   + beta[c],
                                      (v[i+1] - mu) * inv * g[c+1] + beta[c+1]);
    }
    __half* ob = out + ((size_t)bb * HW + pix) * C_DIM + hf * 32;
#pragma unroll
    for (int q4 = 0; q4 < 4; q4++)
        *(uint4*)&ob[q4 * 8] = ((uint4*)h)[q4];
}

// ---------------------------------------------------------------------------
// Kernel 2: flow warp + stack + LayerNorm kv -> NHWC fp16 (2 threads/pixel)
// ---------------------------------------------------------------------------
__global__ void warp_ln_kv_kernel(const float* __restrict__ k_inp,
                                  const float* __restrict__ flow_f,
                                  const float* __restrict__ flow_b,
                                  const float* __restrict__ g,
                                  const float* __restrict__ beta,
                                  __half* __restrict__ out)
{
    int t   = blockIdx.x * blockDim.x + threadIdx.x;
    int pix = t >> 1;
    int hf  = t & 1;
    if (pix >= HW) return;
    int f  = blockIdx.y;   // 0..2
    int bb = blockIdx.z;   // 0..1
    int y = pix >> 7, x = pix & 127;

    int src = pix;
    bool valid = true;
    if (f != 1) {
        const float* fl = (f == 0) ? flow_f : flow_b;
        float fx = fl[((size_t)bb * 2 + 0) * HW + pix];
        float fy = fl[((size_t)bb * 2 + 1) * HW + pix];
        int ix = (int)rintf((float)x + fx);
        int iy = (int)rintf((float)y + fy);
        valid = (ix >= 0) && (ix < W_IMG) && (iy >= 0) && (iy < H_IMG);
        int cx = min(max(ix, 0), W_IMG - 1);
        int cy = min(max(iy, 0), H_IMG - 1);
        src = cy * W_IMG + cx;
    }

    const float* base = k_inp + (((size_t)bb * 3 + f) * C_DIM + hf * 32) * HW + src;
    float v[32];
    float s = 0.f;
#pragma unroll
    for (int i = 0; i < 32; i++) {
        float vv = valid ? base[(size_t)i * HW] : 0.f;
        v[i] = vv; s += vv;
    }
    s += __shfl_xor_sync(0xffffffffu, s, 1);
    float mu = s * (1.f / C_DIM);
    float var = 0.f;
#pragma unroll
    for (int i = 0; i < 32; i++) { float d = v[i] - mu; var += d * d; }
    var += __shfl_xor_sync(0xffffffffu, var, 1);
    var *= (1.f / C_DIM);
    float inv = rsqrtf(var + LN_EPS);

    __half2 h[16];
#pragma unroll
    for (int i = 0; i < 32; i += 2) {
        int c = hf * 32 + i;
        h[i >> 1] = __floats2half2_rn((v[i]   - mu) * inv * g[c]   + beta[c],
                                      (v[i+1] - mu) * inv * g[c+1] + beta[c+1]);
    }
    __half* ob = out + (((size_t)(bb * 3 + f)) * HW + pix) * C_DIM + hf * 32;
#pragma unroll
    for (int q4 = 0; q4 < 4; q4++)
        *(uint4*)&ob[q4 * 8] = ((uint4*)h)[q4];
}

// ---------------------------------------------------------------------------
// Kernel 3: 3x3 conv as implicit GEMM on wmma fp16 (m16n16k16, fp32 accum).
// One CTA = ROWS rows x 64 output channels; all 9 taps staged per chunk.
// Warp layout: ROWS x PXG x NOCG = 8; warp tile = (MF*16) px x (NF*16) oc.
// ---------------------------------------------------------------------------
#define AROWH 72                            // halfs per px (64 + 8 pad)

template <int ROWS, int MF, bool OUT_FP16_NHWC>
__global__ __launch_bounds__(256, 1)
void conv3x3_h_kernel(const __half* __restrict__ in,   // NHWC fp16
                      const __half* __restrict__ Wt,   // [9][OC][IC] fp16
                      void* __restrict__ out_raw,
                      int IC, int OC)
{
    constexpr int PXG  = 128 / (16 * MF);    // px groups
    constexpr int NOCG = 8 / (ROWS * PXG);   // oc groups
    constexpr int OCW  = 64 / NOCG;          // oc per warp
    constexpr int NF   = OCW / 16;           // B fragments per warp
    static_assert(ROWS * PXG * NOCG == 8, "warp layout");
    constexpr int A_ELEMS = (ROWS + 2) * 130 * AROWH;
    constexpr int B_ELEMS = 9 * 64 * AROWH;

    extern __shared__ __half smh[];
    __half* sA   = smh;
    __half* sB   = smh + A_ELEMS;
    float*  sEpi = (float*)(smh + A_ELEMS + B_ELEMS);   // 8 x 320 floats

    int tid  = threadIdx.x;
    int wid  = tid >> 5;
    int lane = tid & 31;

    int y0  = blockIdx.x * ROWS;
    int oc0 = blockIdx.y * 64;
    int img = blockIdx.z;

    int warp_row = wid % ROWS;
    int warp_pxg = (wid / ROWS) % PXG;
    int warp_ocg = wid / (ROWS * PXG);

    wmma::fragment<wmma::accumulator, 16, 16, 16, float> acc[MF][NF];
#pragma unroll
    for (int mf = 0; mf < MF; mf++)
#pragma unroll
        for (int nf = 0; nf < NF; nf++) wmma::fill_fragment(acc[mf][nf], 0.0f);

    const int chunks = IC / 64;

    for (int c = 0; c < chunks; c++) {
        int ic0 = c * 64;

        __syncthreads();
        // ---- stage A: (ROWS+2) rows x 130 px x 64 ic ----
        for (int i = tid; i < (ROWS + 2) * 130 * 8; i += 256) {
            int r   = i / (130 * 8);
            int rem = i % (130 * 8);
            int p   = rem >> 3;
            int v   = rem & 7;
            int gy = y0 + r - 1, gx = p - 1;
            uint4 d = make_uint4(0u, 0u, 0u, 0u);
            if (gy >= 0 && gy < H_IMG && gx >= 0 && gx < W_IMG)
                d = *(const uint4*)&in[(((size_t)img * H_IMG + gy) * W_IMG + gx) * IC + ic0 + v * 8];
            *(uint4*)&sA[(r * 130 + p) * AROWH + v * 8] = d;
        }
        // ---- stage B: 9 taps x 64 oc x 64 ic ----
        for (int i = tid; i < 9 * 64 * 8; i += 256) {
            int tap = i / (64 * 8);
            int rem = i % (64 * 8);
            int o   = rem >> 3;
            int v   = rem & 7;
            *(uint4*)&sB[(tap * 64 + o) * AROWH + v * 8] =
                *(const uint4*)&Wt[(((size_t)tap * OC) + oc0 + o) * IC + ic0 + v * 8];
        }
        __syncthreads();

        // ---- compute: 9 taps x 4 k-steps, no barriers ----
#pragma unroll
        for (int dy = 0; dy < 3; dy++) {
#pragma unroll
            for (int dx = 0; dx < 3; dx++) {
                const int tap = dy * 3 + dx;
#pragma unroll
                for (int s = 0; s < 4; s++) {
                    wmma::fragment<wmma::matrix_b, 16, 16, 16, __half,
                                   wmma::col_major> bf[NF];
#pragma unroll
                    for (int nf = 0; nf < NF; nf++)
                        wmma::load_matrix_sync(
                            bf[nf],
                            &sB[(tap * 64 + warp_ocg * OCW + nf * 16) * AROWH + s * 16],
                            AROWH);
#pragma unroll
                    for (int mf = 0; mf < MF; mf++) {
                        int px = warp_pxg * (MF * 16) + mf * 16;
                        wmma::fragment<wmma::matrix_a, 16, 16, 16, __half,
                                       wmma::row_major> af;
                        wmma::load_matrix_sync(
                            af,
                            &sA[((warp_row + dy) * 130 + px + dx) * AROWH + s * 16],
                            AROWH);
#pragma unroll
                        for (int nf = 0; nf < NF; nf++)
                            wmma::mma_sync(acc[mf][nf], af, bf[nf], acc[mf][nf]);
                    }
                }
            }
        }
    }

    // ---- epilogue ----
    int y = y0 + warp_row;
    if (OUT_FP16_NHWC) {
        __half* outp = (__half*)out_raw;
        float* buf = sEpi + wid * 320;            // 16 x 20 fp32 per warp
        int r  = lane >> 1;
        int hp = lane & 1;
#pragma unroll
        for (int mf = 0; mf < MF; mf++) {
            int px = warp_pxg * (MF * 16) + mf * 16;
#pragma unroll
            for (int nf = 0; nf < NF; nf++) {
                int oc = oc0 + warp_ocg * OCW + nf * 16;
                wmma::store_matrix_sync(buf, acc[mf][nf], 20, wmma::mem_row_major);
                __syncwarp();
                float4 a = *(float4*)&buf[r * 20 + hp * 8];
                float4 b = *(float4*)&buf[r * 20 + hp * 8 + 4];
                __half2 h[4];
                h[0] = __floats2half2_rn(a.x, a.y);
                h[1] = __floats2half2_rn(a.z, a.w);
                h[2] = __floats2half2_rn(b.x, b.y);
                h[3] = __floats2half2_rn(b.z, b.w);
                *(uint4*)&outp[(((size_t)img * H_IMG + y) * W_IMG + px + r) * OC + oc + hp * 8] =
                    *(uint4*)h;
                __syncwarp();
            }
        }
    } else {
        float* outp = (float*)out_raw;            // NCHW fp32 (d_out)
#pragma unroll
        for (int mf = 0; mf < MF; mf++) {
            int px = warp_pxg * (MF * 16) + mf * 16;
#pragma unroll
            for (int nf = 0; nf < NF; nf++) {
                int oc = oc0 + warp_ocg * OCW + nf * 16;
                float* dst = &outp[(((size_t)img * OC + oc) * H_IMG + y) * W_IMG + px];
                wmma::store_matrix_sync(dst, acc[mf][nf], HW, wmma::mem_col_major);
            }
        }
    }
}

// ---------------------------------------------------------------------------
// Kernel 4: windowed attention on tensor cores (warp per head).
// ---------------------------------------------------------------------------
#define QSTR 520                              // half stride per pixel row
#define FSTR 68                               // float stride, per-warp staging
#define PSTR 56                               // half stride, probs

__global__ __launch_bounds__(256, 1)
void attn_kernel(const __half* __restrict__ q,
                 const __half* __restrict__ kv,
                 const float* __restrict__ stat,
                 __half* __restrict__ outp)
{
    extern __shared__ __half smh[];
    __half* sQ = smh;                         // [16][QSTR]
    __half* sK = sQ + Q_L * QSTR;             // [48][QSTR]
    __half* sV = sK + KV_L * QSTR;            // [48][QSTR]
    float*  fB = (float*)(sV + KV_L * QSTR);  // 8 x [16][FSTR]
    __half* sP = (__half*)(fB + 8 * Q_L * FSTR); // 8 x [16][PSTR]

    int tid  = threadIdx.x;
    int wid  = tid >> 5;                      // head
    int lane = tid & 31;
    int win = blockIdx.x;
    int bb  = blockIdx.z;
    int wy = win >> 5, wx = win & 31;
    int d0 = wid * DIM_HEAD;

    for (int i = tid; i < Q_L * 64; i += 256) {
        int pi = i >> 6, v = i & 63;
        int py = pi >> 2, px = pi & 3;
        int pix = (wy * 4 + py) * W_IMG + wx * 4 + px;
        *(uint4*)&sQ[pi * QSTR + v * 8] =
            *(const uint4*)&q[((size_t)bb * HW + pix) * INNER + v * 8];
    }
    for (int i = tid; i < KV_L * 64; i += 256) {
        int j = i >> 6, v = i & 63;
        int f = j >> 4, pi = j & 15;
        int py = pi >> 2, px = pi & 3;
        int pix = (wy * 4 + py) * W_IMG + wx * 4 + px;
        size_t base = ((size_t)(bb * 3 + f) * HW + pix) * (2 * INNER);
        *(uint4*)&sK[j * QSTR + v * 8] = *(const uint4*)&kv[base + v * 8];
        *(uint4*)&sV[j * QSTR + v * 8] = *(const uint4*)&kv[base + INNER + v * 8];
    }
    __syncthreads();

    float*  fbw = fB + wid * Q_L * FSTR;
    __half* spw = sP + wid * Q_L * PSTR;

    // ---- sim = q k^T ----
    wmma::fragment<wmma::accumulator, 16, 16, 16, float> sim[3];
#pragma unroll
    for (int n = 0; n < 3; n++) wmma::fill_fragment(sim[n], 0.0f);
#pragma unroll
    for (int s = 0; s < 4; s++) {
        wmma::fragment<wmma::matrix_a, 16, 16, 16, __half, wmma::row_major> af;
        wmma::load_matrix_sync(af, &sQ[d0 + s * 16], QSTR);
#pragma unroll
        for (int n = 0; n < 3; n++) {
            wmma::fragment<wmma::matrix_b, 16, 16, 16, __half, wmma::col_major> bf;
            wmma::load_matrix_sync(bf, &sK[n * 16 * QSTR + d0 + s * 16], QSTR);
            wmma::mma_sync(sim[n], af, bf, sim[n]);
        }
    }
#pragma unroll
    for (int n = 0; n < 3; n++)
        wmma::store_matrix_sync(&fbw[n * 16], sim[n], FSTR, wmma::mem_row_major);
    __syncwarp();

    for (int e = lane; e < Q_L * KV_L; e += 32) {
        int i = e / KV_L, j = e % KV_L;
        fbw[i * FSTR + j] += stat[((size_t)wid * Q_L + i) * KV_L + j];
    }
    __syncwarp();

    if (lane < Q_L) {
        float* row = &fbw[lane * FSTR];
        float m = -1e30f;
#pragma unroll
        for (int j = 0; j < KV_L; j++) m = fmaxf(m, row[j]);
        float ssum = 0.f;
#pragma unroll
        for (int j = 0; j < KV_L; j++) {
            float e = expf(row[j] - m);
            row[j] = e; ssum += e;
        }
        float inv = 1.f / ssum;
#pragma unroll
        for (int j = 0; j < KV_L; j++) row[j] *= inv;
    }
    __syncwarp();

    for (int e = lane; e < Q_L * KV_L; e += 32) {
        int i = e / KV_L, j = e % KV_L;
        spw[i * PSTR + j] = __float2half_rn(fbw[i * FSTR + j]);
    }
    __syncwarp();

    // ---- out = p v ----
    wmma::fragment<wmma::accumulator, 16, 16, 16, float> oacc[4];
#pragma unroll
    for (int n = 0; n < 4; n++) wmma::fill_fragment(oacc[n], 0.0f);
#pragma unroll
    for (int s = 0; s < 3; s++) {
        wmma::fragment<wmma::matrix_a, 16, 16, 16, __half, wmma::row_major> af;
        wmma::load_matrix_sync(af, &spw[s * 16], PSTR);
#pragma unroll
        for (int n = 0; n < 4; n++) {
            wmma::fragment<wmma::matrix_b, 16, 16, 16, __half, wmma::row_major> bf;
            wmma::load_matrix_sync(bf, &sV[s * 16 * QSTR + d0 + n * 16], QSTR);
            wmma::mma_sync(oacc[n], af, bf, oacc[n]);
        }
    }
#pragma unroll
    for (int n = 0; n < 4; n++)
        wmma::store_matrix_sync(&fbw[n * 16], oacc[n], FSTR, wmma::mem_row_major);
    __syncwarp();

    {
        int r  = lane >> 1;
        int hp = lane & 1;
        int py = r >> 2, px = r & 3;
        int pix = (wy * 4 + py) * W_IMG + wx * 4 + px;
        __half* dst = &outp[((size_t)bb * HW + pix) * INNER + d0 + hp * 32];
        const float* srcr = &fbw[r * FSTR + hp * 32];
        __half2 h[16];
#pragma unroll
        for (int t = 0; t < 16; t++)
            h[t] = __floats2half2_rn(srcr[t * 2], srcr[t * 2 + 1]);
#pragma unroll
        for (int t = 0; t < 4; t++)
            *(uint4*)&dst[t * 8] = ((uint4*)h)[t];
    }
}

// ---------------------------------------------------------------------------
// Host launch
// ---------------------------------------------------------------------------
extern "C" void kernel_launch(void* const* d_in, const int* in_sizes, int n_in,
                              void* d_out, int out_size)
{
    (void)in_sizes; (void)n_in; (void)out_size;

    const float* q_inp   = (const float*)d_in[0];
    const float* k_inp   = (const float*)d_in[1];
    const float* flow_f  = (const float*)d_in[2];
    const float* flow_b  = (const float*)d_in[3];
    const float* gq      = (const float*)d_in[4];
    const float* bq      = (const float*)d_in[5];
    const float* gkv     = (const float*)d_in[6];
    const float* bkv     = (const float*)d_in[7];
    const float* Wq      = (const float*)d_in[8];
    const float* Wkv     = (const float*)d_in[9];
    const float* Wout    = (const float*)d_in[10];
    const float* statica = (const float*)d_in[11];

    __half *qn, *kvn, *qb, *kvb, *attb, *wtq, *wtkv, *wtout;
    cudaGetSymbolAddress((void**)&qn,    g_qn);
    cudaGetSymbolAddress((void**)&kvn,   g_kvn);
    cudaGetSymbolAddress((void**)&qb,    g_q);
    cudaGetSymbolAddress((void**)&kvb,   g_kv);
    cudaGetSymbolAddress((void**)&attb,  g_att);
    cudaGetSymbolAddress((void**)&wtq,   g_wt_q);
    cudaGetSymbolAddress((void**)&wtkv,  g_wt_kv);
    cudaGetSymbolAddress((void**)&wtout, g_wt_out);

    const int SMEM4 = ((4 + 2) * 130 * AROWH + 9 * 64 * AROWH) * 2 + 8 * 320 * 4; // 205,504
    const int SMEM1 = ((1 + 2) * 130 * AROWH + 9 * 64 * AROWH) * 2;               // 139,104
    const int SMEMA = (Q_L + 2 * KV_L) * QSTR * 2
                    + 8 * Q_L * FSTR * 4
                    + 8 * Q_L * PSTR * 2;
    cudaFuncSetAttribute((const void*)conv3x3_h_kernel<4, 4, true>,
                         cudaFuncAttributeMaxDynamicSharedMemorySize, SMEM4);
    cudaFuncSetAttribute((const void*)conv3x3_h_kernel<1, 2, false>,
                         cudaFuncAttributeMaxDynamicSharedMemorySize, SMEM1);
    cudaFuncSetAttribute((const void*)attn_kernel,
                         cudaFuncAttributeMaxDynamicSharedMemorySize, SMEMA);

    // 0) weight transforms (fp16; q-scale 0.125 folded into Wq)
    wtrans_kernel<<<(INNER * C_DIM + 255) / 256, 256>>>(Wq, wtq, INNER, C_DIM, 0.125f);
    wtrans_kernel<<<(2 * INNER * C_DIM + 255) / 256, 256>>>(Wkv, wtkv, 2 * INNER, C_DIM, 1.0f);
    wtrans_kernel<<<(C_DIM * INNER + 255) / 256, 256>>>(Wout, wtout, C_DIM, INNER, 1.0f);

    // 1) layernorm q  (NHWC fp16, 2 threads/px)
    ln_q_kernel<<<dim3(2 * HW / 256, 1, B), 256>>>(q_inp, gq, bq, qn);

    // 2) warp + stack + layernorm kv  (NHWC fp16, 2 threads/px)
    warp_ln_kv_kernel<<<dim3(2 * HW / 256, 3, B), 256>>>(k_inp, flow_f, flow_b, gkv, bkv, kvn);

    // 3) conv q: 64 -> 512 : 512 CTAs (R9 shape)
    conv3x3_h_kernel<4, 4, true><<<dim3(H_IMG / 4, INNER / 64, B), 256, SMEM4>>>(
        qn, wtq, qb, C_DIM, INNER);

    // 4) conv kv: 64 -> 1024 : 3072 CTAs (R9 shape)
    conv3x3_h_kernel<4, 4, true><<<dim3(H_IMG / 4, (2 * INNER) / 64, B * 3), 256, SMEM4>>>(
        kvn, wtkv, kvb, C_DIM, 2 * INNER);

    // 5) attention: tensor-core, one block per window
    attn_kernel<<<dim3(1024, 1, B), 256, SMEMA>>>(qb, kvb, statica, attb);

    // 6) conv out: 512 -> 64, fp32 NCHW -> d_out : 256 CTAs (1-row strips)
    conv3x3_h_kernel<1, 2, false><<<dim3(H_IMG, 1, B), 256, SMEM1>>>(
        attb, wtout, (float*)d_out, INNER, C_DIM);
}

// round 12
// speedup vs baseline: 1.0476x; 1.0326x over previous
#include <cuda_runtime.h>
#include <cuda_fp16.h>
#include <mma.h>
#include <math.h>
#include <stdint.h>

using namespace nvcuda;

// ---------------------------------------------------------------------------
// Problem constants
// ---------------------------------------------------------------------------
#define B       2
#define C_DIM   64
#define H_IMG   128
#define W_IMG   128
#define HW      (H_IMG * W_IMG)          // 16384
#define HEADS   8
#define DIM_HEAD 64
#define INNER   (HEADS * DIM_HEAD)       // 512
#define Q_L     16
#define KV_L    48
#define LN_EPS  1e-5f

// ---------------------------------------------------------------------------
// Scratch buffers (__device__ globals; allocation is forbidden)
// ---------------------------------------------------------------------------
__device__ __half g_qn  [B * HW * C_DIM];            // LN(q), NHWC fp16
__device__ __half g_kvn [B * 3 * HW * C_DIM];        // warped+LN kv, NHWC fp16
__device__ __half g_q   [B * HW * INNER];            // conv q out, NHWC fp16 (pre-scaled)
__device__ __half g_kv  [B * 3 * HW * 2 * INNER];    // conv kv out, NHWC fp16
__device__ __half g_att [B * HW * INNER];            // attention out, NHWC fp16
__device__ __half g_wt_q  [9 * INNER * C_DIM];       // Wq*0.125 as [tap][oc][ic] fp16
__device__ __half g_wt_kv [9 * 2 * INNER * C_DIM];   // Wkv as [tap][oc][ic] fp16
__device__ __half g_wt_out[9 * C_DIM * INNER];       // Wout as [tap][oc][ic] fp16

// ---------------------------------------------------------------------------
// Kernel 0: weight transform  W[oc][ic][3][3] -> Wt[tap][oc][ic] (fp16, scaled)
// ---------------------------------------------------------------------------
__global__ void wtrans_kernel(const float* __restrict__ W,
                              __half* __restrict__ Wt, int OC, int IC,
                              float scale)
{
    int idx = blockIdx.x * blockDim.x + threadIdx.x;
    if (idx >= OC * IC) return;
    int oc = idx / IC, ic = idx % IC;
    const float* src = W + ((size_t)oc * IC + ic) * 9;
#pragma unroll
    for (int t = 0; t < 9; t++)
        Wt[((size_t)t * OC + oc) * IC + ic] = __float2half_rn(src[t] * scale);
}

// ---------------------------------------------------------------------------
// Kernel 1: LayerNorm q -> NHWC fp16. Two threads per pixel (32 ch each),
// pair-combined via shfl.
// ---------------------------------------------------------------------------
__global__ void ln_q_kernel(const float* __restrict__ q_inp,
                            const float* __restrict__ g,
                            const float* __restrict__ beta,
                            __half* __restrict__ out)
{
    int t   = blockIdx.x * blockDim.x + threadIdx.x;
    int pix = t >> 1;
    int hf  = t & 1;                 // channel half: 0 -> ch 0..31, 1 -> 32..63
    if (pix >= HW) return;
    int bb = blockIdx.z;

    const float* base = q_inp + ((size_t)bb * C_DIM + hf * 32) * HW + pix;
    float v[32];
    float s = 0.f;
#pragma unroll
    for (int i = 0; i < 32; i++) { v[i] = base[(size_t)i * HW]; s += v[i]; }
    s += __shfl_xor_sync(0xffffffffu, s, 1);
    float mu = s * (1.f / C_DIM);
    float var = 0.f;
#pragma unroll
    for (int i = 0; i < 32; i++) { float d = v[i] - mu; var += d * d; }
    var += __shfl_xor_sync(0xffffffffu, var, 1);
    var *= (1.f / C_DIM);
    float inv = rsqrtf(var + LN_EPS);

    __half2 h[16];
#pragma unroll
    for (int i = 0; i < 32; i += 2) {
        int c = hf * 32 + i;
        h[i >> 1] = __floats2half2_rn((v[i]   - mu) * inv * g[c]   + beta[c],
                                      (v[i+1] - mu) * inv * g[c+1] + beta[c+1]);
    }
    __half* ob = out + ((size_t)bb * HW + pix) * C_DIM + hf * 32;
#pragma unroll
    for (int q4 = 0; q4 < 4; q4++)
        *(uint4*)&ob[q4 * 8] = ((uint4*)h)[q4];
}

// ---------------------------------------------------------------------------
// Kernel 2: flow warp + stack + LayerNorm kv -> NHWC fp16 (2 threads/pixel)
// ---------------------------------------------------------------------------
__global__ void warp_ln_kv_kernel(const float* __restrict__ k_inp,
                                  const float* __restrict__ flow_f,
                                  const float* __restrict__ flow_b,
                                  const float* __restrict__ g,
                                  const float* __restrict__ beta,
                                  __half* __restrict__ out)
{
    int t   = blockIdx.x * blockDim.x + threadIdx.x;
    int pix = t >> 1;
    int hf  = t & 1;
    if (pix >= HW) return;
    int f  = blockIdx.y;   // 0..2
    int bb = blockIdx.z;   // 0..1
    int y = pix >> 7, x = pix & 127;

    int src = pix;
    bool valid = true;
    if (f != 1) {
        const float* fl = (f == 0) ? flow_f : flow_b;
        float fx = fl[((size_t)bb * 2 + 0) * HW + pix];
        float fy = fl[((size_t)bb * 2 + 1) * HW + pix];
        int ix = (int)rintf((float)x + fx);
        int iy = (int)rintf((float)y + fy);
        valid = (ix >= 0) && (ix < W_IMG) && (iy >= 0) && (iy < H_IMG);
        int cx = min(max(ix, 0), W_IMG - 1);
        int cy = min(max(iy, 0), H_IMG - 1);
        src = cy * W_IMG + cx;
    }

    const float* base = k_inp + (((size_t)bb * 3 + f) * C_DIM + hf * 32) * HW + src;
    float v[32];
    float s = 0.f;
#pragma unroll
    for (int i = 0; i < 32; i++) {
        float vv = valid ? base[(size_t)i * HW] : 0.f;
        v[i] = vv; s += vv;
    }
    s += __shfl_xor_sync(0xffffffffu, s, 1);
    float mu = s * (1.f / C_DIM);
    float var = 0.f;
#pragma unroll
    for (int i = 0; i < 32; i++) { float d = v[i] - mu; var += d * d; }
    var += __shfl_xor_sync(0xffffffffu, var, 1);
    var *= (1.f / C_DIM);
    float inv = rsqrtf(var + LN_EPS);

    __half2 h[16];
#pragma unroll
    for (int i = 0; i < 32; i += 2) {
        int c = hf * 32 + i;
        h[i >> 1] = __floats2half2_rn((v[i]   - mu) * inv * g[c]   + beta[c],
                                      (v[i+1] - mu) * inv * g[c+1] + beta[c+1]);
    }
    __half* ob = out + (((size_t)(bb * 3 + f)) * HW + pix) * C_DIM + hf * 32;
#pragma unroll
    for (int q4 = 0; q4 < 4; q4++)
        *(uint4*)&ob[q4 * 8] = ((uint4*)h)[q4];
}

// ---------------------------------------------------------------------------
// Kernel 3: 3x3 conv as implicit GEMM on wmma fp16 (m16n16k16, fp32 accum).
// One CTA = ROWS rows x 64 output channels; all 9 taps staged per chunk.
// Warp layout: ROWS x PXG x NOCG = 8; warp tile = (MF*16) px x (NF*16) oc.
// q/kv: ROWS=4, MF=4 (NF=4). conv_out: ROWS=2, MF=4 (NF=2).  [R9 shapes]
// ---------------------------------------------------------------------------
#define AROWH 72                            // halfs per px (64 + 8 pad)

template <int ROWS, int MF, bool OUT_FP16_NHWC>
__global__ __launch_bounds__(256, 1)
void conv3x3_h_kernel(const __half* __restrict__ in,   // NHWC fp16
                      const __half* __restrict__ Wt,   // [9][OC][IC] fp16
                      void* __restrict__ out_raw,
                      int IC, int OC)
{
    constexpr int PXG  = 128 / (16 * MF);    // px groups
    constexpr int NOCG = 8 / (ROWS * PXG);   // oc groups
    constexpr int OCW  = 64 / NOCG;          // oc per warp
    constexpr int NF   = OCW / 16;           // B fragments per warp
    static_assert(ROWS * PXG * NOCG == 8, "warp layout");
    constexpr int A_ELEMS = (ROWS + 2) * 130 * AROWH;
    constexpr int B_ELEMS = 9 * 64 * AROWH;

    extern __shared__ __half smh[];
    __half* sA   = smh;
    __half* sB   = smh + A_ELEMS;
    float*  sEpi = (float*)(smh + A_ELEMS + B_ELEMS);   // 8 x 320 floats

    int tid  = threadIdx.x;
    int wid  = tid >> 5;
    int lane = tid & 31;

    int y0  = blockIdx.x * ROWS;
    int oc0 = blockIdx.y * 64;
    int img = blockIdx.z;

    int warp_row = wid % ROWS;
    int warp_pxg = (wid / ROWS) % PXG;
    int warp_ocg = wid / (ROWS * PXG);

    wmma::fragment<wmma::accumulator, 16, 16, 16, float> acc[MF][NF];
#pragma unroll
    for (int mf = 0; mf < MF; mf++)
#pragma unroll
        for (int nf = 0; nf < NF; nf++) wmma::fill_fragment(acc[mf][nf], 0.0f);

    const int chunks = IC / 64;

    for (int c = 0; c < chunks; c++) {
        int ic0 = c * 64;

        __syncthreads();
        // ---- stage A: (ROWS+2) rows x 130 px x 64 ic ----
        for (int i = tid; i < (ROWS + 2) * 130 * 8; i += 256) {
            int r   = i / (130 * 8);
            int rem = i % (130 * 8);
            int p   = rem >> 3;
            int v   = rem & 7;
            int gy = y0 + r - 1, gx = p - 1;
            uint4 d = make_uint4(0u, 0u, 0u, 0u);
            if (gy >= 0 && gy < H_IMG && gx >= 0 && gx < W_IMG)
                d = *(const uint4*)&in[(((size_t)img * H_IMG + gy) * W_IMG + gx) * IC + ic0 + v * 8];
            *(uint4*)&sA[(r * 130 + p) * AROWH + v * 8] = d;
        }
        // ---- stage B: 9 taps x 64 oc x 64 ic ----
        for (int i = tid; i < 9 * 64 * 8; i += 256) {
            int tap = i / (64 * 8);
            int rem = i % (64 * 8);
            int o   = rem >> 3;
            int v   = rem & 7;
            *(uint4*)&sB[(tap * 64 + o) * AROWH + v * 8] =
                *(const uint4*)&Wt[(((size_t)tap * OC) + oc0 + o) * IC + ic0 + v * 8];
        }
        __syncthreads();

        // ---- compute: 9 taps x 4 k-steps, no barriers ----
#pragma unroll
        for (int dy = 0; dy < 3; dy++) {
#pragma unroll
            for (int dx = 0; dx < 3; dx++) {
                const int tap = dy * 3 + dx;
#pragma unroll
                for (int s = 0; s < 4; s++) {
                    wmma::fragment<wmma::matrix_b, 16, 16, 16, __half,
                                   wmma::col_major> bf[NF];
#pragma unroll
                    for (int nf = 0; nf < NF; nf++)
                        wmma::load_matrix_sync(
                            bf[nf],
                            &sB[(tap * 64 + warp_ocg * OCW + nf * 16) * AROWH + s * 16],
                            AROWH);
#pragma unroll
                    for (int mf = 0; mf < MF; mf++) {
                        int px = warp_pxg * (MF * 16) + mf * 16;
                        wmma::fragment<wmma::matrix_a, 16, 16, 16, __half,
                                       wmma::row_major> af;
                        wmma::load_matrix_sync(
                            af,
                            &sA[((warp_row + dy) * 130 + px + dx) * AROWH + s * 16],
                            AROWH);
#pragma unroll
                        for (int nf = 0; nf < NF; nf++)
                            wmma::mma_sync(acc[mf][nf], af, bf[nf], acc[mf][nf]);
                    }
                }
            }
        }
    }

    // ---- epilogue ----
    int y = y0 + warp_row;
    if (OUT_FP16_NHWC) {
        __half* outp = (__half*)out_raw;
        float* buf = sEpi + wid * 320;            // 16 x 20 fp32 per warp
        int r  = lane >> 1;
        int hp = lane & 1;
#pragma unroll
        for (int mf = 0; mf < MF; mf++) {
            int px = warp_pxg * (MF * 16) + mf * 16;
#pragma unroll
            for (int nf = 0; nf < NF; nf++) {
                int oc = oc0 + warp_ocg * OCW + nf * 16;
                wmma::store_matrix_sync(buf, acc[mf][nf], 20, wmma::mem_row_major);
                __syncwarp();
                float4 a = *(float4*)&buf[r * 20 + hp * 8];
                float4 b = *(float4*)&buf[r * 20 + hp * 8 + 4];
                __half2 h[4];
                h[0] = __floats2half2_rn(a.x, a.y);
                h[1] = __floats2half2_rn(a.z, a.w);
                h[2] = __floats2half2_rn(b.x, b.y);
                h[3] = __floats2half2_rn(b.z, b.w);
                *(uint4*)&outp[(((size_t)img * H_IMG + y) * W_IMG + px + r) * OC + oc + hp * 8] =
                    *(uint4*)h;
                __syncwarp();
            }
        }
    } else {
        float* outp = (float*)out_raw;            // NCHW fp32 (d_out)
#pragma unroll
        for (int mf = 0; mf < MF; mf++) {
            int px = warp_pxg * (MF * 16) + mf * 16;
#pragma unroll
            for (int nf = 0; nf < NF; nf++) {
                int oc = oc0 + warp_ocg * OCW + nf * 16;
                float* dst = &outp[(((size_t)img * OC + oc) * H_IMG + y) * W_IMG + px];
                wmma::store_matrix_sync(dst, acc[mf][nf], HW, wmma::mem_col_major);
            }
        }
    }
}

// ---------------------------------------------------------------------------
// Kernel 4: windowed attention on tensor cores (warp per head).
// ---------------------------------------------------------------------------
#define QSTR 520                              // half stride per pixel row
#define FSTR 68                               // float stride, per-warp staging
#define PSTR 56                               // half stride, probs

__global__ __launch_bounds__(256, 1)
void attn_kernel(const __half* __restrict__ q,
                 const __half* __restrict__ kv,
                 const float* __restrict__ stat,
                 __half* __restrict__ outp)
{
    extern __shared__ __half smh[];
    __half* sQ = smh;                         // [16][QSTR]
    __half* sK = sQ + Q_L * QSTR;             // [48][QSTR]
    __half* sV = sK + KV_L * QSTR;            // [48][QSTR]
    float*  fB = (float*)(sV + KV_L * QSTR);  // 8 x [16][FSTR]
    __half* sP = (__half*)(fB + 8 * Q_L * FSTR); // 8 x [16][PSTR]

    int tid  = threadIdx.x;
    int wid  = tid >> 5;                      // head
    int lane = tid & 31;
    int win = blockIdx.x;
    int bb  = blockIdx.z;
    int wy = win >> 5, wx = win & 31;
    int d0 = wid * DIM_HEAD;

    for (int i = tid; i < Q_L * 64; i += 256) {
        int pi = i >> 6, v = i & 63;
        int py = pi >> 2, px = pi & 3;
        int pix = (wy * 4 + py) * W_IMG + wx * 4 + px;
        *(uint4*)&sQ[pi * QSTR + v * 8] =
            *(const uint4*)&q[((size_t)bb * HW + pix) * INNER + v * 8];
    }
    for (int i = tid; i < KV_L * 64; i += 256) {
        int j = i >> 6, v = i & 63;
        int f = j >> 4, pi = j & 15;
        int py = pi >> 2, px = pi & 3;
        int pix = (wy * 4 + py) * W_IMG + wx * 4 + px;
        size_t base = ((size_t)(bb * 3 + f) * HW + pix) * (2 * INNER);
        *(uint4*)&sK[j * QSTR + v * 8] = *(const uint4*)&kv[base + v * 8];
        *(uint4*)&sV[j * QSTR + v * 8] = *(const uint4*)&kv[base + INNER + v * 8];
    }
    __syncthreads();

    float*  fbw = fB + wid * Q_L * FSTR;
    __half* spw = sP + wid * Q_L * PSTR;

    // ---- sim = q k^T ----
    wmma::fragment<wmma::accumulator, 16, 16, 16, float> sim[3];
#pragma unroll
    for (int n = 0; n < 3; n++) wmma::fill_fragment(sim[n], 0.0f);
#pragma unroll
    for (int s = 0; s < 4; s++) {
        wmma::fragment<wmma::matrix_a, 16, 16, 16, __half, wmma::row_major> af;
        wmma::load_matrix_sync(af, &sQ[d0 + s * 16], QSTR);
#pragma unroll
        for (int n = 0; n < 3; n++) {
            wmma::fragment<wmma::matrix_b, 16, 16, 16, __half, wmma::col_major> bf;
            wmma::load_matrix_sync(bf, &sK[n * 16 * QSTR + d0 + s * 16], QSTR);
            wmma::mma_sync(sim[n], af, bf, sim[n]);
        }
    }
#pragma unroll
    for (int n = 0; n < 3; n++)
        wmma::store_matrix_sync(&fbw[n * 16], sim[n], FSTR, wmma::mem_row_major);
    __syncwarp();

    for (int e = lane; e < Q_L * KV_L; e += 32) {
        int i = e / KV_L, j = e % KV_L;
        fbw[i * FSTR + j] += stat[((size_t)wid * Q_L + i) * KV_L + j];
    }
    __syncwarp();

    if (lane < Q_L) {
        float* row = &fbw[lane * FSTR];
        float m = -1e30f;
#pragma unroll
        for (int j = 0; j < KV_L; j++) m = fmaxf(m, row[j]);
        float ssum = 0.f;
#pragma unroll
        for (int j = 0; j < KV_L; j++) {
            float e = expf(row[j] - m);
            row[j] = e; ssum += e;
        }
        float inv = 1.f / ssum;
#pragma unroll
        for (int j = 0; j < KV_L; j++) row[j] *= inv;
    }
    __syncwarp();

    for (int e = lane; e < Q_L * KV_L; e += 32) {
        int i = e / KV_L, j = e % KV_L;
        spw[i * PSTR + j] = __float2half_rn(fbw[i * FSTR + j]);
    }
    __syncwarp();

    // ---- out = p v ----
    wmma::fragment<wmma::accumulator, 16, 16, 16, float> oacc[4];
#pragma unroll
    for (int n = 0; n < 4; n++) wmma::fill_fragment(oacc[n], 0.0f);
#pragma unroll
    for (int s = 0; s < 3; s++) {
        wmma::fragment<wmma::matrix_a, 16, 16, 16, __half, wmma::row_major> af;
        wmma::load_matrix_sync(af, &spw[s * 16], PSTR);
#pragma unroll
        for (int n = 0; n < 4; n++) {
            wmma::fragment<wmma::matrix_b, 16, 16, 16, __half, wmma::row_major> bf;
            wmma::load_matrix_sync(bf, &sV[s * 16 * QSTR + d0 + n * 16], QSTR);
            wmma::mma_sync(oacc[n], af, bf, oacc[n]);
        }
    }
#pragma unroll
    for (int n = 0; n < 4; n++)
        wmma::store_matrix_sync(&fbw[n * 16], oacc[n], FSTR, wmma::mem_row_major);
    __syncwarp();

    {
        int r  = lane >> 1;
        int hp = lane & 1;
        int py = r >> 2, px = r & 3;
        int pix = (wy * 4 + py) * W_IMG + wx * 4 + px;
        __half* dst = &outp[((size_t)bb * HW + pix) * INNER + d0 + hp * 32];
        const float* srcr = &fbw[r * FSTR + hp * 32];
        __half2 h[16];
#pragma unroll
        for (int t = 0; t < 16; t++)
            h[t] = __floats2half2_rn(srcr[t * 2], srcr[t * 2 + 1]);
#pragma unroll
        for (int t = 0; t < 4; t++)
            *(uint4*)&dst[t * 8] = ((uint4*)h)[t];
    }
}

// ---------------------------------------------------------------------------
// Host launch
// ---------------------------------------------------------------------------
extern "C" void kernel_launch(void* const* d_in, const int* in_sizes, int n_in,
                              void* d_out, int out_size)
{
    (void)in_sizes; (void)n_in; (void)out_size;

    const float* q_inp   = (const float*)d_in[0];
    const float* k_inp   = (const float*)d_in[1];
    const float* flow_f  = (const float*)d_in[2];
    const float* flow_b  = (const float*)d_in[3];
    const float* gq      = (const float*)d_in[4];
    const float* bq      = (const float*)d_in[5];
    const float* gkv     = (const float*)d_in[6];
    const float* bkv     = (const float*)d_in[7];
    const float* Wq      = (const float*)d_in[8];
    const float* Wkv     = (const float*)d_in[9];
    const float* Wout    = (const float*)d_in[10];
    const float* statica = (const float*)d_in[11];

    __half *qn, *kvn, *qb, *kvb, *attb, *wtq, *wtkv, *wtout;
    cudaGetSymbolAddress((void**)&qn,    g_qn);
    cudaGetSymbolAddress((void**)&kvn,   g_kvn);
    cudaGetSymbolAddress((void**)&qb,    g_q);
    cudaGetSymbolAddress((void**)&kvb,   g_kv);
    cudaGetSymbolAddress((void**)&attb,  g_att);
    cudaGetSymbolAddress((void**)&wtq,   g_wt_q);
    cudaGetSymbolAddress((void**)&wtkv,  g_wt_kv);
    cudaGetSymbolAddress((void**)&wtout, g_wt_out);

    const int SMEM4 = ((4 + 2) * 130 * AROWH + 9 * 64 * AROWH) * 2 + 8 * 320 * 4; // 205,504
    const int SMEM2 = ((2 + 2) * 130 * AROWH + 9 * 64 * AROWH) * 2;               // 157,824
    const int SMEMA = (Q_L + 2 * KV_L) * QSTR * 2
                    + 8 * Q_L * FSTR * 4
                    + 8 * Q_L * PSTR * 2;
    cudaFuncSetAttribute((const void*)conv3x3_h_kernel<4, 4, true>,
                         cudaFuncAttributeMaxDynamicSharedMemorySize, SMEM4);
    cudaFuncSetAttribute((const void*)conv3x3_h_kernel<2, 4, false>,
                         cudaFuncAttributeMaxDynamicSharedMemorySize, SMEM2);
    cudaFuncSetAttribute((const void*)attn_kernel,
                         cudaFuncAttributeMaxDynamicSharedMemorySize, SMEMA);

    // 0) weight transforms (fp16; q-scale 0.125 folded into Wq)
    wtrans_kernel<<<(INNER * C_DIM + 255) / 256, 256>>>(Wq, wtq, INNER, C_DIM, 0.125f);
    wtrans_kernel<<<(2 * INNER * C_DIM + 255) / 256, 256>>>(Wkv, wtkv, 2 * INNER, C_DIM, 1.0f);
    wtrans_kernel<<<(C_DIM * INNER + 255) / 256, 256>>>(Wout, wtout, C_DIM, INNER, 1.0f);

    // 1) layernorm q  (NHWC fp16, 2 threads/px)
    ln_q_kernel<<<dim3(2 * HW / 256, 1, B), 256>>>(q_inp, gq, bq, qn);

    // 2) warp + stack + layernorm kv  (NHWC fp16, 2 threads/px)
    warp_ln_kv_kernel<<<dim3(2 * HW / 256, 3, B), 256>>>(k_inp, flow_f, flow_b, gkv, bkv, kvn);

    // 3) conv q: 64 -> 512 : 512 CTAs (R9 shape)
    conv3x3_h_kernel<4, 4, true><<<dim3(H_IMG / 4, INNER / 64, B), 256, SMEM4>>>(
        qn, wtq, qb, C_DIM, INNER);

    // 4) conv kv: 64 -> 1024 : 3072 CTAs (R9 shape)
    conv3x3_h_kernel<4, 4, true><<<dim3(H_IMG / 4, (2 * INNER) / 64, B * 3), 256, SMEM4>>>(
        kvn, wtkv, kvb, C_DIM, 2 * INNER);

    // 5) attention: tensor-core, one block per window
    attn_kernel<<<dim3(1024, 1, B), 256, SMEMA>>>(qb, kvb, statica, attb);

    // 6) conv out: 512 -> 64, fp32 NCHW -> d_out : 128 CTAs (R9 shape)
    conv3x3_h_kernel<2, 4, false><<<dim3(H_IMG / 2, 1, B), 256, SMEM2>>>(
        attb, wtout, (float*)d_out, INNER, C_DIM);
}

// round 13
// speedup vs baseline: 1.1748x; 1.1215x over previous
#include <cuda_runtime.h>
#include <cuda_fp16.h>
#include <mma.h>
#include <math.h>
#include <stdint.h>

using namespace nvcuda;

// ---------------------------------------------------------------------------
// Problem constants
// ---------------------------------------------------------------------------
#define B       2
#define C_DIM   64
#define H_IMG   128
#define W_IMG   128
#define HW      (H_IMG * W_IMG)          // 16384
#define HEADS   8
#define DIM_HEAD 64
#define INNER   (HEADS * DIM_HEAD)       // 512
#define Q_L     16
#define KV_L    48
#define LN_EPS  1e-5f

// ---------------------------------------------------------------------------
// Scratch buffers (__device__ globals; allocation is forbidden)
// ---------------------------------------------------------------------------
__device__ __half g_qn  [B * HW * C_DIM];            // LN(q), NHWC fp16
__device__ __half g_kvn [B * 3 * HW * C_DIM];        // warped+LN kv, NHWC fp16
__device__ __half g_q   [B * HW * INNER];            // conv q out, NHWC fp16 (pre-scaled)
__device__ __half g_kv  [B * 3 * HW * 2 * INNER];    // conv kv out, NHWC fp16
__device__ __half g_att [B * HW * INNER];            // attention out, NHWC fp16
__device__ __half g_wt_q  [9 * INNER * C_DIM];       // Wq*0.125 as [tap][oc][ic] fp16
__device__ __half g_wt_kv [9 * 2 * INNER * C_DIM];   // Wkv as [tap][oc][ic] fp16
__device__ __half g_wt_out[9 * C_DIM * INNER];       // Wout as [tap][oc][ic] fp16

// ---------------------------------------------------------------------------
// cp.async helpers (16B, cg; zfill via src-size)
// ---------------------------------------------------------------------------
__device__ __forceinline__ void cp16z(uint32_t dst, const void* src, int sz) {
    asm volatile("cp.async.cg.shared.global [%0], [%1], 16, %2;"
                 :: "r"(dst), "l"(src), "r"(sz) : "memory");
}
__device__ __forceinline__ void cp16(uint32_t dst, const void* src) {
    asm volatile("cp.async.cg.shared.global [%0], [%1], 16;"
                 :: "r"(dst), "l"(src) : "memory");
}
#define CP_WAIT_ALL() asm volatile("cp.async.wait_all;" ::: "memory")

// ---------------------------------------------------------------------------
// Kernel 0: all three weight transforms in one launch.
// W[oc][ic][3][3] -> Wt[tap][oc][ic] (fp16; Wq scaled by 0.125)
// ---------------------------------------------------------------------------
__global__ void wtrans_all_kernel(const float* __restrict__ Wq,
                                  const float* __restrict__ Wkv,
                                  const float* __restrict__ Wout,
                                  __half* __restrict__ wtq,
                                  __half* __restrict__ wtkv,
                                  __half* __restrict__ wtout)
{
    int idx = blockIdx.x * blockDim.x + threadIdx.x;
    const float* W; __half* Wt; int OC, IC; float scale;
    if (idx < INNER * C_DIM) {
        W = Wq; Wt = wtq; OC = INNER; IC = C_DIM; scale = 0.125f;
    } else if (idx < INNER * C_DIM + 2 * INNER * C_DIM) {
        idx -= INNER * C_DIM;
        W = Wkv; Wt = wtkv; OC = 2 * INNER; IC = C_DIM; scale = 1.0f;
    } else if (idx < 2 * (INNER * C_DIM) + 2 * INNER * C_DIM) {
        idx -= 3 * INNER * C_DIM;
        W = Wout; Wt = wtout; OC = C_DIM; IC = INNER; scale = 1.0f;
    } else return;

    int oc = idx / IC, ic = idx % IC;
    const float* src = W + ((size_t)oc * IC + ic) * 9;
#pragma unroll
    for (int t = 0; t < 9; t++)
        Wt[((size_t)t * OC + oc) * IC + ic] = __float2half_rn(src[t] * scale);
}

// ---------------------------------------------------------------------------
// Kernel 1: merged LayerNorm (q and warped-kv) -> NHWC fp16.
// grid.y = 4: f in {0,1,2} -> kv frame f, f == 3 -> q.
// Two threads per pixel (32 ch each), pair-combined via shfl.
// ---------------------------------------------------------------------------
__global__ void ln_all_kernel(const float* __restrict__ q_inp,
                              const float* __restrict__ k_inp,
                              const float* __restrict__ flow_f,
                              const float* __restrict__ flow_b,
                              const float* __restrict__ gq,
                              const float* __restrict__ bq,
                              const float* __restrict__ gkv,
                              const float* __restrict__ bkv,
                              __half* __restrict__ qn,
                              __half* __restrict__ kvn)
{
    int t   = blockIdx.x * blockDim.x + threadIdx.x;
    int pix = t >> 1;
    int hf  = t & 1;                 // channel half
    if (pix >= HW) return;
    int f  = blockIdx.y;             // 0..2 kv, 3 q
    int bb = blockIdx.z;

    const float* base;
    const float* g;
    const float* beta;
    __half* ob;
    bool valid = true;

    if (f == 3) {
        base = q_inp + ((size_t)bb * C_DIM + hf * 32) * HW + pix;
        g = gq; beta = bq;
        ob = qn + ((size_t)bb * HW + pix) * C_DIM + hf * 32;
    } else {
        int y = pix >> 7, x = pix & 127;
        int src = pix;
        if (f != 1) {
            const float* fl = (f == 0) ? flow_f : flow_b;
            float fx = fl[((size_t)bb * 2 + 0) * HW + pix];
            float fy = fl[((size_t)bb * 2 + 1) * HW + pix];
            int ix = (int)rintf((float)x + fx);
            int iy = (int)rintf((float)y + fy);
            valid = (ix >= 0) && (ix < W_IMG) && (iy >= 0) && (iy < H_IMG);
            int cx = min(max(ix, 0), W_IMG - 1);
            int cy = min(max(iy, 0), H_IMG - 1);
            src = cy * W_IMG + cx;
        }
        base = k_inp + (((size_t)bb * 3 + f) * C_DIM + hf * 32) * HW + src;
        g = gkv; beta = bkv;
        ob = kvn + (((size_t)(bb * 3 + f)) * HW + pix) * C_DIM + hf * 32;
    }

    float v[32];
    float s = 0.f;
#pragma unroll
    for (int i = 0; i < 32; i++) {
        float vv = valid ? base[(size_t)i * HW] : 0.f;
        v[i] = vv; s += vv;
    }
    s += __shfl_xor_sync(0xffffffffu, s, 1);
    float mu = s * (1.f / C_DIM);
    float var = 0.f;
#pragma unroll
    for (int i = 0; i < 32; i++) { float d = v[i] - mu; var += d * d; }
    var += __shfl_xor_sync(0xffffffffu, var, 1);
    var *= (1.f / C_DIM);
    float inv = rsqrtf(var + LN_EPS);

    __half2 h[16];
#pragma unroll
    for (int i = 0; i < 32; i += 2) {
        int c = hf * 32 + i;
        h[i >> 1] = __floats2half2_rn((v[i]   - mu) * inv * g[c]   + beta[c],
                                      (v[i+1] - mu) * inv * g[c+1] + beta[c+1]);
    }
#pragma unroll
    for (int q4 = 0; q4 < 4; q4++)
        *(uint4*)&ob[q4 * 8] = ((uint4*)h)[q4];
}

// ---------------------------------------------------------------------------
// Kernel 3a: MERGED conv q + conv kv (single launch, linearized grid).
// ROWS=4, MF=4, NF=4 (R9-proven shape). IC=64 (single chunk). cp.async stage.
// CTA t<3072: kv (6 imgs x 16 oc-tiles x 32 y-strips); else q (2 x 8 x 32).
// ---------------------------------------------------------------------------
#define AROWH 72                            // halfs per px (64 + 8 pad)
#define A6_ELEMS (6 * 130 * AROWH)          // 56160 halfs

__global__ __launch_bounds__(256, 1)
void conv_qkv_kernel(const __half* __restrict__ qn,
                     const __half* __restrict__ wtq,
                     __half* __restrict__ qb,
                     const __half* __restrict__ kvn,
                     const __half* __restrict__ wtkv,
                     __half* __restrict__ kvb)
{
    constexpr int ROWS = 4, MF = 4, NF = 4, OCW = 64;

    extern __shared__ __half smh[];
    __half* sA   = smh;                               // [6][130][AROWH]
    __half* sB   = smh + A6_ELEMS;                    // [9][64][AROWH]
    float*  sEpi = (float*)(smh + A6_ELEMS + 9 * 64 * AROWH);

    uint32_t sA_u = (uint32_t)__cvta_generic_to_shared(sA);
    uint32_t sB_u = (uint32_t)__cvta_generic_to_shared(sB);

    int tid  = threadIdx.x;
    int wid  = tid >> 5;
    int lane = tid & 31;

    // ---- decode linearized grid ----
    const __half* in; const __half* Wt; __half* outp; int OC;
    int octile, ystrip;
    {
        int t = blockIdx.x;
        if (t < 3072) {                        // kv: img = t/512
            int img = t >> 9; int rem = t & 511;
            octile = rem >> 5; ystrip = rem & 31;
            in   = kvn + (size_t)img * HW * C_DIM;
            Wt   = wtkv;
            outp = kvb + (size_t)img * HW * (2 * INNER);
            OC   = 2 * INNER;
        } else {                               // q: img = (t-3072)/256
            t -= 3072;
            int img = t >> 8; int rem = t & 255;
            octile = rem >> 5; ystrip = rem & 31;
            in   = qn + (size_t)img * HW * C_DIM;
            Wt   = wtq;
            outp = qb + (size_t)img * HW * INNER;
            OC   = INNER;
        }
    }
    int y0  = ystrip * ROWS;
    int oc0 = octile * 64;

    int warp_row = wid & 3;                   // ROWS=4
    int warp_pxg = wid >> 2;                  // PXG=2

    wmma::fragment<wmma::accumulator, 16, 16, 16, float> acc[MF][NF];
#pragma unroll
    for (int mf = 0; mf < MF; mf++)
#pragma unroll
        for (int nf = 0; nf < NF; nf++) wmma::fill_fragment(acc[mf][nf], 0.0f);

    // ---- stage A via cp.async: 6 rows x 130 px x 64 ic ----
    for (int i = tid; i < 6 * 130 * 8; i += 256) {
        int r   = i / (130 * 8);
        int rem = i % (130 * 8);
        int p   = rem >> 3;
        int v   = rem & 7;
        int gy = y0 + r - 1, gx = p - 1;
        bool ok = (gy >= 0) && (gy < H_IMG) && (gx >= 0) && (gx < W_IMG);
        int cy = ok ? gy : 0, cx = ok ? gx : 0;
        const __half* src = &in[((size_t)cy * W_IMG + cx) * C_DIM + v * 8];
        cp16z(sA_u + ((r * 130 + p) * AROWH + v * 8) * 2, src, ok ? 16 : 0);
    }
    // ---- stage B via cp.async: 9 taps x 64 oc x 64 ic ----
    for (int i = tid; i < 9 * 64 * 8; i += 256) {
        int tap = i / (64 * 8);
        int rem = i % (64 * 8);
        int o   = rem >> 3;
        int v   = rem & 7;
        cp16(sB_u + ((tap * 64 + o) * AROWH + v * 8) * 2,
             &Wt[(((size_t)tap * OC) + oc0 + o) * C_DIM + v * 8]);
    }
    CP_WAIT_ALL();
    __syncthreads();

    // ---- compute: 9 taps x 4 k-steps ----
#pragma unroll
    for (int dy = 0; dy < 3; dy++) {
#pragma unroll
        for (int dx = 0; dx < 3; dx++) {
            const int tap = dy * 3 + dx;
#pragma unroll
            for (int s = 0; s < 4; s++) {
                wmma::fragment<wmma::matrix_b, 16, 16, 16, __half,
                               wmma::col_major> bf[NF];
#pragma unroll
                for (int nf = 0; nf < NF; nf++)
                    wmma::load_matrix_sync(
                        bf[nf], &sB[(tap * 64 + nf * 16) * AROWH + s * 16], AROWH);
#pragma unroll
                for (int mf = 0; mf < MF; mf++) {
                    int px = warp_pxg * 64 + mf * 16;
                    wmma::fragment<wmma::matrix_a, 16, 16, 16, __half,
                                   wmma::row_major> af;
                    wmma::load_matrix_sync(
                        af, &sA[((warp_row + dy) * 130 + px + dx) * AROWH + s * 16],
                        AROWH);
#pragma unroll
                    for (int nf = 0; nf < NF; nf++)
                        wmma::mma_sync(acc[mf][nf], af, bf[nf], acc[mf][nf]);
                }
            }
        }
    }

    // ---- epilogue: fp16 NHWC ----
    int y = y0 + warp_row;
    float* buf = sEpi + wid * 320;            // 16 x 20 fp32 per warp
    int r  = lane >> 1;
    int hp = lane & 1;
#pragma unroll
    for (int mf = 0; mf < MF; mf++) {
        int px = warp_pxg * 64 + mf * 16;
#pragma unroll
        for (int nf = 0; nf < NF; nf++) {
            int oc = oc0 + nf * 16;
            wmma::store_matrix_sync(buf, acc[mf][nf], 20, wmma::mem_row_major);
            __syncwarp();
            float4 a = *(float4*)&buf[r * 20 + hp * 8];
            float4 b = *(float4*)&buf[r * 20 + hp * 8 + 4];
            __half2 h[4];
            h[0] = __floats2half2_rn(a.x, a.y);
            h[1] = __floats2half2_rn(a.z, a.w);
            h[2] = __floats2half2_rn(b.x, b.y);
            h[3] = __floats2half2_rn(b.z, b.w);
            *(uint4*)&outp[((size_t)(y * W_IMG) + px + r) * OC + oc + hp * 8] =
                *(uint4*)h;
            __syncwarp();
        }
    }
}

// ---------------------------------------------------------------------------
// Kernel 3b: conv_out (512->64) — ROWS=2, MF=4, NF=2; 8 IC chunks; cp.async.
// fp32 NCHW output straight to d_out.
// ---------------------------------------------------------------------------
__global__ __launch_bounds__(256, 1)
void conv_out_kernel(const __half* __restrict__ in,   // NHWC fp16 (g_att)
                     const __half* __restrict__ Wt,   // [9][64][512] fp16
                     float* __restrict__ outp)        // NCHW fp32 (d_out)
{
    constexpr int ROWS = 2, MF = 4, NF = 2, OCW = 32;
    constexpr int IC = INNER, OC = C_DIM;
    constexpr int A_ELEMS = (ROWS + 2) * 130 * AROWH;

    extern __shared__ __half smh[];
    __half* sA = smh;
    __half* sB = smh + A_ELEMS;
    uint32_t sA_u = (uint32_t)__cvta_generic_to_shared(sA);
    uint32_t sB_u = (uint32_t)__cvta_generic_to_shared(sB);

    int tid  = threadIdx.x;
    int wid  = tid >> 5;

    int y0  = blockIdx.x * ROWS;
    int img = blockIdx.z;

    int warp_row = wid & 1;                   // ROWS=2
    int warp_pxg = (wid >> 1) & 1;            // PXG=2
    int warp_ocg = wid >> 2;                  // NOCG=2

    wmma::fragment<wmma::accumulator, 16, 16, 16, float> acc[MF][NF];
#pragma unroll
    for (int mf = 0; mf < MF; mf++)
#pragma unroll
        for (int nf = 0; nf < NF; nf++) wmma::fill_fragment(acc[mf][nf], 0.0f);

    for (int c = 0; c < IC / 64; c++) {
        int ic0 = c * 64;

        __syncthreads();
        for (int i = tid; i < (ROWS + 2) * 130 * 8; i += 256) {
            int r   = i / (130 * 8);
            int rem = i % (130 * 8);
            int p   = rem >> 3;
            int v   = rem & 7;
            int gy = y0 + r - 1, gx = p - 1;
            bool ok = (gy >= 0) && (gy < H_IMG) && (gx >= 0) && (gx < W_IMG);
            int cy = ok ? gy : 0, cx = ok ? gx : 0;
            const __half* src =
                &in[(((size_t)img * H_IMG + cy) * W_IMG + cx) * IC + ic0 + v * 8];
            cp16z(sA_u + ((r * 130 + p) * AROWH + v * 8) * 2, src, ok ? 16 : 0);
        }
        for (int i = tid; i < 9 * 64 * 8; i += 256) {
            int tap = i / (64 * 8);
            int rem = i % (64 * 8);
            int o   = rem >> 3;
            int v   = rem & 7;
            cp16(sB_u + ((tap * 64 + o) * AROWH + v * 8) * 2,
                 &Wt[(((size_t)tap * OC) + o) * IC + ic0 + v * 8]);
        }
        CP_WAIT_ALL();
        __syncthreads();

#pragma unroll
        for (int dy = 0; dy < 3; dy++) {
#pragma unroll
            for (int dx = 0; dx < 3; dx++) {
                const int tap = dy * 3 + dx;
#pragma unroll
                for (int s = 0; s < 4; s++) {
                    wmma::fragment<wmma::matrix_b, 16, 16, 16, __half,
                                   wmma::col_major> bf[NF];
#pragma unroll
                    for (int nf = 0; nf < NF; nf++)
                        wmma::load_matrix_sync(
                            bf[nf],
                            &sB[(tap * 64 + warp_ocg * OCW + nf * 16) * AROWH + s * 16],
                            AROWH);
#pragma unroll
                    for (int mf = 0; mf < MF; mf++) {
                        int px = warp_pxg * 64 + mf * 16;
                        wmma::fragment<wmma::matrix_a, 16, 16, 16, __half,
                                       wmma::row_major> af;
                        wmma::load_matrix_sync(
                            af, &sA[((warp_row + dy) * 130 + px + dx) * AROWH + s * 16],
                            AROWH);
#pragma unroll
                        for (int nf = 0; nf < NF; nf++)
                            wmma::mma_sync(acc[mf][nf], af, bf[nf], acc[mf][nf]);
                    }
                }
            }
        }
    }

    int y = y0 + warp_row;
#pragma unroll
    for (int mf = 0; mf < MF; mf++) {
        int px = warp_pxg * 64 + mf * 16;
#pragma unroll
        for (int nf = 0; nf < NF; nf++) {
            int oc = warp_ocg * OCW + nf * 16;
            float* dst = &outp[(((size_t)img * OC + oc) * H_IMG + y) * W_IMG + px];
            wmma::store_matrix_sync(dst, acc[mf][nf], HW, wmma::mem_col_major);
        }
    }
}

// ---------------------------------------------------------------------------
// Kernel 4: windowed attention on tensor cores (warp per head). Unchanged.
// ---------------------------------------------------------------------------
#define QSTR 520
#define FSTR 68
#define PSTR 56

__global__ __launch_bounds__(256, 1)
void attn_kernel(const __half* __restrict__ q,
                 const __half* __restrict__ kv,
                 const float* __restrict__ stat,
                 __half* __restrict__ outp)
{
    extern __shared__ __half smh[];
    __half* sQ = smh;                         // [16][QSTR]
    __half* sK = sQ + Q_L * QSTR;             // [48][QSTR]
    __half* sV = sK + KV_L * QSTR;            // [48][QSTR]
    float*  fB = (float*)(sV + KV_L * QSTR);  // 8 x [16][FSTR]
    __half* sP = (__half*)(fB + 8 * Q_L * FSTR); // 8 x [16][PSTR]

    int tid  = threadIdx.x;
    int wid  = tid >> 5;
    int lane = tid & 31;
    int win = blockIdx.x;
    int bb  = blockIdx.z;
    int wy = win >> 5, wx = win & 31;
    int d0 = wid * DIM_HEAD;

    for (int i = tid; i < Q_L * 64; i += 256) {
        int pi = i >> 6, v = i & 63;
        int py = pi >> 2, px = pi & 3;
        int pix = (wy * 4 + py) * W_IMG + wx * 4 + px;
        *(uint4*)&sQ[pi * QSTR + v * 8] =
            *(const uint4*)&q[((size_t)bb * HW + pix) * INNER + v * 8];
    }
    for (int i = tid; i < KV_L * 64; i += 256) {
        int j = i >> 6, v = i & 63;
        int f = j >> 4, pi = j & 15;
        int py = pi >> 2, px = pi & 3;
        int pix = (wy * 4 + py) * W_IMG + wx * 4 + px;
        size_t base = ((size_t)(bb * 3 + f) * HW + pix) * (2 * INNER);
        *(uint4*)&sK[j * QSTR + v * 8] = *(const uint4*)&kv[base + v * 8];
        *(uint4*)&sV[j * QSTR + v * 8] = *(const uint4*)&kv[base + INNER + v * 8];
    }
    __syncthreads();

    float*  fbw = fB + wid * Q_L * FSTR;
    __half* spw = sP + wid * Q_L * PSTR;

    wmma::fragment<wmma::accumulator, 16, 16, 16, float> sim[3];
#pragma unroll
    for (int n = 0; n < 3; n++) wmma::fill_fragment(sim[n], 0.0f);
#pragma unroll
    for (int s = 0; s < 4; s++) {
        wmma::fragment<wmma::matrix_a, 16, 16, 16, __half, wmma::row_major> af;
        wmma::load_matrix_sync(af, &sQ[d0 + s * 16], QSTR);
#pragma unroll
        for (int n = 0; n < 3; n++) {
            wmma::fragment<wmma::matrix_b, 16, 16, 16, __half, wmma::col_major> bf;
            wmma::load_matrix_sync(bf, &sK[n * 16 * QSTR + d0 + s * 16], QSTR);
            wmma::mma_sync(sim[n], af, bf, sim[n]);
        }
    }
#pragma unroll
    for (int n = 0; n < 3; n++)
        wmma::store_matrix_sync(&fbw[n * 16], sim[n], FSTR, wmma::mem_row_major);
    __syncwarp();

    for (int e = lane; e < Q_L * KV_L; e += 32) {
        int i = e / KV_L, j = e % KV_L;
        fbw[i * FSTR + j] += stat[((size_t)wid * Q_L + i) * KV_L + j];
    }
    __syncwarp();

    if (lane < Q_L) {
        float* row = &fbw[lane * FSTR];
        float m = -1e30f;
#pragma unroll
        for (int j = 0; j < KV_L; j++) m = fmaxf(m, row[j]);
        float ssum = 0.f;
#pragma unroll
        for (int j = 0; j < KV_L; j++) {
            float e = expf(row[j] - m);
            row[j] = e; ssum += e;
        }
        float inv = 1.f / ssum;
#pragma unroll
        for (int j = 0; j < KV_L; j++) row[j] *= inv;
    }
    __syncwarp();

    for (int e = lane; e < Q_L * KV_L; e += 32) {
        int i = e / KV_L, j = e % KV_L;
        spw[i * PSTR + j] = __float2half_rn(fbw[i * FSTR + j]);
    }
    __syncwarp();

    wmma::fragment<wmma::accumulator, 16, 16, 16, float> oacc[4];
#pragma unroll
    for (int n = 0; n < 4; n++) wmma::fill_fragment(oacc[n], 0.0f);
#pragma unroll
    for (int s = 0; s < 3; s++) {
        wmma::fragment<wmma::matrix_a, 16, 16, 16, __half, wmma::row_major> af;
        wmma::load_matrix_sync(af, &spw[s * 16], PSTR);
#pragma unroll
        for (int n = 0; n < 4; n++) {
            wmma::fragment<wmma::matrix_b, 16, 16, 16, __half, wmma::row_major> bf;
            wmma::load_matrix_sync(bf, &sV[s * 16 * QSTR + d0 + n * 16], QSTR);
            wmma::mma_sync(oacc[n], af, bf, oacc[n]);
        }
    }
#pragma unroll
    for (int n = 0; n < 4; n++)
        wmma::store_matrix_sync(&fbw[n * 16], oacc[n], FSTR, wmma::mem_row_major);
    __syncwarp();

    {
        int r  = lane >> 1;
        int hp = lane & 1;
        int py = r >> 2, px = r & 3;
        int pix = (wy * 4 + py) * W_IMG + wx * 4 + px;
        __half* dst = &outp[((size_t)bb * HW + pix) * INNER + d0 + hp * 32];
        const float* srcr = &fbw[r * FSTR + hp * 32];
        __half2 h[16];
#pragma unroll
        for (int t = 0; t < 16; t++)
            h[t] = __floats2half2_rn(srcr[t * 2], srcr[t * 2 + 1]);
#pragma unroll
        for (int t = 0; t < 4; t++)
            *(uint4*)&dst[t * 8] = ((uint4*)h)[t];
    }
}

// ---------------------------------------------------------------------------
// Host launch
// ---------------------------------------------------------------------------
extern "C" void kernel_launch(void* const* d_in, const int* in_sizes, int n_in,
                              void* d_out, int out_size)
{
    (void)in_sizes; (void)n_in; (void)out_size;

    const float* q_inp   = (const float*)d_in[0];
    const float* k_inp   = (const float*)d_in[1];
    const float* flow_f  = (const float*)d_in[2];
    const float* flow_b  = (const float*)d_in[3];
    const float* gq      = (const float*)d_in[4];
    const float* bq      = (const float*)d_in[5];
    const float* gkv     = (const float*)d_in[6];
    const float* bkv     = (const float*)d_in[7];
    const float* Wq      = (const float*)d_in[8];
    const float* Wkv     = (const float*)d_in[9];
    const float* Wout    = (const float*)d_in[10];
    const float* statica = (const float*)d_in[11];

    __half *qn, *kvn, *qb, *kvb, *attb, *wtq, *wtkv, *wtout;
    cudaGetSymbolAddress((void**)&qn,    g_qn);
    cudaGetSymbolAddress((void**)&kvn,   g_kvn);
    cudaGetSymbolAddress((void**)&qb,    g_q);
    cudaGetSymbolAddress((void**)&kvb,   g_kv);
    cudaGetSymbolAddress((void**)&attb,  g_att);
    cudaGetSymbolAddress((void**)&wtq,   g_wt_q);
    cudaGetSymbolAddress((void**)&wtkv,  g_wt_kv);
    cudaGetSymbolAddress((void**)&wtout, g_wt_out);

    const int SMEM_QKV = (A6_ELEMS + 9 * 64 * AROWH) * 2 + 8 * 320 * 4;  // 205,504
    const int SMEM_OUT = ((2 + 2) * 130 * AROWH + 9 * 64 * AROWH) * 2;   // 157,824
    const int SMEMA = (Q_L + 2 * KV_L) * QSTR * 2
                    + 8 * Q_L * FSTR * 4
                    + 8 * Q_L * PSTR * 2;
    cudaFuncSetAttribute((const void*)conv_qkv_kernel,
                         cudaFuncAttributeMaxDynamicSharedMemorySize, SMEM_QKV);
    cudaFuncSetAttribute((const void*)conv_out_kernel,
                         cudaFuncAttributeMaxDynamicSharedMemorySize, SMEM_OUT);
    cudaFuncSetAttribute((const void*)attn_kernel,
                         cudaFuncAttributeMaxDynamicSharedMemorySize, SMEMA);

    // 0) all weight transforms in one launch
    wtrans_all_kernel<<<(4 * INNER * C_DIM + 255) / 256, 256>>>(
        Wq, Wkv, Wout, wtq, wtkv, wtout);

    // 1) merged layernorm (q + warped kv), 2 threads/px
    ln_all_kernel<<<dim3(2 * HW / 256, 4, B), 256>>>(
        q_inp, k_inp, flow_f, flow_b, gq, bq, gkv, bkv, qn, kvn);

    // 2) merged conv q + conv kv : 3584 CTAs, one launch
    conv_qkv_kernel<<<3584, 256, SMEM_QKV>>>(qn, wtq, qb, kvn, wtkv, kvb);

    // 3) attention: tensor-core, one block per window
    attn_kernel<<<dim3(1024, 1, B), 256, SMEMA>>>(qb, kvb, statica, attb);

    // 4) conv out: 512 -> 64, fp32 NCHW -> d_out : 128 CTAs
    conv_out_kernel<<<dim3(H_IMG / 2, 1, B), 256, SMEM_OUT>>>(
        attb, wtout, (float*)d_out);
}

// round 14
// speedup vs baseline: 1.2638x; 1.0758x over previous
#include <cuda_runtime.h>
#include <cuda_fp16.h>
#include <mma.h>
#include <math.h>
#include <stdint.h>

using namespace nvcuda;

// ---------------------------------------------------------------------------
// Problem constants
// ---------------------------------------------------------------------------
#define B       2
#define C_DIM   64
#define H_IMG   128
#define W_IMG   128
#define HW      (H_IMG * W_IMG)          // 16384
#define HEADS   8
#define DIM_HEAD 64
#define INNER   (HEADS * DIM_HEAD)       // 512
#define Q_L     16
#define KV_L    48
#define LN_EPS  1e-5f

// ---------------------------------------------------------------------------
// Scratch buffers (__device__ globals; allocation is forbidden)
// ---------------------------------------------------------------------------
__device__ __half g_qn  [B * HW * C_DIM];            // LN(q), NHWC fp16
__device__ __half g_kvn [B * 3 * HW * C_DIM];        // warped+LN kv, NHWC fp16
__device__ __half g_q   [B * HW * INNER];            // conv q out, NHWC fp16 (pre-scaled)
__device__ __half g_kv  [B * 3 * HW * 2 * INNER];    // conv kv out, NHWC fp16
__device__ __half g_att [B * HW * INNER];            // attention out, NHWC fp16
__device__ __half g_wt_q  [9 * INNER * C_DIM];       // Wq*0.125 as [tap][oc][ic] fp16
__device__ __half g_wt_kv [9 * 2 * INNER * C_DIM];   // Wkv as [tap][oc][ic] fp16
__device__ __half g_wt_out[9 * C_DIM * INNER];       // Wout as [tap][oc][ic] fp16

// ---------------------------------------------------------------------------
// cp.async helpers (16B, cg; zfill via src-size)
// ---------------------------------------------------------------------------
__device__ __forceinline__ void cp16z(uint32_t dst, const void* src, int sz) {
    asm volatile("cp.async.cg.shared.global [%0], [%1], 16, %2;"
                 :: "r"(dst), "l"(src), "r"(sz) : "memory");
}
__device__ __forceinline__ void cp16(uint32_t dst, const void* src) {
    asm volatile("cp.async.cg.shared.global [%0], [%1], 16;"
                 :: "r"(dst), "l"(src) : "memory");
}
#define CP_WAIT_ALL() asm volatile("cp.async.wait_all;" ::: "memory")

// ---------------------------------------------------------------------------
// Kernel 0: all three weight transforms in one launch.
// ---------------------------------------------------------------------------
__global__ void wtrans_all_kernel(const float* __restrict__ Wq,
                                  const float* __restrict__ Wkv,
                                  const float* __restrict__ Wout,
                                  __half* __restrict__ wtq,
                                  __half* __restrict__ wtkv,
                                  __half* __restrict__ wtout)
{
    int idx = blockIdx.x * blockDim.x + threadIdx.x;
    const float* W; __half* Wt; int OC, IC; float scale;
    if (idx < INNER * C_DIM) {
        W = Wq; Wt = wtq; OC = INNER; IC = C_DIM; scale = 0.125f;
    } else if (idx < INNER * C_DIM + 2 * INNER * C_DIM) {
        idx -= INNER * C_DIM;
        W = Wkv; Wt = wtkv; OC = 2 * INNER; IC = C_DIM; scale = 1.0f;
    } else if (idx < 2 * (INNER * C_DIM) + 2 * INNER * C_DIM) {
        idx -= 3 * INNER * C_DIM;
        W = Wout; Wt = wtout; OC = C_DIM; IC = INNER; scale = 1.0f;
    } else return;

    int oc = idx / IC, ic = idx % IC;
    const float* src = W + ((size_t)oc * IC + ic) * 9;
#pragma unroll
    for (int t = 0; t < 9; t++)
        Wt[((size_t)t * OC + oc) * IC + ic] = __float2half_rn(src[t] * scale);
}

// ---------------------------------------------------------------------------
// Kernel 1: merged LayerNorm (q and warped-kv) -> NHWC fp16.
// grid.y = 4: f in {0,1,2} -> kv frame f, f == 3 -> q. 2 threads/pixel.
// ---------------------------------------------------------------------------
__global__ void ln_all_kernel(const float* __restrict__ q_inp,
                              const float* __restrict__ k_inp,
                              const float* __restrict__ flow_f,
                              const float* __restrict__ flow_b,
                              const float* __restrict__ gq,
                              const float* __restrict__ bq,
                              const float* __restrict__ gkv,
                              const float* __restrict__ bkv,
                              __half* __restrict__ qn,
                              __half* __restrict__ kvn)
{
    int t   = blockIdx.x * blockDim.x + threadIdx.x;
    int pix = t >> 1;
    int hf  = t & 1;
    if (pix >= HW) return;
    int f  = blockIdx.y;             // 0..2 kv, 3 q
    int bb = blockIdx.z;

    const float* base;
    const float* g;
    const float* beta;
    __half* ob;
    bool valid = true;

    if (f == 3) {
        base = q_inp + ((size_t)bb * C_DIM + hf * 32) * HW + pix;
        g = gq; beta = bq;
        ob = qn + ((size_t)bb * HW + pix) * C_DIM + hf * 32;
    } else {
        int y = pix >> 7, x = pix & 127;
        int src = pix;
        if (f != 1) {
            const float* fl = (f == 0) ? flow_f : flow_b;
            float fx = fl[((size_t)bb * 2 + 0) * HW + pix];
            float fy = fl[((size_t)bb * 2 + 1) * HW + pix];
            int ix = (int)rintf((float)x + fx);
            int iy = (int)rintf((float)y + fy);
            valid = (ix >= 0) && (ix < W_IMG) && (iy >= 0) && (iy < H_IMG);
            int cx = min(max(ix, 0), W_IMG - 1);
            int cy = min(max(iy, 0), H_IMG - 1);
            src = cy * W_IMG + cx;
        }
        base = k_inp + (((size_t)bb * 3 + f) * C_DIM + hf * 32) * HW + src;
        g = gkv; beta = bkv;
        ob = kvn + (((size_t)(bb * 3 + f)) * HW + pix) * C_DIM + hf * 32;
    }

    float v[32];
    float s = 0.f;
#pragma unroll
    for (int i = 0; i < 32; i++) {
        float vv = valid ? base[(size_t)i * HW] : 0.f;
        v[i] = vv; s += vv;
    }
    s += __shfl_xor_sync(0xffffffffu, s, 1);
    float mu = s * (1.f / C_DIM);
    float var = 0.f;
#pragma unroll
    for (int i = 0; i < 32; i++) { float d = v[i] - mu; var += d * d; }
    var += __shfl_xor_sync(0xffffffffu, var, 1);
    var *= (1.f / C_DIM);
    float inv = rsqrtf(var + LN_EPS);

    __half2 h[16];
#pragma unroll
    for (int i = 0; i < 32; i += 2) {
        int c = hf * 32 + i;
        h[i >> 1] = __floats2half2_rn((v[i]   - mu) * inv * g[c]   + beta[c],
                                      (v[i+1] - mu) * inv * g[c+1] + beta[c+1]);
    }
#pragma unroll
    for (int q4 = 0; q4 < 4; q4++)
        *(uint4*)&ob[q4 * 8] = ((uint4*)h)[q4];
}

// ---------------------------------------------------------------------------
// Kernel 3a: MERGED conv q + conv kv (single launch, linearized grid).
// ROWS=4, MF=4, NF=4. IC=64 (single chunk). cp.async stage.  [R13, unchanged]
// ---------------------------------------------------------------------------
#define AROWH 72
#define A6_ELEMS (6 * 130 * AROWH)

__global__ __launch_bounds__(256, 1)
void conv_qkv_kernel(const __half* __restrict__ qn,
                     const __half* __restrict__ wtq,
                     __half* __restrict__ qb,
                     const __half* __restrict__ kvn,
                     const __half* __restrict__ wtkv,
                     __half* __restrict__ kvb)
{
    constexpr int MF = 4, NF = 4;

    extern __shared__ __half smh[];
    __half* sA   = smh;
    __half* sB   = smh + A6_ELEMS;
    float*  sEpi = (float*)(smh + A6_ELEMS + 9 * 64 * AROWH);

    uint32_t sA_u = (uint32_t)__cvta_generic_to_shared(sA);
    uint32_t sB_u = (uint32_t)__cvta_generic_to_shared(sB);

    int tid  = threadIdx.x;
    int wid  = tid >> 5;
    int lane = tid & 31;

    const __half* in; const __half* Wt; __half* outp; int OC;
    int octile, ystrip;
    {
        int t = blockIdx.x;
        if (t < 3072) {
            int img = t >> 9; int rem = t & 511;
            octile = rem >> 5; ystrip = rem & 31;
            in   = kvn + (size_t)img * HW * C_DIM;
            Wt   = wtkv;
            outp = kvb + (size_t)img * HW * (2 * INNER);
            OC   = 2 * INNER;
        } else {
            t -= 3072;
            int img = t >> 8; int rem = t & 255;
            octile = rem >> 5; ystrip = rem & 31;
            in   = qn + (size_t)img * HW * C_DIM;
            Wt   = wtq;
            outp = qb + (size_t)img * HW * INNER;
            OC   = INNER;
        }
    }
    int y0  = ystrip * 4;
    int oc0 = octile * 64;

    int warp_row = wid & 3;
    int warp_pxg = wid >> 2;

    wmma::fragment<wmma::accumulator, 16, 16, 16, float> acc[MF][NF];
#pragma unroll
    for (int mf = 0; mf < MF; mf++)
#pragma unroll
        for (int nf = 0; nf < NF; nf++) wmma::fill_fragment(acc[mf][nf], 0.0f);

    for (int i = tid; i < 6 * 130 * 8; i += 256) {
        int r   = i / (130 * 8);
        int rem = i % (130 * 8);
        int p   = rem >> 3;
        int v   = rem & 7;
        int gy = y0 + r - 1, gx = p - 1;
        bool ok = (gy >= 0) && (gy < H_IMG) && (gx >= 0) && (gx < W_IMG);
        int cy = ok ? gy : 0, cx = ok ? gx : 0;
        const __half* src = &in[((size_t)cy * W_IMG + cx) * C_DIM + v * 8];
        cp16z(sA_u + ((r * 130 + p) * AROWH + v * 8) * 2, src, ok ? 16 : 0);
    }
    for (int i = tid; i < 9 * 64 * 8; i += 256) {
        int tap = i / (64 * 8);
        int rem = i % (64 * 8);
        int o   = rem >> 3;
        int v   = rem & 7;
        cp16(sB_u + ((tap * 64 + o) * AROWH + v * 8) * 2,
             &Wt[(((size_t)tap * OC) + oc0 + o) * C_DIM + v * 8]);
    }
    CP_WAIT_ALL();
    __syncthreads();

#pragma unroll
    for (int dy = 0; dy < 3; dy++) {
#pragma unroll
        for (int dx = 0; dx < 3; dx++) {
            const int tap = dy * 3 + dx;
#pragma unroll
            for (int s = 0; s < 4; s++) {
                wmma::fragment<wmma::matrix_b, 16, 16, 16, __half,
                               wmma::col_major> bf[NF];
#pragma unroll
                for (int nf = 0; nf < NF; nf++)
                    wmma::load_matrix_sync(
                        bf[nf], &sB[(tap * 64 + nf * 16) * AROWH + s * 16], AROWH);
#pragma unroll
                for (int mf = 0; mf < MF; mf++) {
                    int px = warp_pxg * 64 + mf * 16;
                    wmma::fragment<wmma::matrix_a, 16, 16, 16, __half,
                                   wmma::row_major> af;
                    wmma::load_matrix_sync(
                        af, &sA[((warp_row + dy) * 130 + px + dx) * AROWH + s * 16],
                        AROWH);
#pragma unroll
                    for (int nf = 0; nf < NF; nf++)
                        wmma::mma_sync(acc[mf][nf], af, bf[nf], acc[mf][nf]);
                }
            }
        }
    }

    int y = y0 + warp_row;
    float* buf = sEpi + wid * 320;
    int r  = lane >> 1;
    int hp = lane & 1;
#pragma unroll
    for (int mf = 0; mf < MF; mf++) {
        int px = warp_pxg * 64 + mf * 16;
#pragma unroll
        for (int nf = 0; nf < NF; nf++) {
            int oc = oc0 + nf * 16;
            wmma::store_matrix_sync(buf, acc[mf][nf], 20, wmma::mem_row_major);
            __syncwarp();
            float4 a = *(float4*)&buf[r * 20 + hp * 8];
            float4 b = *(float4*)&buf[r * 20 + hp * 8 + 4];
            __half2 h[4];
            h[0] = __floats2half2_rn(a.x, a.y);
            h[1] = __floats2half2_rn(a.z, a.w);
            h[2] = __floats2half2_rn(b.x, b.y);
            h[3] = __floats2half2_rn(b.z, b.w);
            *(uint4*)&outp[((size_t)(y * W_IMG) + px + r) * OC + oc + hp * 8] =
                *(uint4*)h;
            __syncwarp();
        }
    }
}

// ---------------------------------------------------------------------------
// Kernel 3b: conv_out (512->64) — ROWS=2, MF=4, NF=2; 8 IC chunks. [R13]
// ---------------------------------------------------------------------------
__global__ __launch_bounds__(256, 1)
void conv_out_kernel(const __half* __restrict__ in,
                     const __half* __restrict__ Wt,
                     float* __restrict__ outp)
{
    constexpr int MF = 4, NF = 2, OCW = 32;
    constexpr int IC = INNER, OC = C_DIM;
    constexpr int A_ELEMS = 4 * 130 * AROWH;

    extern __shared__ __half smh[];
    __half* sA = smh;
    __half* sB = smh + A_ELEMS;
    uint32_t sA_u = (uint32_t)__cvta_generic_to_shared(sA);
    uint32_t sB_u = (uint32_t)__cvta_generic_to_shared(sB);

    int tid  = threadIdx.x;
    int wid  = tid >> 5;

    int y0  = blockIdx.x * 2;
    int img = blockIdx.z;

    int warp_row = wid & 1;
    int warp_pxg = (wid >> 1) & 1;
    int warp_ocg = wid >> 2;

    wmma::fragment<wmma::accumulator, 16, 16, 16, float> acc[MF][NF];
#pragma unroll
    for (int mf = 0; mf < MF; mf++)
#pragma unroll
        for (int nf = 0; nf < NF; nf++) wmma::fill_fragment(acc[mf][nf], 0.0f);

    for (int c = 0; c < IC / 64; c++) {
        int ic0 = c * 64;

        __syncthreads();
        for (int i = tid; i < 4 * 130 * 8; i += 256) {
            int r   = i / (130 * 8);
            int rem = i % (130 * 8);
            int p   = rem >> 3;
            int v   = rem & 7;
            int gy = y0 + r - 1, gx = p - 1;
            bool ok = (gy >= 0) && (gy < H_IMG) && (gx >= 0) && (gx < W_IMG);
            int cy = ok ? gy : 0, cx = ok ? gx : 0;
            const __half* src =
                &in[(((size_t)img * H_IMG + cy) * W_IMG + cx) * IC + ic0 + v * 8];
            cp16z(sA_u + ((r * 130 + p) * AROWH + v * 8) * 2, src, ok ? 16 : 0);
        }
        for (int i = tid; i < 9 * 64 * 8; i += 256) {
            int tap = i / (64 * 8);
            int rem = i % (64 * 8);
            int o   = rem >> 3;
            int v   = rem & 7;
            cp16(sB_u + ((tap * 64 + o) * AROWH + v * 8) * 2,
                 &Wt[(((size_t)tap * OC) + o) * IC + ic0 + v * 8]);
        }
        CP_WAIT_ALL();
        __syncthreads();

#pragma unroll
        for (int dy = 0; dy < 3; dy++) {
#pragma unroll
            for (int dx = 0; dx < 3; dx++) {
                const int tap = dy * 3 + dx;
#pragma unroll
                for (int s = 0; s < 4; s++) {
                    wmma::fragment<wmma::matrix_b, 16, 16, 16, __half,
                                   wmma::col_major> bf[NF];
#pragma unroll
                    for (int nf = 0; nf < NF; nf++)
                        wmma::load_matrix_sync(
                            bf[nf],
                            &sB[(tap * 64 + warp_ocg * OCW + nf * 16) * AROWH + s * 16],
                            AROWH);
#pragma unroll
                    for (int mf = 0; mf < MF; mf++) {
                        int px = warp_pxg * 64 + mf * 16;
                        wmma::fragment<wmma::matrix_a, 16, 16, 16, __half,
                                       wmma::row_major> af;
                        wmma::load_matrix_sync(
                            af, &sA[((warp_row + dy) * 130 + px + dx) * AROWH + s * 16],
                            AROWH);
#pragma unroll
                        for (int nf = 0; nf < NF; nf++)
                            wmma::mma_sync(acc[mf][nf], af, bf[nf], acc[mf][nf]);
                    }
                }
            }
        }
    }

    int y = y0 + warp_row;
#pragma unroll
    for (int mf = 0; mf < MF; mf++) {
        int px = warp_pxg * 64 + mf * 16;
#pragma unroll
        for (int nf = 0; nf < NF; nf++) {
            int oc = warp_ocg * OCW + nf * 16;
            float* dst = &outp[(((size_t)img * OC + oc) * H_IMG + y) * W_IMG + px];
            wmma::store_matrix_sync(dst, acc[mf][nf], HW, wmma::mem_col_major);
        }
    }
}

// ---------------------------------------------------------------------------
// Kernel 4: windowed attention on tensor cores — HEAD-PAIR blocks.
// 64 threads = 2 warps = 2 heads; grid (1024, 4, B).
// Stages only the 128-ch slice (both heads) of q/k/v -> ~43 KB smem -> 5 CTA/SM.
// ---------------------------------------------------------------------------
#define CSTR 136                              // half stride per pixel row (128+8)
#define FSTR 68                               // float stride, per-warp staging
#define PSTR 56                               // half stride, probs

__global__ __launch_bounds__(64)
void attn_kernel(const __half* __restrict__ q,
                 const __half* __restrict__ kv,
                 const float* __restrict__ stat,
                 __half* __restrict__ outp)
{
    extern __shared__ __half smh[];
    __half* sQ = smh;                         // [16][CSTR]
    __half* sK = sQ + Q_L * CSTR;             // [48][CSTR]
    __half* sV = sK + KV_L * CSTR;            // [48][CSTR]
    float*  fB = (float*)(sV + KV_L * CSTR);  // 2 x [16][FSTR]
    __half* sP = (__half*)(fB + 2 * Q_L * FSTR); // 2 x [16][PSTR]

    int tid  = threadIdx.x;                   // 0..63
    int w    = tid >> 5;                      // warp = head within pair
    int lane = tid & 31;
    int win = blockIdx.x;
    int hg  = blockIdx.y;                     // head pair 0..3
    int bb  = blockIdx.z;
    int wy = win >> 5, wx = win & 31;
    int cbase = hg * 128;                     // channel base of this pair

    // ---- stage q: 16 px x 16 uint4 (128-ch slice) ----
    for (int i = tid; i < Q_L * 16; i += 64) {
        int pi = i >> 4, v = i & 15;
        int py = pi >> 2, px = pi & 3;
        int pix = (wy * 4 + py) * W_IMG + wx * 4 + px;
        *(uint4*)&sQ[pi * CSTR + v * 8] =
            *(const uint4*)&q[((size_t)bb * HW + pix) * INNER + cbase + v * 8];
    }
    // ---- stage k, v: 48 px x 16 uint4 each ----
    for (int i = tid; i < KV_L * 16; i += 64) {
        int j = i >> 4, v = i & 15;
        int f = j >> 4, pi = j & 15;
        int py = pi >> 2, px = pi & 3;
        int pix = (wy * 4 + py) * W_IMG + wx * 4 + px;
        size_t base = ((size_t)(bb * 3 + f) * HW + pix) * (2 * INNER) + cbase;
        *(uint4*)&sK[j * CSTR + v * 8] = *(const uint4*)&kv[base + v * 8];
        *(uint4*)&sV[j * CSTR + v * 8] = *(const uint4*)&kv[base + INNER + v * 8];
    }
    __syncthreads();

    int dloc = w * DIM_HEAD;                  // head offset within slice
    float*  fbw = fB + w * Q_L * FSTR;
    __half* spw = sP + w * Q_L * PSTR;

    // ---- sim = q k^T ----
    wmma::fragment<wmma::accumulator, 16, 16, 16, float> sim[3];
#pragma unroll
    for (int n = 0; n < 3; n++) wmma::fill_fragment(sim[n], 0.0f);
#pragma unroll
    for (int s = 0; s < 4; s++) {
        wmma::fragment<wmma::matrix_a, 16, 16, 16, __half, wmma::row_major> af;
        wmma::load_matrix_sync(af, &sQ[dloc + s * 16], CSTR);
#pragma unroll
        for (int n = 0; n < 3; n++) {
            wmma::fragment<wmma::matrix_b, 16, 16, 16, __half, wmma::col_major> bf;
            wmma::load_matrix_sync(bf, &sK[n * 16 * CSTR + dloc + s * 16], CSTR);
            wmma::mma_sync(sim[n], af, bf, sim[n]);
        }
    }
#pragma unroll
    for (int n = 0; n < 3; n++)
        wmma::store_matrix_sync(&fbw[n * 16], sim[n], FSTR, wmma::mem_row_major);
    __syncwarp();

    // ---- + static_a ----
    int head = hg * 2 + w;
    for (int e = lane; e < Q_L * KV_L; e += 32) {
        int i = e / KV_L, j = e % KV_L;
        fbw[i * FSTR + j] += stat[((size_t)head * Q_L + i) * KV_L + j];
    }
    __syncwarp();

    // ---- softmax per row (lanes 0..15) ----
    if (lane < Q_L) {
        float* row = &fbw[lane * FSTR];
        float m = -1e30f;
#pragma unroll
        for (int j = 0; j < KV_L; j++) m = fmaxf(m, row[j]);
        float ssum = 0.f;
#pragma unroll
        for (int j = 0; j < KV_L; j++) {
            float e = expf(row[j] - m);
            row[j] = e; ssum += e;
        }
        float inv = 1.f / ssum;
#pragma unroll
        for (int j = 0; j < KV_L; j++) row[j] *= inv;
    }
    __syncwarp();

    // ---- probs -> fp16 ----
    for (int e = lane; e < Q_L * KV_L; e += 32) {
        int i = e / KV_L, j = e % KV_L;
        spw[i * PSTR + j] = __float2half_rn(fbw[i * FSTR + j]);
    }
    __syncwarp();

    // ---- out = p v ----
    wmma::fragment<wmma::accumulator, 16, 16, 16, float> oacc[4];
#pragma unroll
    for (int n = 0; n < 4; n++) wmma::fill_fragment(oacc[n], 0.0f);
#pragma unroll
    for (int s = 0; s < 3; s++) {
        wmma::fragment<wmma::matrix_a, 16, 16, 16, __half, wmma::row_major> af;
        wmma::load_matrix_sync(af, &spw[s * 16], PSTR);
#pragma unroll
        for (int n = 0; n < 4; n++) {
            wmma::fragment<wmma::matrix_b, 16, 16, 16, __half, wmma::row_major> bf;
            wmma::load_matrix_sync(bf, &sV[s * 16 * CSTR + dloc + n * 16], CSTR);
            wmma::mma_sync(oacc[n], af, bf, oacc[n]);
        }
    }
#pragma unroll
    for (int n = 0; n < 4; n++)
        wmma::store_matrix_sync(&fbw[n * 16], oacc[n], FSTR, wmma::mem_row_major);
    __syncwarp();

    // ---- convert + store (two lanes per row, 32 ch each) ----
    {
        int r  = lane >> 1;
        int hp = lane & 1;
        int py = r >> 2, px = r & 3;
        int pix = (wy * 4 + py) * W_IMG + wx * 4 + px;
        __half* dst = &outp[((size_t)bb * HW + pix) * INNER + cbase + dloc + hp * 32];
        const float* srcr = &fbw[r * FSTR + hp * 32];
        __half2 h[16];
#pragma unroll
        for (int t = 0; t < 16; t++)
            h[t] = __floats2half2_rn(srcr[t * 2], srcr[t * 2 + 1]);
#pragma unroll
        for (int t = 0; t < 4; t++)
            *(uint4*)&dst[t * 8] = ((uint4*)h)[t];
    }
}

// ---------------------------------------------------------------------------
// Host launch
// ---------------------------------------------------------------------------
extern "C" void kernel_launch(void* const* d_in, const int* in_sizes, int n_in,
                              void* d_out, int out_size)
{
    (void)in_sizes; (void)n_in; (void)out_size;

    const float* q_inp   = (const float*)d_in[0];
    const float* k_inp   = (const float*)d_in[1];
    const float* flow_f  = (const float*)d_in[2];
    const float* flow_b  = (const float*)d_in[3];
    const float* gq      = (const float*)d_in[4];
    const float* bq      = (const float*)d_in[5];
    const float* gkv     = (const float*)d_in[6];
    const float* bkv     = (const float*)d_in[7];
    const float* Wq      = (const float*)d_in[8];
    const float* Wkv     = (const float*)d_in[9];
    const float* Wout    = (const float*)d_in[10];
    const float* statica = (const float*)d_in[11];

    __half *qn, *kvn, *qb, *kvb, *attb, *wtq, *wtkv, *wtout;
    cudaGetSymbolAddress((void**)&qn,    g_qn);
    cudaGetSymbolAddress((void**)&kvn,   g_kvn);
    cudaGetSymbolAddress((void**)&qb,    g_q);
    cudaGetSymbolAddress((void**)&kvb,   g_kv);
    cudaGetSymbolAddress((void**)&attb,  g_att);
    cudaGetSymbolAddress((void**)&wtq,   g_wt_q);
    cudaGetSymbolAddress((void**)&wtkv,  g_wt_kv);
    cudaGetSymbolAddress((void**)&wtout, g_wt_out);

    const int SMEM_QKV = (A6_ELEMS + 9 * 64 * AROWH) * 2 + 8 * 320 * 4;  // 205,504
    const int SMEM_OUT = (4 * 130 * AROWH + 9 * 64 * AROWH) * 2;         // 157,824
    const int SMEMA = (Q_L + 2 * KV_L) * CSTR * 2                        // q,k,v slice
                    + 2 * Q_L * FSTR * 4                                 // fp32 staging
                    + 2 * Q_L * PSTR * 2;                                // fp16 probs
    cudaFuncSetAttribute((const void*)conv_qkv_kernel,
                         cudaFuncAttributeMaxDynamicSharedMemorySize, SMEM_QKV);
    cudaFuncSetAttribute((const void*)conv_out_kernel,
                         cudaFuncAttributeMaxDynamicSharedMemorySize, SMEM_OUT);
    cudaFuncSetAttribute((const void*)attn_kernel,
                         cudaFuncAttributeMaxDynamicSharedMemorySize, SMEMA);

    // 0) all weight transforms in one launch
    wtrans_all_kernel<<<(4 * INNER * C_DIM + 255) / 256, 256>>>(
        Wq, Wkv, Wout, wtq, wtkv, wtout);

    // 1) merged layernorm (q + warped kv), 2 threads/px
    ln_all_kernel<<<dim3(2 * HW / 256, 4, B), 256>>>(
        q_inp, k_inp, flow_f, flow_b, gq, bq, gkv, bkv, qn, kvn);

    // 2) merged conv q + conv kv : 3584 CTAs, one launch
    conv_qkv_kernel<<<3584, 256, SMEM_QKV>>>(qn, wtq, qb, kvn, wtkv, kvb);

    // 3) attention: head-pair blocks, 5 CTAs/SM
    attn_kernel<<<dim3(1024, HEADS / 2, B), 64, SMEMA>>>(qb, kvb, statica, attb);

    // 4) conv out: 512 -> 64, fp32 NCHW -> d_out : 128 CTAs
    conv_out_kernel<<<dim3(H_IMG / 2, 1, B), 256, SMEM_OUT>>>(
        attb, wtout, (float*)d_out);
}

// round 15
// speedup vs baseline: 1.3807x; 1.0924x over previous
#include <cuda_runtime.h>
#include <cuda_fp16.h>
#include <mma.h>
#include <math.h>
#include <stdint.h>

using namespace nvcuda;

// ---------------------------------------------------------------------------
// Problem constants
// ---------------------------------------------------------------------------
#define B       2
#define C_DIM   64
#define H_IMG   128
#define W_IMG   128
#define HW      (H_IMG * W_IMG)          // 16384
#define HEADS   8
#define DIM_HEAD 64
#define INNER   (HEADS * DIM_HEAD)       // 512
#define Q_L     16
#define KV_L    48
#define LN_EPS  1e-5f

// ---------------------------------------------------------------------------
// Scratch buffers (__device__ globals; allocation is forbidden)
// ---------------------------------------------------------------------------
__device__ __half g_qn  [B * HW * C_DIM];            // LN(q), NHWC fp16
__device__ __half g_kvn [B * 3 * HW * C_DIM];        // warped+LN kv, NHWC fp16
__device__ __half g_q   [B * HW * INNER];            // conv q out, NHWC fp16 (pre-scaled)
__device__ __half g_kv  [B * 3 * HW * 2 * INNER];    // conv kv out, NHWC fp16
__device__ __half g_att [B * HW * INNER];            // attention out, NHWC fp16
__device__ __half g_wt_q  [9 * INNER * C_DIM];       // Wq*0.125 as [tap][oc][ic] fp16
__device__ __half g_wt_kv [9 * 2 * INNER * C_DIM];   // Wkv as [tap][oc][ic] fp16
__device__ __half g_wt_out[9 * C_DIM * INNER];       // Wout as [tap][oc][ic] fp16

// ---------------------------------------------------------------------------
// cp.async helpers (16B, cg; zfill via src-size)
// ---------------------------------------------------------------------------
__device__ __forceinline__ void cp16z(uint32_t dst, const void* src, int sz) {
    asm volatile("cp.async.cg.shared.global [%0], [%1], 16, %2;"
                 :: "r"(dst), "l"(src), "r"(sz) : "memory");
}
__device__ __forceinline__ void cp16(uint32_t dst, const void* src) {
    asm volatile("cp.async.cg.shared.global [%0], [%1], 16;"
                 :: "r"(dst), "l"(src) : "memory");
}
#define CP_WAIT_ALL() asm volatile("cp.async.wait_all;" ::: "memory")

// ---------------------------------------------------------------------------
// Kernel 0: all three weight transforms in one launch.
// ---------------------------------------------------------------------------
__global__ void wtrans_all_kernel(const float* __restrict__ Wq,
                                  const float* __restrict__ Wkv,
                                  const float* __restrict__ Wout,
                                  __half* __restrict__ wtq,
                                  __half* __restrict__ wtkv,
                                  __half* __restrict__ wtout)
{
    int idx = blockIdx.x * blockDim.x + threadIdx.x;
    const float* W; __half* Wt; int OC, IC; float scale;
    if (idx < INNER * C_DIM) {
        W = Wq; Wt = wtq; OC = INNER; IC = C_DIM; scale = 0.125f;
    } else if (idx < INNER * C_DIM + 2 * INNER * C_DIM) {
        idx -= INNER * C_DIM;
        W = Wkv; Wt = wtkv; OC = 2 * INNER; IC = C_DIM; scale = 1.0f;
    } else if (idx < 2 * (INNER * C_DIM) + 2 * INNER * C_DIM) {
        idx -= 3 * INNER * C_DIM;
        W = Wout; Wt = wtout; OC = C_DIM; IC = INNER; scale = 1.0f;
    } else return;

    int oc = idx / IC, ic = idx % IC;
    const float* src = W + ((size_t)oc * IC + ic) * 9;
#pragma unroll
    for (int t = 0; t < 9; t++)
        Wt[((size_t)t * OC + oc) * IC + ic] = __float2half_rn(src[t] * scale);
}

// ---------------------------------------------------------------------------
// Kernel 1: merged LayerNorm (q and warped-kv) -> NHWC fp16.
// ---------------------------------------------------------------------------
__global__ void ln_all_kernel(const float* __restrict__ q_inp,
                              const float* __restrict__ k_inp,
                              const float* __restrict__ flow_f,
                              const float* __restrict__ flow_b,
                              const float* __restrict__ gq,
                              const float* __restrict__ bq,
                              const float* __restrict__ gkv,
                              const float* __restrict__ bkv,
                              __half* __restrict__ qn,
                              __half* __restrict__ kvn)
{
    int t   = blockIdx.x * blockDim.x + threadIdx.x;
    int pix = t >> 1;
    int hf  = t & 1;
    if (pix >= HW) return;
    int f  = blockIdx.y;             // 0..2 kv, 3 q
    int bb = blockIdx.z;

    const float* base;
    const float* g;
    const float* beta;
    __half* ob;
    bool valid = true;

    if (f == 3) {
        base = q_inp + ((size_t)bb * C_DIM + hf * 32) * HW + pix;
        g = gq; beta = bq;
        ob = qn + ((size_t)bb * HW + pix) * C_DIM + hf * 32;
    } else {
        int y = pix >> 7, x = pix & 127;
        int src = pix;
        if (f != 1) {
            const float* fl = (f == 0) ? flow_f : flow_b;
            float fx = fl[((size_t)bb * 2 + 0) * HW + pix];
            float fy = fl[((size_t)bb * 2 + 1) * HW + pix];
            int ix = (int)rintf((float)x + fx);
            int iy = (int)rintf((float)y + fy);
            valid = (ix >= 0) && (ix < W_IMG) && (iy >= 0) && (iy < H_IMG);
            int cx = min(max(ix, 0), W_IMG - 1);
            int cy = min(max(iy, 0), H_IMG - 1);
            src = cy * W_IMG + cx;
        }
        base = k_inp + (((size_t)bb * 3 + f) * C_DIM + hf * 32) * HW + src;
        g = gkv; beta = bkv;
        ob = kvn + (((size_t)(bb * 3 + f)) * HW + pix) * C_DIM + hf * 32;
    }

    float v[32];
    float s = 0.f;
#pragma unroll
    for (int i = 0; i < 32; i++) {
        float vv = valid ? base[(size_t)i * HW] : 0.f;
        v[i] = vv; s += vv;
    }
    s += __shfl_xor_sync(0xffffffffu, s, 1);
    float mu = s * (1.f / C_DIM);
    float var = 0.f;
#pragma unroll
    for (int i = 0; i < 32; i++) { float d = v[i] - mu; var += d * d; }
    var += __shfl_xor_sync(0xffffffffu, var, 1);
    var *= (1.f / C_DIM);
    float inv = rsqrtf(var + LN_EPS);

    __half2 h[16];
#pragma unroll
    for (int i = 0; i < 32; i += 2) {
        int c = hf * 32 + i;
        h[i >> 1] = __floats2half2_rn((v[i]   - mu) * inv * g[c]   + beta[c],
                                      (v[i+1] - mu) * inv * g[c+1] + beta[c+1]);
    }
#pragma unroll
    for (int q4 = 0; q4 < 4; q4++)
        *(uint4*)&ob[q4 * 8] = ((uint4*)h)[q4];
}

// ---------------------------------------------------------------------------
// Kernel 3a: MERGED conv q + conv kv. [R13/R14, unchanged]
// ---------------------------------------------------------------------------
#define AROWH 72
#define A6_ELEMS (6 * 130 * AROWH)

__global__ __launch_bounds__(256, 1)
void conv_qkv_kernel(const __half* __restrict__ qn,
                     const __half* __restrict__ wtq,
                     __half* __restrict__ qb,
                     const __half* __restrict__ kvn,
                     const __half* __restrict__ wtkv,
                     __half* __restrict__ kvb)
{
    constexpr int MF = 4, NF = 4;

    extern __shared__ __half smh[];
    __half* sA   = smh;
    __half* sB   = smh + A6_ELEMS;
    float*  sEpi = (float*)(smh + A6_ELEMS + 9 * 64 * AROWH);

    uint32_t sA_u = (uint32_t)__cvta_generic_to_shared(sA);
    uint32_t sB_u = (uint32_t)__cvta_generic_to_shared(sB);

    int tid  = threadIdx.x;
    int wid  = tid >> 5;
    int lane = tid & 31;

    const __half* in; const __half* Wt; __half* outp; int OC;
    int octile, ystrip;
    {
        int t = blockIdx.x;
        if (t < 3072) {
            int img = t >> 9; int rem = t & 511;
            octile = rem >> 5; ystrip = rem & 31;
            in   = kvn + (size_t)img * HW * C_DIM;
            Wt   = wtkv;
            outp = kvb + (size_t)img * HW * (2 * INNER);
            OC   = 2 * INNER;
        } else {
            t -= 3072;
            int img = t >> 8; int rem = t & 255;
            octile = rem >> 5; ystrip = rem & 31;
            in   = qn + (size_t)img * HW * C_DIM;
            Wt   = wtq;
            outp = qb + (size_t)img * HW * INNER;
            OC   = INNER;
        }
    }
    int y0  = ystrip * 4;
    int oc0 = octile * 64;

    int warp_row = wid & 3;
    int warp_pxg = wid >> 2;

    wmma::fragment<wmma::accumulator, 16, 16, 16, float> acc[MF][NF];
#pragma unroll
    for (int mf = 0; mf < MF; mf++)
#pragma unroll
        for (int nf = 0; nf < NF; nf++) wmma::fill_fragment(acc[mf][nf], 0.0f);

    for (int i = tid; i < 6 * 130 * 8; i += 256) {
        int r   = i / (130 * 8);
        int rem = i % (130 * 8);
        int p   = rem >> 3;
        int v   = rem & 7;
        int gy = y0 + r - 1, gx = p - 1;
        bool ok = (gy >= 0) && (gy < H_IMG) && (gx >= 0) && (gx < W_IMG);
        int cy = ok ? gy : 0, cx = ok ? gx : 0;
        const __half* src = &in[((size_t)cy * W_IMG + cx) * C_DIM + v * 8];
        cp16z(sA_u + ((r * 130 + p) * AROWH + v * 8) * 2, src, ok ? 16 : 0);
    }
    for (int i = tid; i < 9 * 64 * 8; i += 256) {
        int tap = i / (64 * 8);
        int rem = i % (64 * 8);
        int o   = rem >> 3;
        int v   = rem & 7;
        cp16(sB_u + ((tap * 64 + o) * AROWH + v * 8) * 2,
             &Wt[(((size_t)tap * OC) + oc0 + o) * C_DIM + v * 8]);
    }
    CP_WAIT_ALL();
    __syncthreads();

#pragma unroll
    for (int dy = 0; dy < 3; dy++) {
#pragma unroll
        for (int dx = 0; dx < 3; dx++) {
            const int tap = dy * 3 + dx;
#pragma unroll
            for (int s = 0; s < 4; s++) {
                wmma::fragment<wmma::matrix_b, 16, 16, 16, __half,
                               wmma::col_major> bf[NF];
#pragma unroll
                for (int nf = 0; nf < NF; nf++)
                    wmma::load_matrix_sync(
                        bf[nf], &sB[(tap * 64 + nf * 16) * AROWH + s * 16], AROWH);
#pragma unroll
                for (int mf = 0; mf < MF; mf++) {
                    int px = warp_pxg * 64 + mf * 16;
                    wmma::fragment<wmma::matrix_a, 16, 16, 16, __half,
                                   wmma::row_major> af;
                    wmma::load_matrix_sync(
                        af, &sA[((warp_row + dy) * 130 + px + dx) * AROWH + s * 16],
                        AROWH);
#pragma unroll
                    for (int nf = 0; nf < NF; nf++)
                        wmma::mma_sync(acc[mf][nf], af, bf[nf], acc[mf][nf]);
                }
            }
        }
    }

    int y = y0 + warp_row;
    float* buf = sEpi + wid * 320;
    int r  = lane >> 1;
    int hp = lane & 1;
#pragma unroll
    for (int mf = 0; mf < MF; mf++) {
        int px = warp_pxg * 64 + mf * 16;
#pragma unroll
        for (int nf = 0; nf < NF; nf++) {
            int oc = oc0 + nf * 16;
            wmma::store_matrix_sync(buf, acc[mf][nf], 20, wmma::mem_row_major);
            __syncwarp();
            float4 a = *(float4*)&buf[r * 20 + hp * 8];
            float4 b = *(float4*)&buf[r * 20 + hp * 8 + 4];
            __half2 h[4];
            h[0] = __floats2half2_rn(a.x, a.y);
            h[1] = __floats2half2_rn(a.z, a.w);
            h[2] = __floats2half2_rn(b.x, b.y);
            h[3] = __floats2half2_rn(b.z, b.w);
            *(uint4*)&outp[((size_t)(y * W_IMG) + px + r) * OC + oc + hp * 8] =
                *(uint4*)h;
            __syncwarp();
        }
    }
}

// ---------------------------------------------------------------------------
// Kernel 3b: conv_out (512->64). [R13/R14, unchanged]
// ---------------------------------------------------------------------------
__global__ __launch_bounds__(256, 1)
void conv_out_kernel(const __half* __restrict__ in,
                     const __half* __restrict__ Wt,
                     float* __restrict__ outp)
{
    constexpr int MF = 4, NF = 2, OCW = 32;
    constexpr int IC = INNER, OC = C_DIM;
    constexpr int A_ELEMS = 4 * 130 * AROWH;

    extern __shared__ __half smh[];
    __half* sA = smh;
    __half* sB = smh + A_ELEMS;
    uint32_t sA_u = (uint32_t)__cvta_generic_to_shared(sA);
    uint32_t sB_u = (uint32_t)__cvta_generic_to_shared(sB);

    int tid  = threadIdx.x;
    int wid  = tid >> 5;

    int y0  = blockIdx.x * 2;
    int img = blockIdx.z;

    int warp_row = wid & 1;
    int warp_pxg = (wid >> 1) & 1;
    int warp_ocg = wid >> 2;

    wmma::fragment<wmma::accumulator, 16, 16, 16, float> acc[MF][NF];
#pragma unroll
    for (int mf = 0; mf < MF; mf++)
#pragma unroll
        for (int nf = 0; nf < NF; nf++) wmma::fill_fragment(acc[mf][nf], 0.0f);

    for (int c = 0; c < IC / 64; c++) {
        int ic0 = c * 64;

        __syncthreads();
        for (int i = tid; i < 4 * 130 * 8; i += 256) {
            int r   = i / (130 * 8);
            int rem = i % (130 * 8);
            int p   = rem >> 3;
            int v   = rem & 7;
            int gy = y0 + r - 1, gx = p - 1;
            bool ok = (gy >= 0) && (gy < H_IMG) && (gx >= 0) && (gx < W_IMG);
            int cy = ok ? gy : 0, cx = ok ? gx : 0;
            const __half* src =
                &in[(((size_t)img * H_IMG + cy) * W_IMG + cx) * IC + ic0 + v * 8];
            cp16z(sA_u + ((r * 130 + p) * AROWH + v * 8) * 2, src, ok ? 16 : 0);
        }
        for (int i = tid; i < 9 * 64 * 8; i += 256) {
            int tap = i / (64 * 8);
            int rem = i % (64 * 8);
            int o   = rem >> 3;
            int v   = rem & 7;
            cp16(sB_u + ((tap * 64 + o) * AROWH + v * 8) * 2,
                 &Wt[(((size_t)tap * OC) + o) * IC + ic0 + v * 8]);
        }
        CP_WAIT_ALL();
        __syncthreads();

#pragma unroll
        for (int dy = 0; dy < 3; dy++) {
#pragma unroll
            for (int dx = 0; dx < 3; dx++) {
                const int tap = dy * 3 + dx;
#pragma unroll
                for (int s = 0; s < 4; s++) {
                    wmma::fragment<wmma::matrix_b, 16, 16, 16, __half,
                                   wmma::col_major> bf[NF];
#pragma unroll
                    for (int nf = 0; nf < NF; nf++)
                        wmma::load_matrix_sync(
                            bf[nf],
                            &sB[(tap * 64 + warp_ocg * OCW + nf * 16) * AROWH + s * 16],
                            AROWH);
#pragma unroll
                    for (int mf = 0; mf < MF; mf++) {
                        int px = warp_pxg * 64 + mf * 16;
                        wmma::fragment<wmma::matrix_a, 16, 16, 16, __half,
                                       wmma::row_major> af;
                        wmma::load_matrix_sync(
                            af, &sA[((warp_row + dy) * 130 + px + dx) * AROWH + s * 16],
                            AROWH);
#pragma unroll
                        for (int nf = 0; nf < NF; nf++)
                            wmma::mma_sync(acc[mf][nf], af, bf[nf], acc[mf][nf]);
                    }
                }
            }
        }
    }

    int y = y0 + warp_row;
#pragma unroll
    for (int mf = 0; mf < MF; mf++) {
        int px = warp_pxg * 64 + mf * 16;
#pragma unroll
        for (int nf = 0; nf < NF; nf++) {
            int oc = warp_ocg * OCW + nf * 16;
            float* dst = &outp[(((size_t)img * OC + oc) * H_IMG + y) * W_IMG + px];
            wmma::store_matrix_sync(dst, acc[mf][nf], HW, wmma::mem_col_major);
        }
    }
}

// ---------------------------------------------------------------------------
// Kernel 4: attention — FlashAttention-style mma.sync m16n8k16 pipeline.
// 64 threads = 2 warps = head pair; grid (1024, 4, B). smem = q/k/v slice only.
// Softmax entirely in registers via quad shuffles; sim accum -> A frag identity.
// ---------------------------------------------------------------------------
#define CSTR 136                              // half stride per pixel row (128+8)

__device__ __forceinline__ void ldsm4(uint32_t& a0, uint32_t& a1,
                                      uint32_t& a2, uint32_t& a3, uint32_t addr) {
    asm volatile("ldmatrix.sync.aligned.m8n8.x4.shared.b16 {%0,%1,%2,%3}, [%4];"
                 : "=r"(a0), "=r"(a1), "=r"(a2), "=r"(a3) : "r"(addr));
}
__device__ __forceinline__ void ldsm2(uint32_t& b0, uint32_t& b1, uint32_t addr) {
    asm volatile("ldmatrix.sync.aligned.m8n8.x2.shared.b16 {%0,%1}, [%2];"
                 : "=r"(b0), "=r"(b1) : "r"(addr));
}
__device__ __forceinline__ void ldsm2t(uint32_t& b0, uint32_t& b1, uint32_t addr) {
    asm volatile("ldmatrix.sync.aligned.m8n8.x2.trans.shared.b16 {%0,%1}, [%2];"
                 : "=r"(b0), "=r"(b1) : "r"(addr));
}
__device__ __forceinline__ void mma16816(float* d, uint32_t a0, uint32_t a1,
                                         uint32_t a2, uint32_t a3,
                                         uint32_t b0, uint32_t b1) {
    asm volatile(
        "mma.sync.aligned.m16n8k16.row.col.f32.f16.f16.f32 "
        "{%0,%1,%2,%3}, {%4,%5,%6,%7}, {%8,%9}, {%0,%1,%2,%3};"
        : "+f"(d[0]), "+f"(d[1]), "+f"(d[2]), "+f"(d[3])
        : "r"(a0), "r"(a1), "r"(a2), "r"(a3), "r"(b0), "r"(b1));
}

__global__ __launch_bounds__(64)
void attn_kernel(const __half* __restrict__ q,
                 const __half* __restrict__ kv,
                 const float* __restrict__ stat,
                 __half* __restrict__ outp)
{
    extern __shared__ __half smh[];
    __half* sQ = smh;                         // [16][CSTR]
    __half* sK = sQ + Q_L * CSTR;             // [48][CSTR]
    __half* sV = sK + KV_L * CSTR;            // [48][CSTR]

    int tid  = threadIdx.x;                   // 0..63
    int w    = tid >> 5;                      // warp = head within pair
    int lane = tid & 31;
    int win = blockIdx.x;
    int hg  = blockIdx.y;                     // head pair 0..3
    int bb  = blockIdx.z;
    int wy = win >> 5, wx = win & 31;
    int cbase = hg * 128;

    // ---- stage q/k/v 128-ch slices ----
    for (int i = tid; i < Q_L * 16; i += 64) {
        int pi = i >> 4, v = i & 15;
        int py = pi >> 2, px = pi & 3;
        int pix = (wy * 4 + py) * W_IMG + wx * 4 + px;
        *(uint4*)&sQ[pi * CSTR + v * 8] =
            *(const uint4*)&q[((size_t)bb * HW + pix) * INNER + cbase + v * 8];
    }
    for (int i = tid; i < KV_L * 16; i += 64) {
        int j = i >> 4, v = i & 15;
        int f = j >> 4, pi = j & 15;
        int py = pi >> 2, px = pi & 3;
        int pix = (wy * 4 + py) * W_IMG + wx * 4 + px;
        size_t base = ((size_t)(bb * 3 + f) * HW + pix) * (2 * INNER) + cbase;
        *(uint4*)&sK[j * CSTR + v * 8] = *(const uint4*)&kv[base + v * 8];
        *(uint4*)&sV[j * CSTR + v * 8] = *(const uint4*)&kv[base + INNER + v * 8];
    }
    __syncthreads();

    int dloc = w * DIM_HEAD;
    uint32_t sQ_u = (uint32_t)__cvta_generic_to_shared(sQ);
    uint32_t sK_u = (uint32_t)__cvta_generic_to_shared(sK);
    uint32_t sV_u = (uint32_t)__cvta_generic_to_shared(sV);

    int r  = lane >> 2;                       // row within fragment (0..7)
    int cq = (lane & 3) * 2;                  // col pair base

    // ---- sim = q k^T : 6 n-tiles x 4 k-steps ----
    float d[6][4];
#pragma unroll
    for (int j = 0; j < 6; j++)
#pragma unroll
        for (int e = 0; e < 4; e++) d[j][e] = 0.f;

    int l8  = lane & 7;
    int sel = (lane >> 3) & 1;
#pragma unroll
    for (int s = 0; s < 4; s++) {
        uint32_t a0, a1, a2, a3;
        uint32_t aaddr = sQ_u +
            (((lane & 15) * CSTR) + dloc + s * 16 + (lane >> 4) * 8) * 2;
        ldsm4(a0, a1, a2, a3, aaddr);
#pragma unroll
        for (int j = 0; j < 6; j++) {
            uint32_t b0, b1;
            uint32_t baddr = sK_u +
                (((j * 8 + l8) * CSTR) + dloc + s * 16 + sel * 8) * 2;
            ldsm2(b0, b1, baddr);
            mma16816(d[j], a0, a1, a2, a3, b0, b1);
        }
    }

    // ---- + static_a (L1-cached small table) ----
    int head = hg * 2 + w;
    const float* st = stat + (size_t)head * Q_L * KV_L;
#pragma unroll
    for (int j = 0; j < 6; j++) {
        int cc = j * 8 + cq;
        d[j][0] += __ldg(&st[r * KV_L + cc]);
        d[j][1] += __ldg(&st[r * KV_L + cc + 1]);
        d[j][2] += __ldg(&st[(r + 8) * KV_L + cc]);
        d[j][3] += __ldg(&st[(r + 8) * KV_L + cc + 1]);
    }

    // ---- softmax in registers (rows r and r+8) ----
    float mlo = -1e30f, mhi = -1e30f;
#pragma unroll
    for (int j = 0; j < 6; j++) {
        mlo = fmaxf(mlo, fmaxf(d[j][0], d[j][1]));
        mhi = fmaxf(mhi, fmaxf(d[j][2], d[j][3]));
    }
    mlo = fmaxf(mlo, __shfl_xor_sync(0xffffffffu, mlo, 1));
    mlo = fmaxf(mlo, __shfl_xor_sync(0xffffffffu, mlo, 2));
    mhi = fmaxf(mhi, __shfl_xor_sync(0xffffffffu, mhi, 1));
    mhi = fmaxf(mhi, __shfl_xor_sync(0xffffffffu, mhi, 2));

    float slo = 0.f, shi = 0.f;
#pragma unroll
    for (int j = 0; j < 6; j++) {
        d[j][0] = expf(d[j][0] - mlo); slo += d[j][0];
        d[j][1] = expf(d[j][1] - mlo); slo += d[j][1];
        d[j][2] = expf(d[j][2] - mhi); shi += d[j][2];
        d[j][3] = expf(d[j][3] - mhi); shi += d[j][3];
    }
    slo += __shfl_xor_sync(0xffffffffu, slo, 1);
    slo += __shfl_xor_sync(0xffffffffu, slo, 2);
    shi += __shfl_xor_sync(0xffffffffu, shi, 1);
    shi += __shfl_xor_sync(0xffffffffu, shi, 2);
    float ilo = 1.f / slo, ihi = 1.f / shi;

    // ---- pack probs to fp16 A-fragments (accumulator->A identity) ----
    uint32_t plo[6], phi[6];
#pragma unroll
    for (int j = 0; j < 6; j++) {
        __half2 h0 = __floats2half2_rn(d[j][0] * ilo, d[j][1] * ilo);
        __half2 h1 = __floats2half2_rn(d[j][2] * ihi, d[j][3] * ihi);
        plo[j] = *(uint32_t*)&h0;
        phi[j] = *(uint32_t*)&h1;
    }

    // ---- out = p v : 8 n-tiles x 3 k-steps ----
    float o[8][4];
#pragma unroll
    for (int n = 0; n < 8; n++)
#pragma unroll
        for (int e = 0; e < 4; e++) o[n][e] = 0.f;

#pragma unroll
    for (int kb = 0; kb < 3; kb++) {
        uint32_t a0 = plo[2 * kb], a1 = phi[2 * kb];
        uint32_t a2 = plo[2 * kb + 1], a3 = phi[2 * kb + 1];
#pragma unroll
        for (int n = 0; n < 8; n++) {
            uint32_t b0, b1;
            uint32_t baddr = sV_u +
                (((kb * 16 + sel * 8 + l8) * CSTR) + dloc + n * 8) * 2;
            ldsm2t(b0, b1, baddr);
            mma16816(o[n], a0, a1, a2, a3, b0, b1);
        }
    }

    // ---- store: rows r and r+8, half2 per n-tile ----
    {
        int py = r >> 2, px = r & 3;
        int pix_lo = (wy * 4 + py) * W_IMG + wx * 4 + px;
        int r2 = r + 8;
        int py2 = r2 >> 2, px2 = r2 & 3;
        int pix_hi = (wy * 4 + py2) * W_IMG + wx * 4 + px2;
        __half* dlo = &outp[((size_t)bb * HW + pix_lo) * INNER + cbase + dloc + cq];
        __half* dhi = &outp[((size_t)bb * HW + pix_hi) * INNER + cbase + dloc + cq];
#pragma unroll
        for (int n = 0; n < 8; n++) {
            __half2 h0 = __floats2half2_rn(o[n][0], o[n][1]);
            __half2 h1 = __floats2half2_rn(o[n][2], o[n][3]);
            *(__half2*)&dlo[n * 8] = h0;
            *(__half2*)&dhi[n * 8] = h1;
        }
    }
}

// ---------------------------------------------------------------------------
// Host launch
// ---------------------------------------------------------------------------
extern "C" void kernel_launch(void* const* d_in, const int* in_sizes, int n_in,
                              void* d_out, int out_size)
{
    (void)in_sizes; (void)n_in; (void)out_size;

    const float* q_inp   = (const float*)d_in[0];
    const float* k_inp   = (const float*)d_in[1];
    const float* flow_f  = (const float*)d_in[2];
    const float* flow_b  = (const float*)d_in[3];
    const float* gq      = (const float*)d_in[4];
    const float* bq      = (const float*)d_in[5];
    const float* gkv     = (const float*)d_in[6];
    const float* bkv     = (const float*)d_in[7];
    const float* Wq      = (const float*)d_in[8];
    const float* Wkv     = (const float*)d_in[9];
    const float* Wout    = (const float*)d_in[10];
    const float* statica = (const float*)d_in[11];

    __half *qn, *kvn, *qb, *kvb, *attb, *wtq, *wtkv, *wtout;
    cudaGetSymbolAddress((void**)&qn,    g_qn);
    cudaGetSymbolAddress((void**)&kvn,   g_kvn);
    cudaGetSymbolAddress((void**)&qb,    g_q);
    cudaGetSymbolAddress((void**)&kvb,   g_kv);
    cudaGetSymbolAddress((void**)&attb,  g_att);
    cudaGetSymbolAddress((void**)&wtq,   g_wt_q);
    cudaGetSymbolAddress((void**)&wtkv,  g_wt_kv);
    cudaGetSymbolAddress((void**)&wtout, g_wt_out);

    const int SMEM_QKV = (A6_ELEMS + 9 * 64 * AROWH) * 2 + 8 * 320 * 4;  // 205,504
    const int SMEM_OUT = (4 * 130 * AROWH + 9 * 64 * AROWH) * 2;         // 157,824
    const int SMEMA = (Q_L + 2 * KV_L) * CSTR * 2;                       // 30,464
    cudaFuncSetAttribute((const void*)conv_qkv_kernel,
                         cudaFuncAttributeMaxDynamicSharedMemorySize, SMEM_QKV);
    cudaFuncSetAttribute((const void*)conv_out_kernel,
                         cudaFuncAttributeMaxDynamicSharedMemorySize, SMEM_OUT);
    cudaFuncSetAttribute((const void*)attn_kernel,
                         cudaFuncAttributeMaxDynamicSharedMemorySize, SMEMA);

    // 0) all weight transforms in one launch
    wtrans_all_kernel<<<(4 * INNER * C_DIM + 255) / 256, 256>>>(
        Wq, Wkv, Wout, wtq, wtkv, wtout);

    // 1) merged layernorm (q + warped kv), 2 threads/px
    ln_all_kernel<<<dim3(2 * HW / 256, 4, B), 256>>>(
        q_inp, k_inp, flow_f, flow_b, gq, bq, gkv, bkv, qn, kvn);

    // 2) merged conv q + conv kv : 3584 CTAs, one launch
    conv_qkv_kernel<<<3584, 256, SMEM_QKV>>>(qn, wtq, qb, kvn, wtkv, kvb);

    // 3) attention: FA-style register pipeline, 7 CTAs/SM
    attn_kernel<<<dim3(1024, HEADS / 2, B), 64, SMEMA>>>(qb, kvb, statica, attb);

    // 4) conv out: 512 -> 64, fp32 NCHW -> d_out : 128 CTAs
    conv_out_kernel<<<dim3(H_IMG / 2, 1, B), 256, SMEM_OUT>>>(
        attb, wtout, (float*)d_out);
}

// round 16
// speedup vs baseline: 1.4958x; 1.0834x over previous
#include <cuda_runtime.h>
#include <cuda_fp16.h>
#include <mma.h>
#include <math.h>
#include <stdint.h>

using namespace nvcuda;

// ---------------------------------------------------------------------------
// Problem constants
// ---------------------------------------------------------------------------
#define B       2
#define C_DIM   64
#define H_IMG   128
#define W_IMG   128
#define HW      (H_IMG * W_IMG)          // 16384
#define HEADS   8
#define DIM_HEAD 64
#define INNER   (HEADS * DIM_HEAD)       // 512
#define Q_L     16
#define KV_L    48
#define LN_EPS  1e-5f

// ---------------------------------------------------------------------------
// Scratch buffers (__device__ globals; allocation is forbidden)
// ---------------------------------------------------------------------------
__device__ __half g_qn  [B * HW * C_DIM];            // LN(q), NHWC fp16
__device__ __half g_kvn [B * 3 * HW * C_DIM];        // warped+LN kv, NHWC fp16
__device__ __half g_q   [B * HW * INNER];            // conv q out, NHWC fp16 (pre-scaled)
__device__ __half g_kv  [B * 3 * HW * 2 * INNER];    // conv kv out, NHWC fp16
__device__ __half g_att [B * HW * INNER];            // attention out, NHWC fp16
__device__ __half g_wt_q  [9 * INNER * C_DIM];       // Wq*0.125 as [tap][oc][ic] fp16
__device__ __half g_wt_kv [9 * 2 * INNER * C_DIM];   // Wkv as [tap][oc][ic] fp16
__device__ __half g_wt_out[9 * C_DIM * INNER];       // Wout as [tap][oc][ic] fp16

// ---------------------------------------------------------------------------
// cp.async helpers (16B, cg; zfill via src-size)
// ---------------------------------------------------------------------------
__device__ __forceinline__ void cp16z(uint32_t dst, const void* src, int sz) {
    asm volatile("cp.async.cg.shared.global [%0], [%1], 16, %2;"
                 :: "r"(dst), "l"(src), "r"(sz) : "memory");
}
__device__ __forceinline__ void cp16(uint32_t dst, const void* src) {
    asm volatile("cp.async.cg.shared.global [%0], [%1], 16;"
                 :: "r"(dst), "l"(src) : "memory");
}
#define CP_COMMIT()     asm volatile("cp.async.commit_group;" ::: "memory")
#define CP_WAIT(n)      asm volatile("cp.async.wait_group %0;" :: "n"(n) : "memory")
#define CP_WAIT_ALL()   asm volatile("cp.async.wait_all;" ::: "memory")

// ---------------------------------------------------------------------------
// Kernel 0: all three weight transforms in one launch.
// ---------------------------------------------------------------------------
__global__ void wtrans_all_kernel(const float* __restrict__ Wq,
                                  const float* __restrict__ Wkv,
                                  const float* __restrict__ Wout,
                                  __half* __restrict__ wtq,
                                  __half* __restrict__ wtkv,
                                  __half* __restrict__ wtout)
{
    int idx = blockIdx.x * blockDim.x + threadIdx.x;
    const float* W; __half* Wt; int OC, IC; float scale;
    if (idx < INNER * C_DIM) {
        W = Wq; Wt = wtq; OC = INNER; IC = C_DIM; scale = 0.125f;
    } else if (idx < INNER * C_DIM + 2 * INNER * C_DIM) {
        idx -= INNER * C_DIM;
        W = Wkv; Wt = wtkv; OC = 2 * INNER; IC = C_DIM; scale = 1.0f;
    } else if (idx < 2 * (INNER * C_DIM) + 2 * INNER * C_DIM) {
        idx -= 3 * INNER * C_DIM;
        W = Wout; Wt = wtout; OC = C_DIM; IC = INNER; scale = 1.0f;
    } else return;

    int oc = idx / IC, ic = idx % IC;
    const float* src = W + ((size_t)oc * IC + ic) * 9;
#pragma unroll
    for (int t = 0; t < 9; t++)
        Wt[((size_t)t * OC + oc) * IC + ic] = __float2half_rn(src[t] * scale);
}

// ---------------------------------------------------------------------------
// Kernel 1: merged LayerNorm (q and warped-kv) -> NHWC fp16.
// ---------------------------------------------------------------------------
__global__ void ln_all_kernel(const float* __restrict__ q_inp,
                              const float* __restrict__ k_inp,
                              const float* __restrict__ flow_f,
                              const float* __restrict__ flow_b,
                              const float* __restrict__ gq,
                              const float* __restrict__ bq,
                              const float* __restrict__ gkv,
                              const float* __restrict__ bkv,
                              __half* __restrict__ qn,
                              __half* __restrict__ kvn)
{
    int t   = blockIdx.x * blockDim.x + threadIdx.x;
    int pix = t >> 1;
    int hf  = t & 1;
    if (pix >= HW) return;
    int f  = blockIdx.y;             // 0..2 kv, 3 q
    int bb = blockIdx.z;

    const float* base;
    const float* g;
    const float* beta;
    __half* ob;
    bool valid = true;

    if (f == 3) {
        base = q_inp + ((size_t)bb * C_DIM + hf * 32) * HW + pix;
        g = gq; beta = bq;
        ob = qn + ((size_t)bb * HW + pix) * C_DIM + hf * 32;
    } else {
        int y = pix >> 7, x = pix & 127;
        int src = pix;
        if (f != 1) {
            const float* fl = (f == 0) ? flow_f : flow_b;
            float fx = fl[((size_t)bb * 2 + 0) * HW + pix];
            float fy = fl[((size_t)bb * 2 + 1) * HW + pix];
            int ix = (int)rintf((float)x + fx);
            int iy = (int)rintf((float)y + fy);
            valid = (ix >= 0) && (ix < W_IMG) && (iy >= 0) && (iy < H_IMG);
            int cx = min(max(ix, 0), W_IMG - 1);
            int cy = min(max(iy, 0), H_IMG - 1);
            src = cy * W_IMG + cx;
        }
        base = k_inp + (((size_t)bb * 3 + f) * C_DIM + hf * 32) * HW + src;
        g = gkv; beta = bkv;
        ob = kvn + (((size_t)(bb * 3 + f)) * HW + pix) * C_DIM + hf * 32;
    }

    float v[32];
    float s = 0.f;
#pragma unroll
    for (int i = 0; i < 32; i++) {
        float vv = valid ? base[(size_t)i * HW] : 0.f;
        v[i] = vv; s += vv;
    }
    s += __shfl_xor_sync(0xffffffffu, s, 1);
    float mu = s * (1.f / C_DIM);
    float var = 0.f;
#pragma unroll
    for (int i = 0; i < 32; i++) { float d = v[i] - mu; var += d * d; }
    var += __shfl_xor_sync(0xffffffffu, var, 1);
    var *= (1.f / C_DIM);
    float inv = rsqrtf(var + LN_EPS);

    __half2 h[16];
#pragma unroll
    for (int i = 0; i < 32; i += 2) {
        int c = hf * 32 + i;
        h[i >> 1] = __floats2half2_rn((v[i]   - mu) * inv * g[c]   + beta[c],
                                      (v[i+1] - mu) * inv * g[c+1] + beta[c+1]);
    }
#pragma unroll
    for (int q4 = 0; q4 < 4; q4++)
        *(uint4*)&ob[q4 * 8] = ((uint4*)h)[q4];
}

// ---------------------------------------------------------------------------
// Kernel 3a: MERGED conv q + conv kv, pipelined B staging.
// Groups: 0 = A tile, 1 = B taps 0-2, 2 = B taps 3-5, 3 = B taps 6-8;
// progressive wait_group so dy0 compute overlaps B(dy1,dy2) loads.
// ---------------------------------------------------------------------------
#define AROWH 72
#define A6_ELEMS (6 * 130 * AROWH)

__global__ __launch_bounds__(256, 1)
void conv_qkv_kernel(const __half* __restrict__ qn,
                     const __half* __restrict__ wtq,
                     __half* __restrict__ qb,
                     const __half* __restrict__ kvn,
                     const __half* __restrict__ wtkv,
                     __half* __restrict__ kvb)
{
    constexpr int MF = 4, NF = 4;

    extern __shared__ __half smh[];
    __half* sA   = smh;
    __half* sB   = smh + A6_ELEMS;
    float*  sEpi = (float*)(smh + A6_ELEMS + 9 * 64 * AROWH);

    uint32_t sA_u = (uint32_t)__cvta_generic_to_shared(sA);
    uint32_t sB_u = (uint32_t)__cvta_generic_to_shared(sB);

    int tid  = threadIdx.x;
    int wid  = tid >> 5;
    int lane = tid & 31;

    const __half* in; const __half* Wt; __half* outp; int OC;
    int octile, ystrip;
    {
        int t = blockIdx.x;
        if (t < 3072) {
            int img = t >> 9; int rem = t & 511;
            octile = rem >> 5; ystrip = rem & 31;
            in   = kvn + (size_t)img * HW * C_DIM;
            Wt   = wtkv;
            outp = kvb + (size_t)img * HW * (2 * INNER);
            OC   = 2 * INNER;
        } else {
            t -= 3072;
            int img = t >> 8; int rem = t & 255;
            octile = rem >> 5; ystrip = rem & 31;
            in   = qn + (size_t)img * HW * C_DIM;
            Wt   = wtq;
            outp = qb + (size_t)img * HW * INNER;
            OC   = INNER;
        }
    }
    int y0  = ystrip * 4;
    int oc0 = octile * 64;

    int warp_row = wid & 3;
    int warp_pxg = wid >> 2;

    wmma::fragment<wmma::accumulator, 16, 16, 16, float> acc[MF][NF];
#pragma unroll
    for (int mf = 0; mf < MF; mf++)
#pragma unroll
        for (int nf = 0; nf < NF; nf++) wmma::fill_fragment(acc[mf][nf], 0.0f);

    // ---- group 0: stage A (6 rows x 130 px x 64 ic) ----
    for (int i = tid; i < 6 * 130 * 8; i += 256) {
        int r   = i / (130 * 8);
        int rem = i % (130 * 8);
        int p   = rem >> 3;
        int v   = rem & 7;
        int gy = y0 + r - 1, gx = p - 1;
        bool ok = (gy >= 0) && (gy < H_IMG) && (gx >= 0) && (gx < W_IMG);
        int cy = ok ? gy : 0, cx = ok ? gx : 0;
        const __half* src = &in[((size_t)cy * W_IMG + cx) * C_DIM + v * 8];
        cp16z(sA_u + ((r * 130 + p) * AROWH + v * 8) * 2, src, ok ? 16 : 0);
    }
    CP_COMMIT();
    // ---- groups 1..3: B tap-triples ----
#pragma unroll
    for (int dy = 0; dy < 3; dy++) {
        for (int i = tid; i < 3 * 64 * 8; i += 256) {
            int tap = dy * 3 + i / (64 * 8);
            int rem = i % (64 * 8);
            int o   = rem >> 3;
            int v   = rem & 7;
            cp16(sB_u + ((tap * 64 + o) * AROWH + v * 8) * 2,
                 &Wt[(((size_t)tap * OC) + oc0 + o) * C_DIM + v * 8]);
        }
        CP_COMMIT();
    }

    // ---- compute, overlapped with remaining B loads ----
#pragma unroll
    for (int dy = 0; dy < 3; dy++) {
        if (dy == 0)      { CP_WAIT(2); }
        else if (dy == 1) { CP_WAIT(1); }
        else              { CP_WAIT(0); }
        __syncthreads();
#pragma unroll
        for (int dx = 0; dx < 3; dx++) {
            const int tap = dy * 3 + dx;
#pragma unroll
            for (int s = 0; s < 4; s++) {
                wmma::fragment<wmma::matrix_b, 16, 16, 16, __half,
                               wmma::col_major> bf[NF];
#pragma unroll
                for (int nf = 0; nf < NF; nf++)
                    wmma::load_matrix_sync(
                        bf[nf], &sB[(tap * 64 + nf * 16) * AROWH + s * 16], AROWH);
#pragma unroll
                for (int mf = 0; mf < MF; mf++) {
                    int px = warp_pxg * 64 + mf * 16;
                    wmma::fragment<wmma::matrix_a, 16, 16, 16, __half,
                                   wmma::row_major> af;
                    wmma::load_matrix_sync(
                        af, &sA[((warp_row + dy) * 130 + px + dx) * AROWH + s * 16],
                        AROWH);
#pragma unroll
                    for (int nf = 0; nf < NF; nf++)
                        wmma::mma_sync(acc[mf][nf], af, bf[nf], acc[mf][nf]);
                }
            }
        }
    }

    int y = y0 + warp_row;
    float* buf = sEpi + wid * 320;
    int r  = lane >> 1;
    int hp = lane & 1;
#pragma unroll
    for (int mf = 0; mf < MF; mf++) {
        int px = warp_pxg * 64 + mf * 16;
#pragma unroll
        for (int nf = 0; nf < NF; nf++) {
            int oc = oc0 + nf * 16;
            wmma::store_matrix_sync(buf, acc[mf][nf], 20, wmma::mem_row_major);
            __syncwarp();
            float4 a = *(float4*)&buf[r * 20 + hp * 8];
            float4 b = *(float4*)&buf[r * 20 + hp * 8 + 4];
            __half2 h[4];
            h[0] = __floats2half2_rn(a.x, a.y);
            h[1] = __floats2half2_rn(a.z, a.w);
            h[2] = __floats2half2_rn(b.x, b.y);
            h[3] = __floats2half2_rn(b.z, b.w);
            *(uint4*)&outp[((size_t)(y * W_IMG) + px + r) * OC + oc + hp * 8] =
                *(uint4*)h;
            __syncwarp();
        }
    }
}

// ---------------------------------------------------------------------------
// Kernel 3b: conv_out (512->64), per-chunk staged waits.
// ---------------------------------------------------------------------------
__global__ __launch_bounds__(256, 1)
void conv_out_kernel(const __half* __restrict__ in,
                     const __half* __restrict__ Wt,
                     float* __restrict__ outp)
{
    constexpr int MF = 4, NF = 2, OCW = 32;
    constexpr int IC = INNER, OC = C_DIM;
    constexpr int A_ELEMS = 4 * 130 * AROWH;

    extern __shared__ __half smh[];
    __half* sA = smh;
    __half* sB = smh + A_ELEMS;
    uint32_t sA_u = (uint32_t)__cvta_generic_to_shared(sA);
    uint32_t sB_u = (uint32_t)__cvta_generic_to_shared(sB);

    int tid  = threadIdx.x;
    int wid  = tid >> 5;

    int y0  = blockIdx.x * 2;
    int img = blockIdx.z;

    int warp_row = wid & 1;
    int warp_pxg = (wid >> 1) & 1;
    int warp_ocg = wid >> 2;

    wmma::fragment<wmma::accumulator, 16, 16, 16, float> acc[MF][NF];
#pragma unroll
    for (int mf = 0; mf < MF; mf++)
#pragma unroll
        for (int nf = 0; nf < NF; nf++) wmma::fill_fragment(acc[mf][nf], 0.0f);

    for (int c = 0; c < IC / 64; c++) {
        int ic0 = c * 64;

        __syncthreads();                      // protect buffer reuse
        // group 0: A
        for (int i = tid; i < 4 * 130 * 8; i += 256) {
            int r   = i / (130 * 8);
            int rem = i % (130 * 8);
            int p   = rem >> 3;
            int v   = rem & 7;
            int gy = y0 + r - 1, gx = p - 1;
            bool ok = (gy >= 0) && (gy < H_IMG) && (gx >= 0) && (gx < W_IMG);
            int cy = ok ? gy : 0, cx = ok ? gx : 0;
            const __half* src =
                &in[(((size_t)img * H_IMG + cy) * W_IMG + cx) * IC + ic0 + v * 8];
            cp16z(sA_u + ((r * 130 + p) * AROWH + v * 8) * 2, src, ok ? 16 : 0);
        }
        CP_COMMIT();
        // groups 1..3: B tap-triples
#pragma unroll
        for (int dy = 0; dy < 3; dy++) {
            for (int i = tid; i < 3 * 64 * 8; i += 256) {
                int tap = dy * 3 + i / (64 * 8);
                int rem = i % (64 * 8);
                int o   = rem >> 3;
                int v   = rem & 7;
                cp16(sB_u + ((tap * 64 + o) * AROWH + v * 8) * 2,
                     &Wt[(((size_t)tap * OC) + o) * IC + ic0 + v * 8]);
            }
            CP_COMMIT();
        }

#pragma unroll
        for (int dy = 0; dy < 3; dy++) {
            if (dy == 0)      { CP_WAIT(2); }
            else if (dy == 1) { CP_WAIT(1); }
            else              { CP_WAIT(0); }
            __syncthreads();
#pragma unroll
            for (int dx = 0; dx < 3; dx++) {
                const int tap = dy * 3 + dx;
#pragma unroll
                for (int s = 0; s < 4; s++) {
                    wmma::fragment<wmma::matrix_b, 16, 16, 16, __half,
                                   wmma::col_major> bf[NF];
#pragma unroll
                    for (int nf = 0; nf < NF; nf++)
                        wmma::load_matrix_sync(
                            bf[nf],
                            &sB[(tap * 64 + warp_ocg * OCW + nf * 16) * AROWH + s * 16],
                            AROWH);
#pragma unroll
                    for (int mf = 0; mf < MF; mf++) {
                        int px = warp_pxg * 64 + mf * 16;
                        wmma::fragment<wmma::matrix_a, 16, 16, 16, __half,
                                       wmma::row_major> af;
                        wmma::load_matrix_sync(
                            af, &sA[((warp_row + dy) * 130 + px + dx) * AROWH + s * 16],
                            AROWH);
#pragma unroll
                        for (int nf = 0; nf < NF; nf++)
                            wmma::mma_sync(acc[mf][nf], af, bf[nf], acc[mf][nf]);
                    }
                }
            }
        }
    }

    int y = y0 + warp_row;
#pragma unroll
    for (int mf = 0; mf < MF; mf++) {
        int px = warp_pxg * 64 + mf * 16;
#pragma unroll
        for (int nf = 0; nf < NF; nf++) {
            int oc = warp_ocg * OCW + nf * 16;
            float* dst = &outp[(((size_t)img * OC + oc) * H_IMG + y) * W_IMG + px];
            wmma::store_matrix_sync(dst, acc[mf][nf], HW, wmma::mem_col_major);
        }
    }
}

// ---------------------------------------------------------------------------
// Kernel 4: attention — FA-style mma.sync pipeline, cp.async staging.
// ---------------------------------------------------------------------------
#define CSTR 136                              // half stride per pixel row (128+8)

__device__ __forceinline__ void ldsm4(uint32_t& a0, uint32_t& a1,
                                      uint32_t& a2, uint32_t& a3, uint32_t addr) {
    asm volatile("ldmatrix.sync.aligned.m8n8.x4.shared.b16 {%0,%1,%2,%3}, [%4];"
                 : "=r"(a0), "=r"(a1), "=r"(a2), "=r"(a3) : "r"(addr));
}
__device__ __forceinline__ void ldsm2(uint32_t& b0, uint32_t& b1, uint32_t addr) {
    asm volatile("ldmatrix.sync.aligned.m8n8.x2.shared.b16 {%0,%1}, [%2];"
                 : "=r"(b0), "=r"(b1) : "r"(addr));
}
__device__ __forceinline__ void ldsm2t(uint32_t& b0, uint32_t& b1, uint32_t addr) {
    asm volatile("ldmatrix.sync.aligned.m8n8.x2.trans.shared.b16 {%0,%1}, [%2];"
                 : "=r"(b0), "=r"(b1) : "r"(addr));
}
__device__ __forceinline__ void mma16816(float* d, uint32_t a0, uint32_t a1,
                                         uint32_t a2, uint32_t a3,
                                         uint32_t b0, uint32_t b1) {
    asm volatile(
        "mma.sync.aligned.m16n8k16.row.col.f32.f16.f16.f32 "
        "{%0,%1,%2,%3}, {%4,%5,%6,%7}, {%8,%9}, {%0,%1,%2,%3};"
        : "+f"(d[0]), "+f"(d[1]), "+f"(d[2]), "+f"(d[3])
        : "r"(a0), "r"(a1), "r"(a2), "r"(a3), "r"(b0), "r"(b1));
}

__global__ __launch_bounds__(64)
void attn_kernel(const __half* __restrict__ q,
                 const __half* __restrict__ kv,
                 const float* __restrict__ stat,
                 __half* __restrict__ outp)
{
    extern __shared__ __half smh[];
    __half* sQ = smh;                         // [16][CSTR]
    __half* sK = sQ + Q_L * CSTR;             // [48][CSTR]
    __half* sV = sK + KV_L * CSTR;            // [48][CSTR]

    int tid  = threadIdx.x;                   // 0..63
    int w    = tid >> 5;                      // warp = head within pair
    int lane = tid & 31;
    int win = blockIdx.x;
    int hg  = blockIdx.y;                     // head pair 0..3
    int bb  = blockIdx.z;
    int wy = win >> 5, wx = win & 31;
    int cbase = hg * 128;

    uint32_t sQ_u = (uint32_t)__cvta_generic_to_shared(sQ);
    uint32_t sK_u = (uint32_t)__cvta_generic_to_shared(sK);
    uint32_t sV_u = (uint32_t)__cvta_generic_to_shared(sV);

    // ---- stage q/k/v 128-ch slices via cp.async ----
    for (int i = tid; i < Q_L * 16; i += 64) {
        int pi = i >> 4, v = i & 15;
        int py = pi >> 2, px = pi & 3;
        int pix = (wy * 4 + py) * W_IMG + wx * 4 + px;
        cp16(sQ_u + (pi * CSTR + v * 8) * 2,
             &q[((size_t)bb * HW + pix) * INNER + cbase + v * 8]);
    }
    for (int i = tid; i < KV_L * 16; i += 64) {
        int j = i >> 4, v = i & 15;
        int f = j >> 4, pi = j & 15;
        int py = pi >> 2, px = pi & 3;
        int pix = (wy * 4 + py) * W_IMG + wx * 4 + px;
        size_t base = ((size_t)(bb * 3 + f) * HW + pix) * (2 * INNER) + cbase;
        cp16(sK_u + (j * CSTR + v * 8) * 2, &kv[base + v * 8]);
        cp16(sV_u + (j * CSTR + v * 8) * 2, &kv[base + INNER + v * 8]);
    }
    CP_WAIT_ALL();
    __syncthreads();

    int dloc = w * DIM_HEAD;
    int r  = lane >> 2;                       // row within fragment (0..7)
    int cq = (lane & 3) * 2;                  // col pair base

    // ---- sim = q k^T : 6 n-tiles x 4 k-steps ----
    float d[6][4];
#pragma unroll
    for (int j = 0; j < 6; j++)
#pragma unroll
        for (int e = 0; e < 4; e++) d[j][e] = 0.f;

    int l8  = lane & 7;
    int sel = (lane >> 3) & 1;
#pragma unroll
    for (int s = 0; s < 4; s++) {
        uint32_t a0, a1, a2, a3;
        uint32_t aaddr = sQ_u +
            (((lane & 15) * CSTR) + dloc + s * 16 + (lane >> 4) * 8) * 2;
        ldsm4(a0, a1, a2, a3, aaddr);
#pragma unroll
        for (int j = 0; j < 6; j++) {
            uint32_t b0, b1;
            uint32_t baddr = sK_u +
                (((j * 8 + l8) * CSTR) + dloc + s * 16 + sel * 8) * 2;
            ldsm2(b0, b1, baddr);
            mma16816(d[j], a0, a1, a2, a3, b0, b1);
        }
    }

    // ---- + static_a ----
    int head = hg * 2 + w;
    const float* st = stat + (size_t)head * Q_L * KV_L;
#pragma unroll
    for (int j = 0; j < 6; j++) {
        int cc = j * 8 + cq;
        d[j][0] += __ldg(&st[r * KV_L + cc]);
        d[j][1] += __ldg(&st[r * KV_L + cc + 1]);
        d[j][2] += __ldg(&st[(r + 8) * KV_L + cc]);
        d[j][3] += __ldg(&st[(r + 8) * KV_L + cc + 1]);
    }

    // ---- softmax in registers (rows r and r+8) ----
    float mlo = -1e30f, mhi = -1e30f;
#pragma unroll
    for (int j = 0; j < 6; j++) {
        mlo = fmaxf(mlo, fmaxf(d[j][0], d[j][1]));
        mhi = fmaxf(mhi, fmaxf(d[j][2], d[j][3]));
    }
    mlo = fmaxf(mlo, __shfl_xor_sync(0xffffffffu, mlo, 1));
    mlo = fmaxf(mlo, __shfl_xor_sync(0xffffffffu, mlo, 2));
    mhi = fmaxf(mhi, __shfl_xor_sync(0xffffffffu, mhi, 1));
    mhi = fmaxf(mhi, __shfl_xor_sync(0xffffffffu, mhi, 2));

    float slo = 0.f, shi = 0.f;
#pragma unroll
    for (int j = 0; j < 6; j++) {
        d[j][0] = expf(d[j][0] - mlo); slo += d[j][0];
        d[j][1] = expf(d[j][1] - mlo); slo += d[j][1];
        d[j][2] = expf(d[j][2] - mhi); shi += d[j][2];
        d[j][3] = expf(d[j][3] - mhi); shi += d[j][3];
    }
    slo += __shfl_xor_sync(0xffffffffu, slo, 1);
    slo += __shfl_xor_sync(0xffffffffu, slo, 2);
    shi += __shfl_xor_sync(0xffffffffu, shi, 1);
    shi += __shfl_xor_sync(0xffffffffu, shi, 2);
    float ilo = 1.f / slo, ihi = 1.f / shi;

    // ---- pack probs to fp16 A-fragments ----
    uint32_t plo[6], phi[6];
#pragma unroll
    for (int j = 0; j < 6; j++) {
        __half2 h0 = __floats2half2_rn(d[j][0] * ilo, d[j][1] * ilo);
        __half2 h1 = __floats2half2_rn(d[j][2] * ihi, d[j][3] * ihi);
        plo[j] = *(uint32_t*)&h0;
        phi[j] = *(uint32_t*)&h1;
    }

    // ---- out = p v : 8 n-tiles x 3 k-steps ----
    float o[8][4];
#pragma unroll
    for (int n = 0; n < 8; n++)
#pragma unroll
        for (int e = 0; e < 4; e++) o[n][e] = 0.f;

#pragma unroll
    for (int kb = 0; kb < 3; kb++) {
        uint32_t a0 = plo[2 * kb], a1 = phi[2 * kb];
        uint32_t a2 = plo[2 * kb + 1], a3 = phi[2 * kb + 1];
#pragma unroll
        for (int n = 0; n < 8; n++) {
            uint32_t b0, b1;
            uint32_t baddr = sV_u +
                (((kb * 16 + sel * 8 + l8) * CSTR) + dloc + n * 8) * 2;
            ldsm2t(b0, b1, baddr);
            mma16816(o[n], a0, a1, a2, a3, b0, b1);
        }
    }

    // ---- store: rows r and r+8, half2 per n-tile ----
    {
        int py = r >> 2, px = r & 3;
        int pix_lo = (wy * 4 + py) * W_IMG + wx * 4 + px;
        int r2 = r + 8;
        int py2 = r2 >> 2, px2 = r2 & 3;
        int pix_hi = (wy * 4 + py2) * W_IMG + wx * 4 + px2;
        __half* dlo = &outp[((size_t)bb * HW + pix_lo) * INNER + cbase + dloc + cq];
        __half* dhi = &outp[((size_t)bb * HW + pix_hi) * INNER + cbase + dloc + cq];
#pragma unroll
        for (int n = 0; n < 8; n++) {
            __half2 h0 = __floats2half2_rn(o[n][0], o[n][1]);
            __half2 h1 = __floats2half2_rn(o[n][2], o[n][3]);
            *(__half2*)&dlo[n * 8] = h0;
            *(__half2*)&dhi[n * 8] = h1;
        }
    }
}

// ---------------------------------------------------------------------------
// Host launch
// ---------------------------------------------------------------------------
extern "C" void kernel_launch(void* const* d_in, const int* in_sizes, int n_in,
                              void* d_out, int out_size)
{
    (void)in_sizes; (void)n_in; (void)out_size;

    const float* q_inp   = (const float*)d_in[0];
    const float* k_inp   = (const float*)d_in[1];
    const float* flow_f  = (const float*)d_in[2];
    const float* flow_b  = (const float*)d_in[3];
    const float* gq      = (const float*)d_in[4];
    const float* bq      = (const float*)d_in[5];
    const float* gkv     = (const float*)d_in[6];
    const float* bkv     = (const float*)d_in[7];
    const float* Wq      = (const float*)d_in[8];
    const float* Wkv     = (const float*)d_in[9];
    const float* Wout    = (const float*)d_in[10];
    const float* statica = (const float*)d_in[11];

    __half *qn, *kvn, *qb, *kvb, *attb, *wtq, *wtkv, *wtout;
    cudaGetSymbolAddress((void**)&qn,    g_qn);
    cudaGetSymbolAddress((void**)&kvn,   g_kvn);
    cudaGetSymbolAddress((void**)&qb,    g_q);
    cudaGetSymbolAddress((void**)&kvb,   g_kv);
    cudaGetSymbolAddress((void**)&attb,  g_att);
    cudaGetSymbolAddress((void**)&wtq,   g_wt_q);
    cudaGetSymbolAddress((void**)&wtkv,  g_wt_kv);
    cudaGetSymbolAddress((void**)&wtout, g_wt_out);

    const int SMEM_QKV = (A6_ELEMS + 9 * 64 * AROWH) * 2 + 8 * 320 * 4;  // 205,504
    const int SMEM_OUT = (4 * 130 * AROWH + 9 * 64 * AROWH) * 2;         // 157,824
    const int SMEMA = (Q_L + 2 * KV_L) * CSTR * 2;                       // 30,464
    cudaFuncSetAttribute((const void*)conv_qkv_kernel,
                         cudaFuncAttributeMaxDynamicSharedMemorySize, SMEM_QKV);
    cudaFuncSetAttribute((const void*)conv_out_kernel,
                         cudaFuncAttributeMaxDynamicSharedMemorySize, SMEM_OUT);
    cudaFuncSetAttribute((const void*)attn_kernel,
                         cudaFuncAttributeMaxDynamicSharedMemorySize, SMEMA);

    // 0) all weight transforms in one launch
    wtrans_all_kernel<<<(4 * INNER * C_DIM + 255) / 256, 256>>>(
        Wq, Wkv, Wout, wtq, wtkv, wtout);

    // 1) merged layernorm (q + warped kv), 2 threads/px
    ln_all_kernel<<<dim3(2 * HW / 256, 4, B), 256>>>(
        q_inp, k_inp, flow_f, flow_b, gq, bq, gkv, bkv, qn, kvn);

    // 2) merged conv q + conv kv : 3584 CTAs, pipelined staging
    conv_qkv_kernel<<<3584, 256, SMEM_QKV>>>(qn, wtq, qb, kvn, wtkv, kvb);

    // 3) attention: FA-style register pipeline + cp.async staging
    attn_kernel<<<dim3(1024, HEADS / 2, B), 64, SMEMA>>>(qb, kvb, statica, attb);

    // 4) conv out: 512 -> 64, fp32 NCHW -> d_out : 128 CTAs, staged waits
    conv_out_kernel<<<dim3(H_IMG / 2, 1, B), 256, SMEM_OUT>>>(
        attb, wtout, (float*)d_out);
}

// round 17
// speedup vs baseline: 1.4998x; 1.0027x over previous
#include <cuda_runtime.h>
#include <cuda_fp16.h>
#include <mma.h>
#include <math.h>
#include <stdint.h>

using namespace nvcuda;

// ---------------------------------------------------------------------------
// Problem constants
// ---------------------------------------------------------------------------
#define B       2
#define C_DIM   64
#define H_IMG   128
#define W_IMG   128
#define HW      (H_IMG * W_IMG)          // 16384
#define HEADS   8
#define DIM_HEAD 64
#define INNER   (HEADS * DIM_HEAD)       // 512
#define Q_L     16
#define KV_L    48
#define LN_EPS  1e-5f

// ---------------------------------------------------------------------------
// Scratch buffers (__device__ globals; allocation is forbidden)
// ---------------------------------------------------------------------------
__device__ __half g_qn  [B * HW * C_DIM];            // LN(q), NHWC fp16
__device__ __half g_kvn [B * 3 * HW * C_DIM];        // warped+LN kv, NHWC fp16
__device__ __half g_q   [B * HW * INNER];            // conv q out, NHWC fp16 (pre-scaled)
__device__ __half g_kv  [B * 3 * HW * 2 * INNER];    // conv kv out, NHWC fp16
__device__ __half g_att [B * HW * INNER];            // attention out, NHWC fp16
__device__ __half g_wt_q  [9 * INNER * C_DIM];       // Wq*0.125 as [tap][oc][ic] fp16
__device__ __half g_wt_kv [9 * 2 * INNER * C_DIM];   // Wkv as [tap][oc][ic] fp16
__device__ __half g_wt_out[9 * C_DIM * INNER];       // Wout as [tap][oc][ic] fp16

// ---------------------------------------------------------------------------
// cp.async helpers (16B, cg; zfill via src-size)
// ---------------------------------------------------------------------------
__device__ __forceinline__ void cp16z(uint32_t dst, const void* src, int sz) {
    asm volatile("cp.async.cg.shared.global [%0], [%1], 16, %2;"
                 :: "r"(dst), "l"(src), "r"(sz) : "memory");
}
__device__ __forceinline__ void cp16(uint32_t dst, const void* src) {
    asm volatile("cp.async.cg.shared.global [%0], [%1], 16;"
                 :: "r"(dst), "l"(src) : "memory");
}
#define CP_COMMIT()     asm volatile("cp.async.commit_group;" ::: "memory")
#define CP_WAIT(n)      asm volatile("cp.async.wait_group %0;" :: "n"(n) : "memory")
#define CP_WAIT_ALL()   asm volatile("cp.async.wait_all;" ::: "memory")

// ---------------------------------------------------------------------------
// Kernel 0: all three weight transforms in one launch.
// ---------------------------------------------------------------------------
__global__ void wtrans_all_kernel(const float* __restrict__ Wq,
                                  const float* __restrict__ Wkv,
                                  const float* __restrict__ Wout,
                                  __half* __restrict__ wtq,
                                  __half* __restrict__ wtkv,
                                  __half* __restrict__ wtout)
{
    int idx = blockIdx.x * blockDim.x + threadIdx.x;
    const float* W; __half* Wt; int OC, IC; float scale;
    if (idx < INNER * C_DIM) {
        W = Wq; Wt = wtq; OC = INNER; IC = C_DIM; scale = 0.125f;
    } else if (idx < INNER * C_DIM + 2 * INNER * C_DIM) {
        idx -= INNER * C_DIM;
        W = Wkv; Wt = wtkv; OC = 2 * INNER; IC = C_DIM; scale = 1.0f;
    } else if (idx < 2 * (INNER * C_DIM) + 2 * INNER * C_DIM) {
        idx -= 3 * INNER * C_DIM;
        W = Wout; Wt = wtout; OC = C_DIM; IC = INNER; scale = 1.0f;
    } else return;

    int oc = idx / IC, ic = idx % IC;
    const float* src = W + ((size_t)oc * IC + ic) * 9;
#pragma unroll
    for (int t = 0; t < 9; t++)
        Wt[((size_t)t * OC + oc) * IC + ic] = __float2half_rn(src[t] * scale);
}

// ---------------------------------------------------------------------------
// Kernel 1: merged LayerNorm (q and warped-kv) -> NHWC fp16.
// ---------------------------------------------------------------------------
__global__ void ln_all_kernel(const float* __restrict__ q_inp,
                              const float* __restrict__ k_inp,
                              const float* __restrict__ flow_f,
                              const float* __restrict__ flow_b,
                              const float* __restrict__ gq,
                              const float* __restrict__ bq,
                              const float* __restrict__ gkv,
                              const float* __restrict__ bkv,
                              __half* __restrict__ qn,
                              __half* __restrict__ kvn)
{
    int t   = blockIdx.x * blockDim.x + threadIdx.x;
    int pix = t >> 1;
    int hf  = t & 1;
    if (pix >= HW) return;
    int f  = blockIdx.y;             // 0..2 kv, 3 q
    int bb = blockIdx.z;

    const float* base;
    const float* g;
    const float* beta;
    __half* ob;
    bool valid = true;

    if (f == 3) {
        base = q_inp + ((size_t)bb * C_DIM + hf * 32) * HW + pix;
        g = gq; beta = bq;
        ob = qn + ((size_t)bb * HW + pix) * C_DIM + hf * 32;
    } else {
        int y = pix >> 7, x = pix & 127;
        int src = pix;
        if (f != 1) {
            const float* fl = (f == 0) ? flow_f : flow_b;
            float fx = fl[((size_t)bb * 2 + 0) * HW + pix];
            float fy = fl[((size_t)bb * 2 + 1) * HW + pix];
            int ix = (int)rintf((float)x + fx);
            int iy = (int)rintf((float)y + fy);
            valid = (ix >= 0) && (ix < W_IMG) && (iy >= 0) && (iy < H_IMG);
            int cx = min(max(ix, 0), W_IMG - 1);
            int cy = min(max(iy, 0), H_IMG - 1);
            src = cy * W_IMG + cx;
        }
        base = k_inp + (((size_t)bb * 3 + f) * C_DIM + hf * 32) * HW + src;
        g = gkv; beta = bkv;
        ob = kvn + (((size_t)(bb * 3 + f)) * HW + pix) * C_DIM + hf * 32;
    }

    float v[32];
    float s = 0.f;
#pragma unroll
    for (int i = 0; i < 32; i++) {
        float vv = valid ? base[(size_t)i * HW] : 0.f;
        v[i] = vv; s += vv;
    }
    s += __shfl_xor_sync(0xffffffffu, s, 1);
    float mu = s * (1.f / C_DIM);
    float var = 0.f;
#pragma unroll
    for (int i = 0; i < 32; i++) { float d = v[i] - mu; var += d * d; }
    var += __shfl_xor_sync(0xffffffffu, var, 1);
    var *= (1.f / C_DIM);
    float inv = rsqrtf(var + LN_EPS);

    __half2 h[16];
#pragma unroll
    for (int i = 0; i < 32; i += 2) {
        int c = hf * 32 + i;
        h[i >> 1] = __floats2half2_rn((v[i]   - mu) * inv * g[c]   + beta[c],
                                      (v[i+1] - mu) * inv * g[c+1] + beta[c+1]);
    }
#pragma unroll
    for (int q4 = 0; q4 < 4; q4++)
        *(uint4*)&ob[q4 * 8] = ((uint4*)h)[q4];
}

// ---------------------------------------------------------------------------
// Kernel 3a: MERGED conv q + conv kv, pipelined B staging. [R16, unchanged]
// ---------------------------------------------------------------------------
#define AROWH 72
#define A6_ELEMS (6 * 130 * AROWH)

__global__ __launch_bounds__(256, 1)
void conv_qkv_kernel(const __half* __restrict__ qn,
                     const __half* __restrict__ wtq,
                     __half* __restrict__ qb,
                     const __half* __restrict__ kvn,
                     const __half* __restrict__ wtkv,
                     __half* __restrict__ kvb)
{
    constexpr int MF = 4, NF = 4;

    extern __shared__ __half smh[];
    __half* sA   = smh;
    __half* sB   = smh + A6_ELEMS;
    float*  sEpi = (float*)(smh + A6_ELEMS + 9 * 64 * AROWH);

    uint32_t sA_u = (uint32_t)__cvta_generic_to_shared(sA);
    uint32_t sB_u = (uint32_t)__cvta_generic_to_shared(sB);

    int tid  = threadIdx.x;
    int wid  = tid >> 5;
    int lane = tid & 31;

    const __half* in; const __half* Wt; __half* outp; int OC;
    int octile, ystrip;
    {
        int t = blockIdx.x;
        if (t < 3072) {
            int img = t >> 9; int rem = t & 511;
            octile = rem >> 5; ystrip = rem & 31;
            in   = kvn + (size_t)img * HW * C_DIM;
            Wt   = wtkv;
            outp = kvb + (size_t)img * HW * (2 * INNER);
            OC   = 2 * INNER;
        } else {
            t -= 3072;
            int img = t >> 8; int rem = t & 255;
            octile = rem >> 5; ystrip = rem & 31;
            in   = qn + (size_t)img * HW * C_DIM;
            Wt   = wtq;
            outp = qb + (size_t)img * HW * INNER;
            OC   = INNER;
        }
    }
    int y0  = ystrip * 4;
    int oc0 = octile * 64;

    int warp_row = wid & 3;
    int warp_pxg = wid >> 2;

    wmma::fragment<wmma::accumulator, 16, 16, 16, float> acc[MF][NF];
#pragma unroll
    for (int mf = 0; mf < MF; mf++)
#pragma unroll
        for (int nf = 0; nf < NF; nf++) wmma::fill_fragment(acc[mf][nf], 0.0f);

    // ---- group 0: stage A ----
    for (int i = tid; i < 6 * 130 * 8; i += 256) {
        int r   = i / (130 * 8);
        int rem = i % (130 * 8);
        int p   = rem >> 3;
        int v   = rem & 7;
        int gy = y0 + r - 1, gx = p - 1;
        bool ok = (gy >= 0) && (gy < H_IMG) && (gx >= 0) && (gx < W_IMG);
        int cy = ok ? gy : 0, cx = ok ? gx : 0;
        const __half* src = &in[((size_t)cy * W_IMG + cx) * C_DIM + v * 8];
        cp16z(sA_u + ((r * 130 + p) * AROWH + v * 8) * 2, src, ok ? 16 : 0);
    }
    CP_COMMIT();
    // ---- groups 1..3: B tap-triples ----
#pragma unroll
    for (int dy = 0; dy < 3; dy++) {
        for (int i = tid; i < 3 * 64 * 8; i += 256) {
            int tap = dy * 3 + i / (64 * 8);
            int rem = i % (64 * 8);
            int o   = rem >> 3;
            int v   = rem & 7;
            cp16(sB_u + ((tap * 64 + o) * AROWH + v * 8) * 2,
                 &Wt[(((size_t)tap * OC) + oc0 + o) * C_DIM + v * 8]);
        }
        CP_COMMIT();
    }

#pragma unroll
    for (int dy = 0; dy < 3; dy++) {
        if (dy == 0)      { CP_WAIT(2); }
        else if (dy == 1) { CP_WAIT(1); }
        else              { CP_WAIT(0); }
        __syncthreads();
#pragma unroll
        for (int dx = 0; dx < 3; dx++) {
            const int tap = dy * 3 + dx;
#pragma unroll
            for (int s = 0; s < 4; s++) {
                wmma::fragment<wmma::matrix_b, 16, 16, 16, __half,
                               wmma::col_major> bf[NF];
#pragma unroll
                for (int nf = 0; nf < NF; nf++)
                    wmma::load_matrix_sync(
                        bf[nf], &sB[(tap * 64 + nf * 16) * AROWH + s * 16], AROWH);
#pragma unroll
                for (int mf = 0; mf < MF; mf++) {
                    int px = warp_pxg * 64 + mf * 16;
                    wmma::fragment<wmma::matrix_a, 16, 16, 16, __half,
                                   wmma::row_major> af;
                    wmma::load_matrix_sync(
                        af, &sA[((warp_row + dy) * 130 + px + dx) * AROWH + s * 16],
                        AROWH);
#pragma unroll
                    for (int nf = 0; nf < NF; nf++)
                        wmma::mma_sync(acc[mf][nf], af, bf[nf], acc[mf][nf]);
                }
            }
        }
    }

    int y = y0 + warp_row;
    float* buf = sEpi + wid * 320;
    int r  = lane >> 1;
    int hp = lane & 1;
#pragma unroll
    for (int mf = 0; mf < MF; mf++) {
        int px = warp_pxg * 64 + mf * 16;
#pragma unroll
        for (int nf = 0; nf < NF; nf++) {
            int oc = oc0 + nf * 16;
            wmma::store_matrix_sync(buf, acc[mf][nf], 20, wmma::mem_row_major);
            __syncwarp();
            float4 a = *(float4*)&buf[r * 20 + hp * 8];
            float4 b = *(float4*)&buf[r * 20 + hp * 8 + 4];
            __half2 h[4];
            h[0] = __floats2half2_rn(a.x, a.y);
            h[1] = __floats2half2_rn(a.z, a.w);
            h[2] = __floats2half2_rn(b.x, b.y);
            h[3] = __floats2half2_rn(b.z, b.w);
            *(uint4*)&outp[((size_t)(y * W_IMG) + px + r) * OC + oc + hp * 8] =
                *(uint4*)h;
            __syncwarp();
        }
    }
}

// ---------------------------------------------------------------------------
// Kernel 3b: conv_out (512->64), per-chunk staged waits. [R16, unchanged]
// ---------------------------------------------------------------------------
__global__ __launch_bounds__(256, 1)
void conv_out_kernel(const __half* __restrict__ in,
                     const __half* __restrict__ Wt,
                     float* __restrict__ outp)
{
    constexpr int MF = 4, NF = 2, OCW = 32;
    constexpr int IC = INNER, OC = C_DIM;
    constexpr int A_ELEMS = 4 * 130 * AROWH;

    extern __shared__ __half smh[];
    __half* sA = smh;
    __half* sB = smh + A_ELEMS;
    uint32_t sA_u = (uint32_t)__cvta_generic_to_shared(sA);
    uint32_t sB_u = (uint32_t)__cvta_generic_to_shared(sB);

    int tid  = threadIdx.x;
    int wid  = tid >> 5;

    int y0  = blockIdx.x * 2;
    int img = blockIdx.z;

    int warp_row = wid & 1;
    int warp_pxg = (wid >> 1) & 1;
    int warp_ocg = wid >> 2;

    wmma::fragment<wmma::accumulator, 16, 16, 16, float> acc[MF][NF];
#pragma unroll
    for (int mf = 0; mf < MF; mf++)
#pragma unroll
        for (int nf = 0; nf < NF; nf++) wmma::fill_fragment(acc[mf][nf], 0.0f);

    for (int c = 0; c < IC / 64; c++) {
        int ic0 = c * 64;

        __syncthreads();
        for (int i = tid; i < 4 * 130 * 8; i += 256) {
            int r   = i / (130 * 8);
            int rem = i % (130 * 8);
            int p   = rem >> 3;
            int v   = rem & 7;
            int gy = y0 + r - 1, gx = p - 1;
            bool ok = (gy >= 0) && (gy < H_IMG) && (gx >= 0) && (gx < W_IMG);
            int cy = ok ? gy : 0, cx = ok ? gx : 0;
            const __half* src =
                &in[(((size_t)img * H_IMG + cy) * W_IMG + cx) * IC + ic0 + v * 8];
            cp16z(sA_u + ((r * 130 + p) * AROWH + v * 8) * 2, src, ok ? 16 : 0);
        }
        CP_COMMIT();
#pragma unroll
        for (int dy = 0; dy < 3; dy++) {
            for (int i = tid; i < 3 * 64 * 8; i += 256) {
                int tap = dy * 3 + i / (64 * 8);
                int rem = i % (64 * 8);
                int o   = rem >> 3;
                int v   = rem & 7;
                cp16(sB_u + ((tap * 64 + o) * AROWH + v * 8) * 2,
                     &Wt[(((size_t)tap * OC) + o) * IC + ic0 + v * 8]);
            }
            CP_COMMIT();
        }

#pragma unroll
        for (int dy = 0; dy < 3; dy++) {
            if (dy == 0)      { CP_WAIT(2); }
            else if (dy == 1) { CP_WAIT(1); }
            else              { CP_WAIT(0); }
            __syncthreads();
#pragma unroll
            for (int dx = 0; dx < 3; dx++) {
                const int tap = dy * 3 + dx;
#pragma unroll
                for (int s = 0; s < 4; s++) {
                    wmma::fragment<wmma::matrix_b, 16, 16, 16, __half,
                                   wmma::col_major> bf[NF];
#pragma unroll
                    for (int nf = 0; nf < NF; nf++)
                        wmma::load_matrix_sync(
                            bf[nf],
                            &sB[(tap * 64 + warp_ocg * OCW + nf * 16) * AROWH + s * 16],
                            AROWH);
#pragma unroll
                    for (int mf = 0; mf < MF; mf++) {
                        int px = warp_pxg * 64 + mf * 16;
                        wmma::fragment<wmma::matrix_a, 16, 16, 16, __half,
                                       wmma::row_major> af;
                        wmma::load_matrix_sync(
                            af, &sA[((warp_row + dy) * 130 + px + dx) * AROWH + s * 16],
                            AROWH);
#pragma unroll
                        for (int nf = 0; nf < NF; nf++)
                            wmma::mma_sync(acc[mf][nf], af, bf[nf], acc[mf][nf]);
                    }
                }
            }
        }
    }

    int y = y0 + warp_row;
#pragma unroll
    for (int mf = 0; mf < MF; mf++) {
        int px = warp_pxg * 64 + mf * 16;
#pragma unroll
        for (int nf = 0; nf < NF; nf++) {
            int oc = warp_ocg * OCW + nf * 16;
            float* dst = &outp[(((size_t)img * OC + oc) * H_IMG + y) * W_IMG + px];
            wmma::store_matrix_sync(dst, acc[mf][nf], HW, wmma::mem_col_major);
        }
    }
}

// ---------------------------------------------------------------------------
// Kernel 4: attention — FA-style mma.sync pipeline, SPLIT-GROUP cp.async:
// group(q,k) then group(v); sim/softmax overlap the V load.
// ---------------------------------------------------------------------------
#define CSTR 136                              // half stride per pixel row (128+8)

__device__ __forceinline__ void ldsm4(uint32_t& a0, uint32_t& a1,
                                      uint32_t& a2, uint32_t& a3, uint32_t addr) {
    asm volatile("ldmatrix.sync.aligned.m8n8.x4.shared.b16 {%0,%1,%2,%3}, [%4];"
                 : "=r"(a0), "=r"(a1), "=r"(a2), "=r"(a3) : "r"(addr));
}
__device__ __forceinline__ void ldsm2(uint32_t& b0, uint32_t& b1, uint32_t addr) {
    asm volatile("ldmatrix.sync.aligned.m8n8.x2.shared.b16 {%0,%1}, [%2];"
                 : "=r"(b0), "=r"(b1) : "r"(addr));
}
__device__ __forceinline__ void ldsm2t(uint32_t& b0, uint32_t& b1, uint32_t addr) {
    asm volatile("ldmatrix.sync.aligned.m8n8.x2.trans.shared.b16 {%0,%1}, [%2];"
                 : "=r"(b0), "=r"(b1) : "r"(addr));
}
__device__ __forceinline__ void mma16816(float* d, uint32_t a0, uint32_t a1,
                                         uint32_t a2, uint32_t a3,
                                         uint32_t b0, uint32_t b1) {
    asm volatile(
        "mma.sync.aligned.m16n8k16.row.col.f32.f16.f16.f32 "
        "{%0,%1,%2,%3}, {%4,%5,%6,%7}, {%8,%9}, {%0,%1,%2,%3};"
        : "+f"(d[0]), "+f"(d[1]), "+f"(d[2]), "+f"(d[3])
        : "r"(a0), "r"(a1), "r"(a2), "r"(a3), "r"(b0), "r"(b1));
}

__global__ __launch_bounds__(64)
void attn_kernel(const __half* __restrict__ q,
                 const __half* __restrict__ kv,
                 const float* __restrict__ stat,
                 __half* __restrict__ outp)
{
    extern __shared__ __half smh[];
    __half* sQ = smh;                         // [16][CSTR]
    __half* sK = sQ + Q_L * CSTR;             // [48][CSTR]
    __half* sV = sK + KV_L * CSTR;            // [48][CSTR]

    int tid  = threadIdx.x;                   // 0..63
    int w    = tid >> 5;                      // warp = head within pair
    int lane = tid & 31;
    int win = blockIdx.x;
    int hg  = blockIdx.y;                     // head pair 0..3
    int bb  = blockIdx.z;
    int wy = win >> 5, wx = win & 31;
    int cbase = hg * 128;

    uint32_t sQ_u = (uint32_t)__cvta_generic_to_shared(sQ);
    uint32_t sK_u = (uint32_t)__cvta_generic_to_shared(sK);
    uint32_t sV_u = (uint32_t)__cvta_generic_to_shared(sV);

    // ---- group 0: stage q and k ----
    for (int i = tid; i < Q_L * 16; i += 64) {
        int pi = i >> 4, v = i & 15;
        int py = pi >> 2, px = pi & 3;
        int pix = (wy * 4 + py) * W_IMG + wx * 4 + px;
        cp16(sQ_u + (pi * CSTR + v * 8) * 2,
             &q[((size_t)bb * HW + pix) * INNER + cbase + v * 8]);
    }
    for (int i = tid; i < KV_L * 16; i += 64) {
        int j = i >> 4, v = i & 15;
        int f = j >> 4, pi = j & 15;
        int py = pi >> 2, px = pi & 3;
        int pix = (wy * 4 + py) * W_IMG + wx * 4 + px;
        size_t base = ((size_t)(bb * 3 + f) * HW + pix) * (2 * INNER) + cbase;
        cp16(sK_u + (j * CSTR + v * 8) * 2, &kv[base + v * 8]);
    }
    CP_COMMIT();
    // ---- group 1: stage v ----
    for (int i = tid; i < KV_L * 16; i += 64) {
        int j = i >> 4, v = i & 15;
        int f = j >> 4, pi = j & 15;
        int py = pi >> 2, px = pi & 3;
        int pix = (wy * 4 + py) * W_IMG + wx * 4 + px;
        size_t base = ((size_t)(bb * 3 + f) * HW + pix) * (2 * INNER) + cbase;
        cp16(sV_u + (j * CSTR + v * 8) * 2, &kv[base + INNER + v * 8]);
    }
    CP_COMMIT();

    int dloc = w * DIM_HEAD;
    int r  = lane >> 2;                       // row within fragment (0..7)
    int cq = (lane & 3) * 2;                  // col pair base
    int head = hg * 2 + w;

    // ---- prefetch static_a while loads are in flight ----
    float sa[6][4];
    {
        const float* st = stat + (size_t)head * Q_L * KV_L;
#pragma unroll
        for (int j = 0; j < 6; j++) {
            int cc = j * 8 + cq;
            sa[j][0] = __ldg(&st[r * KV_L + cc]);
            sa[j][1] = __ldg(&st[r * KV_L + cc + 1]);
            sa[j][2] = __ldg(&st[(r + 8) * KV_L + cc]);
            sa[j][3] = __ldg(&st[(r + 8) * KV_L + cc + 1]);
        }
    }

    // ---- wait for q,k only; V still streaming ----
    CP_WAIT(1);
    __syncthreads();

    // ---- sim = q k^T : 6 n-tiles x 4 k-steps ----
    float d[6][4];
#pragma unroll
    for (int j = 0; j < 6; j++)
#pragma unroll
        for (int e = 0; e < 4; e++) d[j][e] = 0.f;

    int l8  = lane & 7;
    int sel = (lane >> 3) & 1;
#pragma unroll
    for (int s = 0; s < 4; s++) {
        uint32_t a0, a1, a2, a3;
        uint32_t aaddr = sQ_u +
            (((lane & 15) * CSTR) + dloc + s * 16 + (lane >> 4) * 8) * 2;
        ldsm4(a0, a1, a2, a3, aaddr);
#pragma unroll
        for (int j = 0; j < 6; j++) {
            uint32_t b0, b1;
            uint32_t baddr = sK_u +
                (((j * 8 + l8) * CSTR) + dloc + s * 16 + sel * 8) * 2;
            ldsm2(b0, b1, baddr);
            mma16816(d[j], a0, a1, a2, a3, b0, b1);
        }
    }

    // ---- + static_a (prefetched) ----
#pragma unroll
    for (int j = 0; j < 6; j++) {
        d[j][0] += sa[j][0];
        d[j][1] += sa[j][1];
        d[j][2] += sa[j][2];
        d[j][3] += sa[j][3];
    }

    // ---- softmax in registers (rows r and r+8) ----
    float mlo = -1e30f, mhi = -1e30f;
#pragma unroll
    for (int j = 0; j < 6; j++) {
        mlo = fmaxf(mlo, fmaxf(d[j][0], d[j][1]));
        mhi = fmaxf(mhi, fmaxf(d[j][2], d[j][3]));
    }
    mlo = fmaxf(mlo, __shfl_xor_sync(0xffffffffu, mlo, 1));
    mlo = fmaxf(mlo, __shfl_xor_sync(0xffffffffu, mlo, 2));
    mhi = fmaxf(mhi, __shfl_xor_sync(0xffffffffu, mhi, 1));
    mhi = fmaxf(mhi, __shfl_xor_sync(0xffffffffu, mhi, 2));

    float slo = 0.f, shi = 0.f;
#pragma unroll
    for (int j = 0; j < 6; j++) {
        d[j][0] = expf(d[j][0] - mlo); slo += d[j][0];
        d[j][1] = expf(d[j][1] - mlo); slo += d[j][1];
        d[j][2] = expf(d[j][2] - mhi); shi += d[j][2];
        d[j][3] = expf(d[j][3] - mhi); shi += d[j][3];
    }
    slo += __shfl_xor_sync(0xffffffffu, slo, 1);
    slo += __shfl_xor_sync(0xffffffffu, slo, 2);
    shi += __shfl_xor_sync(0xffffffffu, shi, 1);
    shi += __shfl_xor_sync(0xffffffffu, shi, 2);
    float ilo = 1.f / slo, ihi = 1.f / shi;

    // ---- pack probs to fp16 A-fragments ----
    uint32_t plo[6], phi[6];
#pragma unroll
    for (int j = 0; j < 6; j++) {
        __half2 h0 = __floats2half2_rn(d[j][0] * ilo, d[j][1] * ilo);
        __half2 h1 = __floats2half2_rn(d[j][2] * ihi, d[j][3] * ihi);
        plo[j] = *(uint32_t*)&h0;
        phi[j] = *(uint32_t*)&h1;
    }

    // ---- wait for V ----
    CP_WAIT(0);
    __syncthreads();

    // ---- out = p v : 8 n-tiles x 3 k-steps ----
    float o[8][4];
#pragma unroll
    for (int n = 0; n < 8; n++)
#pragma unroll
        for (int e = 0; e < 4; e++) o[n][e] = 0.f;

#pragma unroll
    for (int kb = 0; kb < 3; kb++) {
        uint32_t a0 = plo[2 * kb], a1 = phi[2 * kb];
        uint32_t a2 = plo[2 * kb + 1], a3 = phi[2 * kb + 1];
#pragma unroll
        for (int n = 0; n < 8; n++) {
            uint32_t b0, b1;
            uint32_t baddr = sV_u +
                (((kb * 16 + sel * 8 + l8) * CSTR) + dloc + n * 8) * 2;
            ldsm2t(b0, b1, baddr);
            mma16816(o[n], a0, a1, a2, a3, b0, b1);
        }
    }

    // ---- store: rows r and r+8, half2 per n-tile ----
    {
        int py = r >> 2, px = r & 3;
        int pix_lo = (wy * 4 + py) * W_IMG + wx * 4 + px;
        int r2 = r + 8;
        int py2 = r2 >> 2, px2 = r2 & 3;
        int pix_hi = (wy * 4 + py2) * W_IMG + wx * 4 + px2;
        __half* dlo = &outp[((size_t)bb * HW + pix_lo) * INNER + cbase + dloc + cq];
        __half* dhi = &outp[((size_t)bb * HW + pix_hi) * INNER + cbase + dloc + cq];
#pragma unroll
        for (int n = 0; n < 8; n++) {
            __half2 h0 = __floats2half2_rn(o[n][0], o[n][1]);
            __half2 h1 = __floats2half2_rn(o[n][2], o[n][3]);
            *(__half2*)&dlo[n * 8] = h0;
            *(__half2*)&dhi[n * 8] = h1;
        }
    }
}

// ---------------------------------------------------------------------------
// Host launch
// ---------------------------------------------------------------------------
extern "C" void kernel_launch(void* const* d_in, const int* in_sizes, int n_in,
                              void* d_out, int out_size)
{
    (void)in_sizes; (void)n_in; (void)out_size;

    const float* q_inp   = (const float*)d_in[0];
    const float* k_inp   = (const float*)d_in[1];
    const float* flow_f  = (const float*)d_in[2];
    const float* flow_b  = (const float*)d_in[3];
    const float* gq      = (const float*)d_in[4];
    const float* bq      = (const float*)d_in[5];
    const float* gkv     = (const float*)d_in[6];
    const float* bkv     = (const float*)d_in[7];
    const float* Wq      = (const float*)d_in[8];
    const float* Wkv     = (const float*)d_in[9];
    const float* Wout    = (const float*)d_in[10];
    const float* statica = (const float*)d_in[11];

    __half *qn, *kvn, *qb, *kvb, *attb, *wtq, *wtkv, *wtout;
    cudaGetSymbolAddress((void**)&qn,    g_qn);
    cudaGetSymbolAddress((void**)&kvn,   g_kvn);
    cudaGetSymbolAddress((void**)&qb,    g_q);
    cudaGetSymbolAddress((void**)&kvb,   g_kv);
    cudaGetSymbolAddress((void**)&attb,  g_att);
    cudaGetSymbolAddress((void**)&wtq,   g_wt_q);
    cudaGetSymbolAddress((void**)&wtkv,  g_wt_kv);
    cudaGetSymbolAddress((void**)&wtout, g_wt_out);

    const int SMEM_QKV = (A6_ELEMS + 9 * 64 * AROWH) * 2 + 8 * 320 * 4;  // 205,504
    const int SMEM_OUT = (4 * 130 * AROWH + 9 * 64 * AROWH) * 2;         // 157,824
    const int SMEMA = (Q_L + 2 * KV_L) * CSTR * 2;                       // 30,464
    cudaFuncSetAttribute((const void*)conv_qkv_kernel,
                         cudaFuncAttributeMaxDynamicSharedMemorySize, SMEM_QKV);
    cudaFuncSetAttribute((const void*)conv_out_kernel,
                         cudaFuncAttributeMaxDynamicSharedMemorySize, SMEM_OUT);
    cudaFuncSetAttribute((const void*)attn_kernel,
                         cudaFuncAttributeMaxDynamicSharedMemorySize, SMEMA);

    // 0) all weight transforms in one launch
    wtrans_all_kernel<<<(4 * INNER * C_DIM + 255) / 256, 256>>>(
        Wq, Wkv, Wout, wtq, wtkv, wtout);

    // 1) merged layernorm (q + warped kv), 2 threads/px
    ln_all_kernel<<<dim3(2 * HW / 256, 4, B), 256>>>(
        q_inp, k_inp, flow_f, flow_b, gq, bq, gkv, bkv, qn, kvn);

    // 2) merged conv q + conv kv : 3584 CTAs, pipelined staging
    conv_qkv_kernel<<<3584, 256, SMEM_QKV>>>(qn, wtq, qb, kvn, wtkv, kvb);

    // 3) attention: FA-style register pipeline, split-group staging
    attn_kernel<<<dim3(1024, HEADS / 2, B), 64, SMEMA>>>(qb, kvb, statica, attb);

    // 4) conv out: 512 -> 64, fp32 NCHW -> d_out : 128 CTAs, staged waits
    conv_out_kernel<<<dim3(H_IMG / 2, 1, B), 256, SMEM_OUT>>>(
        attb, wtout, (float*)d_out);
}